// round 1
// baseline (speedup 1.0000x reference)
#include <cuda_runtime.h>
#include <cuda_bf16.h>
#include <math.h>

// ---------------- problem constants ----------------
#define NL   4
#define DM   768
#define DI   1536
#define DS   16
#define DTR  48
#define DCONV 4
#define VOCAB 32000
#define BB   2
#define LL   512
#define TT   (BB*LL)          // 1024 tokens
#define EPS  1e-5f

// ---------------- scratch (static device memory; no allocations) -------------
__device__ float g_h   [TT * DM];        // residual stream
__device__ float g_xn  [TT * DM];        // rmsnorm output
__device__ float g_proj[TT * 2 * DI];    // in_proj output (h | gate)
__device__ float g_conv[TT * DI];        // conv + silu output
__device__ float g_ssm [TT * 80];        // x_proj output (dt_raw | B | C)
__device__ float g_dt  [TT * DI];        // softplus(dt)
__device__ float g_y   [TT * DI];        // scan output * gate

// ---------------- small helpers ----------------
__device__ __forceinline__ float siluf(float x) {
    return x / (1.0f + __expf(-x));
}
__device__ __forceinline__ float softplusf(float x) {
    // log1p(exp(-|x|)) + max(x, 0)  (stable)
    return fmaxf(x, 0.0f) + log1pf(__expf(-fabsf(x)));
}

// ---------------- embedding gather ----------------
__global__ void embed_kernel(const int* __restrict__ ids,
                             const float* __restrict__ embed,
                             float* __restrict__ out) {
    int t = blockIdx.x;
    int id = ids[t];
    const float* src = embed + (size_t)id * DM;
    float* dst = out + (size_t)t * DM;
    for (int d = threadIdx.x; d < DM; d += blockDim.x)
        dst[d] = src[d];
}

// ---------------- rmsnorm (one block per token row) ----------------
__global__ void rmsnorm_kernel(const float* __restrict__ x,
                               const float* __restrict__ w,
                               float* __restrict__ out) {
    __shared__ float red[256];
    int t = blockIdx.x;
    const float* row = x + (size_t)t * DM;
    float s = 0.0f;
    for (int d = threadIdx.x; d < DM; d += blockDim.x) {
        float v = row[d];
        s += v * v;
    }
    red[threadIdx.x] = s;
    __syncthreads();
    for (int off = 128; off > 0; off >>= 1) {
        if (threadIdx.x < off) red[threadIdx.x] += red[threadIdx.x + off];
        __syncthreads();
    }
    float scale = rsqrtf(red[0] / (float)DM + EPS);
    float* dst = out + (size_t)t * DM;
    for (int d = threadIdx.x; d < DM; d += blockDim.x)
        dst[d] = row[d] * scale * w[d];
}

// ---------------- generic SGEMM: C[M,N] = A[M,K] @ W[N,K]^T (+epilogue) ------
// BM=BN=64, BK=16, 256 threads, 4x4 micro-tile. M always multiple of 64,
// K always multiple of 16; N guarded.
#define GBM 64
#define GBN 64
#define GBK 16

enum { EPI_NONE = 0, EPI_SOFTPLUS_BIAS = 1, EPI_RESID = 2 };

template <int EPI>
__global__ void __launch_bounds__(256)
gemm_tn_kernel(const float* __restrict__ A, int lda,
               const float* __restrict__ W, int ldw,
               float* __restrict__ C, int ldc,
               int M, int N, int K,
               const float* __restrict__ bias,
               const float* __restrict__ resid, int ldr)
{
    __shared__ float As[GBK][GBM + 1];
    __shared__ float Ws[GBK][GBN + 1];

    int tid = threadIdx.x;
    int bm = blockIdx.y * GBM;
    int bn = blockIdx.x * GBN;

    int lr = tid >> 2;          // 0..63
    int lk = (tid & 3) << 2;    // 0,4,8,12
    int ty = tid >> 4;          // 0..15
    int tx = tid & 15;          // 0..15

    float acc[4][4];
    #pragma unroll
    for (int i = 0; i < 4; i++)
        #pragma unroll
        for (int j = 0; j < 4; j++) acc[i][j] = 0.0f;

    for (int k0 = 0; k0 < K; k0 += GBK) {
        // load A tile (rows always in-bounds: M multiple of 64)
        {
            const float4 v = *(const float4*)(A + (size_t)(bm + lr) * lda + k0 + lk);
            As[lk + 0][lr] = v.x; As[lk + 1][lr] = v.y;
            As[lk + 2][lr] = v.z; As[lk + 3][lr] = v.w;
        }
        // load W tile (guard N)
        {
            float4 v = make_float4(0.f, 0.f, 0.f, 0.f);
            int row = bn + lr;
            if (row < N)
                v = *(const float4*)(W + (size_t)row * ldw + k0 + lk);
            Ws[lk + 0][lr] = v.x; Ws[lk + 1][lr] = v.y;
            Ws[lk + 2][lr] = v.z; Ws[lk + 3][lr] = v.w;
        }
        __syncthreads();

        #pragma unroll
        for (int kk = 0; kk < GBK; kk++) {
            float a[4], b[4];
            #pragma unroll
            for (int i = 0; i < 4; i++) a[i] = As[kk][ty * 4 + i];
            #pragma unroll
            for (int j = 0; j < 4; j++) b[j] = Ws[kk][tx * 4 + j];
            #pragma unroll
            for (int i = 0; i < 4; i++)
                #pragma unroll
                for (int j = 0; j < 4; j++)
                    acc[i][j] = fmaf(a[i], b[j], acc[i][j]);
        }
        __syncthreads();
    }

    #pragma unroll
    for (int i = 0; i < 4; i++) {
        int row = bm + ty * 4 + i;
        #pragma unroll
        for (int j = 0; j < 4; j++) {
            int col = bn + tx * 4 + j;
            if (col < N) {
                float v = acc[i][j];
                if (EPI == EPI_SOFTPLUS_BIAS) v = softplusf(v + bias[col]);
                if (EPI == EPI_RESID)         v = v + resid[(size_t)row * ldr + col];
                C[(size_t)row * ldc + col] = v;
            }
        }
    }
}

// ---------------- causal depthwise conv (width 4) + silu ----------------
__global__ void conv_silu_kernel(const float* __restrict__ proj,   // [TT, 2*DI]
                                 const float* __restrict__ cw,     // [DI, 4]
                                 const float* __restrict__ cb,     // [DI]
                                 float* __restrict__ out)          // [TT, DI]
{
    int idx = blockIdx.x * blockDim.x + threadIdx.x;
    if (idx >= TT * DI) return;
    int d = idx % DI;
    int t = idx / DI;
    int l = t % LL;
    float w0 = cw[d * 4 + 0], w1 = cw[d * 4 + 1], w2 = cw[d * 4 + 2], w3 = cw[d * 4 + 3];
    float acc = cb[d];
    // out[l] = sum_j w[j] * h[l-3+j]  (zero pad left within batch)
    if (l >= 3) acc = fmaf(w0, proj[(size_t)(t - 3) * (2 * DI) + d], acc);
    if (l >= 2) acc = fmaf(w1, proj[(size_t)(t - 2) * (2 * DI) + d], acc);
    if (l >= 1) acc = fmaf(w2, proj[(size_t)(t - 1) * (2 * DI) + d], acc);
    acc = fmaf(w3, proj[(size_t)t * (2 * DI) + d], acc);
    out[idx] = siluf(acc);
}

// ---------------- selective scan ----------------
// One thread per (b, d, s). 16 lanes (one d) reduce the C-dot via shfl.
// grid: (DI/16, BB), block: 256 (16 d's per block)
__global__ void scan_kernel(const float* __restrict__ dt,     // [TT, DI]
                            const float* __restrict__ hconv,  // [TT, DI]
                            const float* __restrict__ ssm,    // [TT, 80]
                            const float* __restrict__ proj,   // [TT, 2*DI] (gate)
                            const float* __restrict__ A_log,  // [DI, DS] (layer slice)
                            const float* __restrict__ D_skip, // [DI]
                            float* __restrict__ y)            // [TT, DI]
{
    int s = threadIdx.x & 15;
    int d = blockIdx.x * 16 + (threadIdx.x >> 4);
    int b = blockIdx.y;

    float Aneg = -__expf(A_log[d * DS + s]);
    float Dk = D_skip[d];

    float state = 0.0f;
    for (int l = 0; l < LL; l++) {
        int t = b * LL + l;
        float dtv = dt[(size_t)t * DI + d];
        float hv  = hconv[(size_t)t * DI + d];
        float Bv  = ssm[(size_t)t * 80 + DTR + s];
        float Cv  = ssm[(size_t)t * 80 + DTR + DS + s];
        float a = __expf(dtv * Aneg);
        state = fmaf(a, state, dtv * hv * Bv);
        float p = state * Cv;
        // reduce over 16 lanes
        p += __shfl_xor_sync(0xffffffffu, p, 8);
        p += __shfl_xor_sync(0xffffffffu, p, 4);
        p += __shfl_xor_sync(0xffffffffu, p, 2);
        p += __shfl_xor_sync(0xffffffffu, p, 1);
        if (s == 0) {
            float g = proj[(size_t)t * (2 * DI) + DI + d];
            y[(size_t)t * DI + d] = (p + Dk * hv) * siluf(g);
        }
    }
}

// ---------------- launcher ----------------
extern "C" void kernel_launch(void* const* d_in, const int* in_sizes, int n_in,
                              void* d_out, int out_size)
{
    const int*   input_ids = (const int*)  d_in[0];
    const float* embed     = (const float*)d_in[1];
    const float* norm_f_w  = (const float*)d_in[2];
    const float* in_proj_w = (const float*)d_in[3];
    const float* conv_w    = (const float*)d_in[4];
    const float* conv_b    = (const float*)d_in[5];
    const float* x_proj_w  = (const float*)d_in[6];
    const float* dt_proj_w = (const float*)d_in[7];
    const float* dt_proj_b = (const float*)d_in[8];
    const float* A_log     = (const float*)d_in[9];
    const float* D_skip    = (const float*)d_in[10];
    const float* out_proj_w= (const float*)d_in[11];
    const float* norm_w    = (const float*)d_in[12];
    float* logits = (float*)d_out;

    float *ph, *pxn, *pproj, *pconv, *pssm, *pdt, *py;
    cudaGetSymbolAddress((void**)&ph,    g_h);
    cudaGetSymbolAddress((void**)&pxn,   g_xn);
    cudaGetSymbolAddress((void**)&pproj, g_proj);
    cudaGetSymbolAddress((void**)&pconv, g_conv);
    cudaGetSymbolAddress((void**)&pssm,  g_ssm);
    cudaGetSymbolAddress((void**)&pdt,   g_dt);
    cudaGetSymbolAddress((void**)&py,    g_y);

    // 1) embedding
    embed_kernel<<<TT, 256>>>(input_ids, embed, ph);

    for (int i = 0; i < NL; i++) {
        const float* w_in  = in_proj_w  + (size_t)i * (2 * DI) * DM;
        const float* w_cv  = conv_w     + (size_t)i * DI * DCONV;
        const float* b_cv  = conv_b     + (size_t)i * DI;
        const float* w_xp  = x_proj_w   + (size_t)i * (DTR + 2 * DS) * DI;
        const float* w_dtp = dt_proj_w  + (size_t)i * DI * DTR;
        const float* b_dtp = dt_proj_b  + (size_t)i * DI;
        const float* a_log = A_log      + (size_t)i * DI * DS;
        const float* d_sk  = D_skip     + (size_t)i * DI;
        const float* w_out = out_proj_w + (size_t)i * DM * DI;
        const float* w_nrm = norm_w     + (size_t)i * DM;

        // rmsnorm
        rmsnorm_kernel<<<TT, 256>>>(ph, w_nrm, pxn);

        // in_proj: [1024,768] @ [3072,768]^T -> [1024,3072]
        {
            dim3 grid((2 * DI) / GBN, TT / GBM);
            gemm_tn_kernel<EPI_NONE><<<grid, 256>>>(
                pxn, DM, w_in, DM, pproj, 2 * DI, TT, 2 * DI, DM, nullptr, nullptr, 0);
        }

        // conv + silu
        conv_silu_kernel<<<(TT * DI + 255) / 256, 256>>>(pproj, w_cv, b_cv, pconv);

        // x_proj: [1024,1536] @ [80,1536]^T -> [1024,80]
        {
            dim3 grid((80 + GBN - 1) / GBN, TT / GBM);
            gemm_tn_kernel<EPI_NONE><<<grid, 256>>>(
                pconv, DI, w_xp, DI, pssm, 80, TT, 80, DI, nullptr, nullptr, 0);
        }

        // dt_proj + softplus: [1024,48(lda=80)] @ [1536,48]^T -> [1024,1536]
        {
            dim3 grid(DI / GBN, TT / GBM);
            gemm_tn_kernel<EPI_SOFTPLUS_BIAS><<<grid, 256>>>(
                pssm, 80, w_dtp, DTR, pdt, DI, TT, DI, DTR, b_dtp, nullptr, 0);
        }

        // selective scan (+ D skip + gate silu)
        {
            dim3 grid(DI / 16, BB);
            scan_kernel<<<grid, 256>>>(pdt, pconv, pssm, pproj, a_log, d_sk, py);
        }

        // out_proj + residual: h = h + y @ w_out^T  ([1024,1536] @ [768,1536]^T)
        {
            dim3 grid(DM / GBN, TT / GBM);
            gemm_tn_kernel<EPI_RESID><<<grid, 256>>>(
                py, DI, w_out, DI, ph, DM, TT, DM, DI, nullptr, ph, DM);
        }
    }

    // final rmsnorm
    rmsnorm_kernel<<<TT, 256>>>(ph, norm_f_w, pxn);

    // lm head: [1024,768] @ [32000,768]^T -> [1024,32000]
    {
        dim3 grid(VOCAB / GBN, TT / GBM);
        gemm_tn_kernel<EPI_NONE><<<grid, 256>>>(
            pxn, DM, embed, DM, logits, VOCAB, TT, VOCAB, DM, nullptr, nullptr, 0);
    }
}

// round 3
// speedup vs baseline: 1.4970x; 1.4970x over previous
#include <cuda_runtime.h>
#include <cuda_bf16.h>
#include <cstdint>
#include <math.h>

// ---------------- problem constants ----------------
#define NL    4
#define DM    768
#define DI    1536
#define DS    16
#define DTR   48
#define DCONV 4
#define VOCAB 32000
#define BB    2
#define LL    512
#define TT    (BB*LL)          // 1024 tokens
#define EPS   1e-5f

// ---------------- scratch (static device memory; no allocations) -------------
__device__ float g_h   [TT * DM];            // residual stream (fp32)
__device__ float g_proj[TT * 2 * DI];        // in_proj output (h | gate)
__device__ float g_conv[TT * DI];            // conv + silu output
__device__ float g_ssm [TT * 80];            // x_proj output (dt_raw | B | C)
__device__ float g_dt  [TT * DI];            // softplus(dt)

// bf16x3 planes along K. Activations: [hi, lo, hi]; weights: [hi, hi, lo].
__device__ __nv_bfloat16 g_xn_big   [TT * 3 * DM];        // rmsnorm out,  K'=2304
__device__ __nv_bfloat16 g_y_big    [TT * 3 * DI];        // scan out,     K'=4608
__device__ __nv_bfloat16 g_inw_big  [(2*DI) * 3 * DM];    // in_proj_w
__device__ __nv_bfloat16 g_outw_big [DM * 3 * DI];        // out_proj_w
__device__ __nv_bfloat16 g_embed_big[(size_t)VOCAB * 3 * DM]; // embed (lm head)

// ---------------- helpers ----------------
__device__ __forceinline__ uint32_t smem_u32(const void* p) {
    uint32_t a;
    asm("{ .reg .u64 t; cvta.to.shared.u64 t, %1; cvt.u32.u64 %0, t; }" : "=r"(a) : "l"(p));
    return a;
}
__device__ __forceinline__ void cp_async16(uint32_t dst, const void* src) {
    asm volatile("cp.async.cg.shared.global [%0], [%1], 16;" :: "r"(dst), "l"(src));
}
#define CP_COMMIT() asm volatile("cp.async.commit_group;" ::: "memory")
#define CP_WAIT(n)  asm volatile("cp.async.wait_group %0;" :: "n"(n) : "memory")

__device__ __forceinline__ float siluf(float x) { return x / (1.0f + __expf(-x)); }
__device__ __forceinline__ float softplusf(float x) {
    return fmaxf(x, 0.0f) + log1pf(__expf(-fabsf(x)));
}
__device__ __forceinline__ void split_bf16(float v, __nv_bfloat16& hi, __nv_bfloat16& lo) {
    hi = __float2bfloat16(v);
    lo = __float2bfloat16(v - __bfloat162float(hi));
}

// ---------------- embedding gather ----------------
__global__ void embed_kernel(const int* __restrict__ ids,
                             const float* __restrict__ embed,
                             float* __restrict__ out) {
    int t = blockIdx.x;
    int id = ids[t];
    const float* src = embed + (size_t)id * DM;
    float* dst = out + (size_t)t * DM;
    for (int d = threadIdx.x; d < DM; d += blockDim.x) dst[d] = src[d];
}

// ---------------- rmsnorm -> bf16x3 activation planes [T, 3*DM] -------------
__global__ void rmsnorm3_kernel(const float* __restrict__ x,
                                const float* __restrict__ w,
                                __nv_bfloat16* __restrict__ out) {
    __shared__ float red[256];
    int t = blockIdx.x;
    const float* row = x + (size_t)t * DM;
    float s = 0.0f;
    for (int d = threadIdx.x; d < DM; d += blockDim.x) { float v = row[d]; s += v * v; }
    red[threadIdx.x] = s;
    __syncthreads();
    for (int off = 128; off > 0; off >>= 1) {
        if (threadIdx.x < off) red[threadIdx.x] += red[threadIdx.x + off];
        __syncthreads();
    }
    float scale = rsqrtf(red[0] / (float)DM + EPS);
    __nv_bfloat16* dst = out + (size_t)t * (3 * DM);
    for (int d = threadIdx.x; d < DM; d += blockDim.x) {
        float v = row[d] * scale * w[d];
        __nv_bfloat16 hi, lo; split_bf16(v, hi, lo);
        dst[d] = hi; dst[DM + d] = lo; dst[2 * DM + d] = hi;
    }
}

// ---------------- fp32 [R,C] -> bf16x3 weight planes [R,3C] (hi,hi,lo) ------
__global__ void convert3_w_kernel(const float* __restrict__ src,
                                  __nv_bfloat16* __restrict__ dst,
                                  int R, int C) {
    size_t idx = (size_t)blockIdx.x * blockDim.x + threadIdx.x;
    if (idx >= (size_t)R * C) return;
    size_t r = idx / C, c = idx % C;
    __nv_bfloat16 hi, lo; split_bf16(src[idx], hi, lo);
    __nv_bfloat16* d = dst + r * (3 * (size_t)C);
    d[c] = hi; d[C + c] = hi; d[2 * (size_t)C + c] = lo;
}

// =============================================================================
// HMMA bf16 GEMM: C[M,N] (=/+=) A[M,Kp] @ W[N,Kp]^T
// 128x128 CTA tile, BK=32, 256 threads (8 warps: 2x4), mma.m16n8k16,
// 2-stage cp.async pipeline, ldmatrix fragments. M,N mult of 128, Kp mult 32.
// =============================================================================
#define BM 128
#define BN 128
#define BK 32
#define SSTR 40   // smem row stride in bf16 (32 + 8 pad)

template <int EPI>  // 0 = store, 1 = in-place add (residual)
__global__ void __launch_bounds__(256)
hmma_gemm_kernel(const __nv_bfloat16* __restrict__ A,
                 const __nv_bfloat16* __restrict__ W,
                 float* __restrict__ C, int Kp, int N)
{
    __shared__ __nv_bfloat16 As[2][BM * SSTR];
    __shared__ __nv_bfloat16 Ws[2][BN * SSTR];

    const int tid = threadIdx.x;
    const int lane = tid & 31;
    const int wid = tid >> 5;
    const int wm = wid >> 2;     // 0..1 -> 64 rows
    const int wn = wid & 3;      // 0..3 -> 32 cols
    const int bm = blockIdx.x * BM;
    const int bn = blockIdx.y * BN;

    // global->smem: each thread copies 2x16B for A and 2x16B for W per tile
    const int ar0 = tid >> 2,          ak0 = (tid & 3) * 8;
    const int ar1 = (tid + 256) >> 2,  ak1 = ak0;   // chunk tid+256: same k col pattern
    // note: (tid+256)&3 == tid&3, so ak1 == ak0

    float acc[4][4][4];
    #pragma unroll
    for (int i = 0; i < 4; i++)
        #pragma unroll
        for (int j = 0; j < 4; j++)
            #pragma unroll
            for (int k = 0; k < 4; k++) acc[i][j][k] = 0.0f;

#define LOAD_TILE(buf, k0) do { \
    cp_async16(smem_u32(&As[buf][ar0 * SSTR + ak0]), A + (size_t)(bm + ar0) * Kp + (k0) + ak0); \
    cp_async16(smem_u32(&As[buf][ar1 * SSTR + ak1]), A + (size_t)(bm + ar1) * Kp + (k0) + ak1); \
    cp_async16(smem_u32(&Ws[buf][ar0 * SSTR + ak0]), W + (size_t)(bn + ar0) * Kp + (k0) + ak0); \
    cp_async16(smem_u32(&Ws[buf][ar1 * SSTR + ak1]), W + (size_t)(bn + ar1) * Kp + (k0) + ak1); \
    CP_COMMIT(); } while (0)

    const int nc = Kp / BK;
    LOAD_TILE(0, 0);

    for (int c = 0; c < nc; c++) {
        if (c + 1 < nc) { LOAD_TILE((c + 1) & 1, (c + 1) * BK); CP_WAIT(1); }
        else            { CP_WAIT(0); }
        __syncthreads();

        const int buf = c & 1;
        #pragma unroll
        for (int ks = 0; ks < 2; ks++) {
            uint32_t a[4][4];
            #pragma unroll
            for (int mt = 0; mt < 4; mt++) {
                int row = wm * 64 + mt * 16 + (lane & 15);
                int col = ks * 16 + (lane >> 4) * 8;
                uint32_t ad = smem_u32(&As[buf][row * SSTR + col]);
                asm volatile("ldmatrix.sync.aligned.m8n8.x4.shared.b16 {%0,%1,%2,%3}, [%4];"
                    : "=r"(a[mt][0]), "=r"(a[mt][1]), "=r"(a[mt][2]), "=r"(a[mt][3]) : "r"(ad));
            }
            uint32_t b[4][2];
            #pragma unroll
            for (int np = 0; np < 2; np++) {
                int grp = lane >> 3, wi = lane & 7;
                int row = wn * 32 + np * 16 + (grp >> 1) * 8 + wi;
                int col = ks * 16 + (grp & 1) * 8;
                uint32_t bd = smem_u32(&Ws[buf][row * SSTR + col]);
                asm volatile("ldmatrix.sync.aligned.m8n8.x4.shared.b16 {%0,%1,%2,%3}, [%4];"
                    : "=r"(b[np * 2][0]), "=r"(b[np * 2][1]),
                      "=r"(b[np * 2 + 1][0]), "=r"(b[np * 2 + 1][1]) : "r"(bd));
            }
            #pragma unroll
            for (int mt = 0; mt < 4; mt++)
                #pragma unroll
                for (int nt = 0; nt < 4; nt++)
                    asm volatile(
                        "mma.sync.aligned.m16n8k16.row.col.f32.bf16.bf16.f32 "
                        "{%0,%1,%2,%3}, {%4,%5,%6,%7}, {%8,%9}, {%0,%1,%2,%3};"
                        : "+f"(acc[mt][nt][0]), "+f"(acc[mt][nt][1]),
                          "+f"(acc[mt][nt][2]), "+f"(acc[mt][nt][3])
                        : "r"(a[mt][0]), "r"(a[mt][1]), "r"(a[mt][2]), "r"(a[mt][3]),
                          "r"(b[nt][0]), "r"(b[nt][1]));
        }
        __syncthreads();
    }
#undef LOAD_TILE

    // epilogue
    #pragma unroll
    for (int mt = 0; mt < 4; mt++) {
        int r0 = bm + wm * 64 + mt * 16 + (lane >> 2);
        #pragma unroll
        for (int nt = 0; nt < 4; nt++) {
            int c0 = bn + wn * 32 + nt * 8 + (lane & 3) * 2;
            float* p0 = C + (size_t)r0 * N + c0;
            float* p1 = C + (size_t)(r0 + 8) * N + c0;
            if (EPI == 1) {
                p0[0] += acc[mt][nt][0]; p0[1] += acc[mt][nt][1];
                p1[0] += acc[mt][nt][2]; p1[1] += acc[mt][nt][3];
            } else {
                p0[0] = acc[mt][nt][0]; p0[1] = acc[mt][nt][1];
                p1[0] = acc[mt][nt][2]; p1[1] = acc[mt][nt][3];
            }
        }
    }
}

// ---------------- fp32 SGEMM for small shapes (x_proj, dt_proj) -------------
#define GBM 64
#define GBN 64
#define GBK 16
enum { EPI_NONE = 0, EPI_SOFTPLUS_BIAS = 1 };

template <int EPI>
__global__ void __launch_bounds__(256)
gemm_tn_kernel(const float* __restrict__ A, int lda,
               const float* __restrict__ W, int ldw,
               float* __restrict__ C, int ldc,
               int M, int N, int K,
               const float* __restrict__ bias)
{
    __shared__ float Asm[GBK][GBM + 1];
    __shared__ float Wsm[GBK][GBN + 1];

    int tid = threadIdx.x;
    int bm = blockIdx.y * GBM;
    int bn = blockIdx.x * GBN;
    int lr = tid >> 2;
    int lk = (tid & 3) << 2;
    int ty = tid >> 4;
    int tx = tid & 15;

    float acc[4][4];
    #pragma unroll
    for (int i = 0; i < 4; i++)
        #pragma unroll
        for (int j = 0; j < 4; j++) acc[i][j] = 0.0f;

    for (int k0 = 0; k0 < K; k0 += GBK) {
        {
            const float4 v = *(const float4*)(A + (size_t)(bm + lr) * lda + k0 + lk);
            Asm[lk + 0][lr] = v.x; Asm[lk + 1][lr] = v.y;
            Asm[lk + 2][lr] = v.z; Asm[lk + 3][lr] = v.w;
        }
        {
            float4 v = make_float4(0.f, 0.f, 0.f, 0.f);
            int row = bn + lr;
            if (row < N) v = *(const float4*)(W + (size_t)row * ldw + k0 + lk);
            Wsm[lk + 0][lr] = v.x; Wsm[lk + 1][lr] = v.y;
            Wsm[lk + 2][lr] = v.z; Wsm[lk + 3][lr] = v.w;
        }
        __syncthreads();
        #pragma unroll
        for (int kk = 0; kk < GBK; kk++) {
            float a[4], b[4];
            #pragma unroll
            for (int i = 0; i < 4; i++) a[i] = Asm[kk][ty * 4 + i];
            #pragma unroll
            for (int j = 0; j < 4; j++) b[j] = Wsm[kk][tx * 4 + j];
            #pragma unroll
            for (int i = 0; i < 4; i++)
                #pragma unroll
                for (int j = 0; j < 4; j++)
                    acc[i][j] = fmaf(a[i], b[j], acc[i][j]);
        }
        __syncthreads();
    }

    #pragma unroll
    for (int i = 0; i < 4; i++) {
        int row = bm + ty * 4 + i;
        #pragma unroll
        for (int j = 0; j < 4; j++) {
            int col = bn + tx * 4 + j;
            if (col < N) {
                float v = acc[i][j];
                if (EPI == EPI_SOFTPLUS_BIAS) v = softplusf(v + bias[col]);
                C[(size_t)row * ldc + col] = v;
            }
        }
    }
}

// ---------------- causal depthwise conv (width 4) + silu ----------------
__global__ void conv_silu_kernel(const float* __restrict__ proj,
                                 const float* __restrict__ cw,
                                 const float* __restrict__ cb,
                                 float* __restrict__ out)
{
    int idx = blockIdx.x * blockDim.x + threadIdx.x;
    if (idx >= TT * DI) return;
    int d = idx % DI;
    int t = idx / DI;
    int l = t % LL;
    float w0 = cw[d * 4 + 0], w1 = cw[d * 4 + 1], w2 = cw[d * 4 + 2], w3 = cw[d * 4 + 3];
    float acc = cb[d];
    if (l >= 3) acc = fmaf(w0, proj[(size_t)(t - 3) * (2 * DI) + d], acc);
    if (l >= 2) acc = fmaf(w1, proj[(size_t)(t - 2) * (2 * DI) + d], acc);
    if (l >= 1) acc = fmaf(w2, proj[(size_t)(t - 1) * (2 * DI) + d], acc);
    acc = fmaf(w3, proj[(size_t)t * (2 * DI) + d], acc);
    out[idx] = siluf(acc);
}

// ---------------- selective scan -> bf16x3 y [T, 3*DI] ----------------
__global__ void scan_kernel(const float* __restrict__ dt,
                            const float* __restrict__ hconv,
                            const float* __restrict__ ssm,
                            const float* __restrict__ proj,
                            const float* __restrict__ A_log,
                            const float* __restrict__ D_skip,
                            __nv_bfloat16* __restrict__ y)
{
    int s = threadIdx.x & 15;
    int d = blockIdx.x * 16 + (threadIdx.x >> 4);
    int b = blockIdx.y;

    float Aneg = -__expf(A_log[d * DS + s]);
    float Dk = D_skip[d];

    float state = 0.0f;
    for (int l = 0; l < LL; l++) {
        int t = b * LL + l;
        float dtv = dt[(size_t)t * DI + d];
        float hv  = hconv[(size_t)t * DI + d];
        float Bv  = ssm[(size_t)t * 80 + DTR + s];
        float Cv  = ssm[(size_t)t * 80 + DTR + DS + s];
        float a = __expf(dtv * Aneg);
        state = fmaf(a, state, dtv * hv * Bv);
        float p = state * Cv;
        p += __shfl_xor_sync(0xffffffffu, p, 8);
        p += __shfl_xor_sync(0xffffffffu, p, 4);
        p += __shfl_xor_sync(0xffffffffu, p, 2);
        p += __shfl_xor_sync(0xffffffffu, p, 1);
        if (s == 0) {
            float g = proj[(size_t)t * (2 * DI) + DI + d];
            float val = (p + Dk * hv) * siluf(g);
            __nv_bfloat16 hi, lo; split_bf16(val, hi, lo);
            __nv_bfloat16* dst = y + (size_t)t * (3 * DI);
            dst[d] = hi; dst[DI + d] = lo; dst[2 * DI + d] = hi;
        }
    }
}

// ---------------- launcher ----------------
extern "C" void kernel_launch(void* const* d_in, const int* in_sizes, int n_in,
                              void* d_out, int out_size)
{
    const int*   input_ids = (const int*)  d_in[0];
    const float* embed     = (const float*)d_in[1];
    const float* norm_f_w  = (const float*)d_in[2];
    const float* in_proj_w = (const float*)d_in[3];
    const float* conv_w    = (const float*)d_in[4];
    const float* conv_b    = (const float*)d_in[5];
    const float* x_proj_w  = (const float*)d_in[6];
    const float* dt_proj_w = (const float*)d_in[7];
    const float* dt_proj_b = (const float*)d_in[8];
    const float* A_log     = (const float*)d_in[9];
    const float* D_skip    = (const float*)d_in[10];
    const float* out_proj_w= (const float*)d_in[11];
    const float* norm_w    = (const float*)d_in[12];
    float* logits = (float*)d_out;

    float *ph, *pproj, *pconv, *pssm, *pdt;
    __nv_bfloat16 *pxn, *py, *pinw, *poutw, *pemb;
    cudaGetSymbolAddress((void**)&ph,    g_h);
    cudaGetSymbolAddress((void**)&pproj, g_proj);
    cudaGetSymbolAddress((void**)&pconv, g_conv);
    cudaGetSymbolAddress((void**)&pssm,  g_ssm);
    cudaGetSymbolAddress((void**)&pdt,   g_dt);
    cudaGetSymbolAddress((void**)&pxn,   g_xn_big);
    cudaGetSymbolAddress((void**)&py,    g_y_big);
    cudaGetSymbolAddress((void**)&pinw,  g_inw_big);
    cudaGetSymbolAddress((void**)&poutw, g_outw_big);
    cudaGetSymbolAddress((void**)&pemb,  g_embed_big);

    // embedding gather + lm-head weight planes
    embed_kernel<<<TT, 256>>>(input_ids, embed, ph);
    {
        size_t n = (size_t)VOCAB * DM;
        convert3_w_kernel<<<(int)((n + 255) / 256), 256>>>(embed, pemb, VOCAB, DM);
    }

    for (int i = 0; i < NL; i++) {
        const float* w_in  = in_proj_w  + (size_t)i * (2 * DI) * DM;
        const float* w_cv  = conv_w     + (size_t)i * DI * DCONV;
        const float* b_cv  = conv_b     + (size_t)i * DI;
        const float* w_xp  = x_proj_w   + (size_t)i * (DTR + 2 * DS) * DI;
        const float* w_dtp = dt_proj_w  + (size_t)i * DI * DTR;
        const float* b_dtp = dt_proj_b  + (size_t)i * DI;
        const float* a_log = A_log      + (size_t)i * DI * DS;
        const float* d_sk  = D_skip     + (size_t)i * DI;
        const float* w_out = out_proj_w + (size_t)i * DM * DI;
        const float* w_nrm = norm_w     + (size_t)i * DM;

        // rmsnorm -> bf16x3
        rmsnorm3_kernel<<<TT, 256>>>(ph, w_nrm, pxn);

        // weight plane conversions for this layer
        convert3_w_kernel<<<((2 * DI) * DM + 255) / 256, 256>>>(w_in, pinw, 2 * DI, DM);
        convert3_w_kernel<<<(DM * DI + 255) / 256, 256>>>(w_out, poutw, DM, DI);

        // in_proj: [1024, 2304] @ [3072, 2304]^T -> proj [1024, 3072]
        {
            dim3 grid(TT / BM, (2 * DI) / BN);
            hmma_gemm_kernel<0><<<grid, 256>>>(pxn, pinw, pproj, 3 * DM, 2 * DI);
        }

        // conv + silu
        conv_silu_kernel<<<(TT * DI + 255) / 256, 256>>>(pproj, w_cv, b_cv, pconv);

        // x_proj: [1024,1536] @ [80,1536]^T -> [1024,80]  (fp32)
        {
            dim3 grid((80 + GBN - 1) / GBN, TT / GBM);
            gemm_tn_kernel<EPI_NONE><<<grid, 256>>>(
                pconv, DI, w_xp, DI, pssm, 80, TT, 80, DI, nullptr);
        }

        // dt_proj + softplus: [1024,48(lda=80)] @ [1536,48]^T -> [1024,1536]
        {
            dim3 grid(DI / GBN, TT / GBM);
            gemm_tn_kernel<EPI_SOFTPLUS_BIAS><<<grid, 256>>>(
                pssm, 80, w_dtp, DTR, pdt, DI, TT, DI, DTR, b_dtp);
        }

        // selective scan (+ D skip + gate silu) -> bf16x3 y
        {
            dim3 grid(DI / 16, BB);
            scan_kernel<<<grid, 256>>>(pdt, pconv, pssm, pproj, a_log, d_sk, py);
        }

        // out_proj + residual (in place): h += y @ w_out^T
        {
            dim3 grid(TT / BM, DM / BN);
            hmma_gemm_kernel<1><<<grid, 256>>>(py, poutw, ph, 3 * DI, DM);
        }
    }

    // final rmsnorm -> bf16x3
    rmsnorm3_kernel<<<TT, 256>>>(ph, norm_f_w, pxn);

    // lm head: [1024, 2304] @ [32000, 2304]^T -> logits [1024, 32000]
    {
        dim3 grid(TT / BM, VOCAB / BN);
        hmma_gemm_kernel<0><<<grid, 256>>>(pxn, pemb, logits, 3 * DM, VOCAB);
    }
}

// round 4
// speedup vs baseline: 1.6542x; 1.1050x over previous
#include <cuda_runtime.h>
#include <cuda_bf16.h>
#include <cstdint>
#include <math.h>

// ---------------- problem constants ----------------
#define NL    4
#define DM    768
#define DI    1536
#define DS    16
#define DTR   48
#define DCONV 4
#define VOCAB 32000
#define BB    2
#define LL    512
#define TT    (BB*LL)          // 1024 tokens
#define EPS   1e-5f

// ---------------- scratch (static device memory; no allocations) -------------
__device__ float g_h   [TT * DM];            // residual stream (fp32)
__device__ float g_proj[TT * 2 * DI];        // in_proj output (h | gate)
__device__ float g_conv[TT * DI];            // conv + silu output
__device__ float g_ssm [TT * 80];            // x_proj output (dt_raw | B | C)
__device__ float g_dt  [TT * DI];            // softplus(dt)

// bf16x3 planes along K. Activations: [hi, lo, hi]; weights: [hi, hi, lo].
__device__ __nv_bfloat16 g_xn_big   [TT * 3 * DM];                 // rmsnorm out
__device__ __nv_bfloat16 g_y_big    [TT * 3 * DI];                 // scan out
__device__ __nv_bfloat16 g_inw_big  [(size_t)NL * (2*DI) * 3 * DM]; // all in_proj_w
__device__ __nv_bfloat16 g_outw_big [(size_t)NL * DM * 3 * DI];     // all out_proj_w
__device__ __nv_bfloat16 g_embed_big[(size_t)VOCAB * 3 * DM];       // embed (lm head)

// ---------------- helpers ----------------
__device__ __forceinline__ uint32_t smem_u32(const void* p) {
    uint32_t a;
    asm("{ .reg .u64 t; cvta.to.shared.u64 t, %1; cvt.u32.u64 %0, t; }" : "=r"(a) : "l"(p));
    return a;
}
__device__ __forceinline__ void cp_async16(uint32_t dst, const void* src) {
    asm volatile("cp.async.cg.shared.global [%0], [%1], 16;" :: "r"(dst), "l"(src));
}
#define CP_COMMIT() asm volatile("cp.async.commit_group;" ::: "memory")
#define CP_WAIT(n)  asm volatile("cp.async.wait_group %0;" :: "n"(n) : "memory")

__device__ __forceinline__ float siluf(float x) { return x / (1.0f + __expf(-x)); }
__device__ __forceinline__ float softplusf(float x) {
    return fmaxf(x, 0.0f) + log1pf(__expf(-fabsf(x)));
}
__device__ __forceinline__ void split_bf16(float v, __nv_bfloat16& hi, __nv_bfloat16& lo) {
    hi = __float2bfloat16(v);
    lo = __float2bfloat16(v - __bfloat162float(hi));
}

// ---------------- embedding gather ----------------
__global__ void embed_kernel(const int* __restrict__ ids,
                             const float* __restrict__ embed,
                             float* __restrict__ out) {
    int t = blockIdx.x;
    int id = ids[t];
    const float* src = embed + (size_t)id * DM;
    float* dst = out + (size_t)t * DM;
    for (int d = threadIdx.x; d < DM; d += blockDim.x) dst[d] = src[d];
}

// ---------------- rmsnorm -> bf16x3 activation planes [T, 3*DM] -------------
__global__ void rmsnorm3_kernel(const float* __restrict__ x,
                                const float* __restrict__ w,
                                __nv_bfloat16* __restrict__ out) {
    __shared__ float red[256];
    int t = blockIdx.x;
    const float* row = x + (size_t)t * DM;
    float s = 0.0f;
    for (int d = threadIdx.x; d < DM; d += blockDim.x) { float v = row[d]; s += v * v; }
    red[threadIdx.x] = s;
    __syncthreads();
    for (int off = 128; off > 0; off >>= 1) {
        if (threadIdx.x < off) red[threadIdx.x] += red[threadIdx.x + off];
        __syncthreads();
    }
    float scale = rsqrtf(red[0] / (float)DM + EPS);
    __nv_bfloat16* dst = out + (size_t)t * (3 * DM);
    for (int d = threadIdx.x; d < DM; d += blockDim.x) {
        float v = row[d] * scale * w[d];
        __nv_bfloat16 hi, lo; split_bf16(v, hi, lo);
        dst[d] = hi; dst[DM + d] = lo; dst[2 * DM + d] = hi;
    }
}

// ---------------- fp32 [R,C] -> bf16x3 weight planes [R,3C] (hi,hi,lo) ------
// C multiple of 4. grid: (ceil(C/4/128), R), 128 threads.
__global__ void convert3_w_kernel(const float* __restrict__ src,
                                  __nv_bfloat16* __restrict__ dst,
                                  int C) {
    int r = blockIdx.y;
    int c4 = blockIdx.x * blockDim.x + threadIdx.x;
    int C4 = C >> 2;
    if (c4 >= C4) return;
    float4 v = *(const float4*)(src + (size_t)r * C + c4 * 4);
    __nv_bfloat16 h0, l0, h1, l1, h2, l2, h3, l3;
    split_bf16(v.x, h0, l0); split_bf16(v.y, h1, l1);
    split_bf16(v.z, h2, l2); split_bf16(v.w, h3, l3);
    __nv_bfloat162 hA = __halves2bfloat162(h0, h1);
    __nv_bfloat162 hB = __halves2bfloat162(h2, h3);
    __nv_bfloat162 lA = __halves2bfloat162(l0, l1);
    __nv_bfloat162 lB = __halves2bfloat162(l2, l3);
    __nv_bfloat16* d = dst + (size_t)r * (3 * (size_t)C) + c4 * 4;
    ((__nv_bfloat162*)d)[0] = hA;            ((__nv_bfloat162*)d)[1] = hB;
    ((__nv_bfloat162*)(d + C))[0] = hA;      ((__nv_bfloat162*)(d + C))[1] = hB;
    ((__nv_bfloat162*)(d + 2 * C))[0] = lA;  ((__nv_bfloat162*)(d + 2 * C))[1] = lB;
}

// =============================================================================
// HMMA bf16 GEMM: C[M,N] (=/+=) A[M,Kp] @ W[N,Kp]^T
// 128x128 CTA tile, BK=32, 256 threads (8 warps: 2x4), mma.m16n8k16,
// 3-stage cp.async pipeline (dynamic smem), 1 sync per K-iter.
// =============================================================================
#define BM 128
#define BN 128
#define BK 32
#define SSTR 40          // smem row stride in bf16 (32 + 8 pad) -> conflict-free
#define NSTAGE 3
#define STAGE_ELEMS (BM * SSTR)
#define HMMA_SMEM (NSTAGE * 2 * STAGE_ELEMS * 2)   // bytes

template <int EPI>  // 0 = store, 1 = in-place add (residual)
__global__ void __launch_bounds__(256, 2)
hmma_gemm_kernel(const __nv_bfloat16* __restrict__ A,
                 const __nv_bfloat16* __restrict__ W,
                 float* __restrict__ C, int Kp, int N)
{
    extern __shared__ __nv_bfloat16 dsm[];
    __nv_bfloat16* Asm = dsm;                          // [NSTAGE][STAGE_ELEMS]
    __nv_bfloat16* Wsm = dsm + NSTAGE * STAGE_ELEMS;   // [NSTAGE][STAGE_ELEMS]

    const int tid = threadIdx.x;
    const int lane = tid & 31;
    const int wid = tid >> 5;
    const int wm = wid >> 2;     // 0..1 -> 64 rows
    const int wn = wid & 3;      // 0..3 -> 32 cols
    const int bm = blockIdx.x * BM;
    const int bn = blockIdx.y * BN;

    const int ar0 = tid >> 2,         ak0 = (tid & 3) * 8;
    const int ar1 = (tid + 256) >> 2; // rows 64..127, same k cols

    float acc[4][4][4];
    #pragma unroll
    for (int i = 0; i < 4; i++)
        #pragma unroll
        for (int j = 0; j < 4; j++)
            #pragma unroll
            for (int k = 0; k < 4; k++) acc[i][j][k] = 0.0f;

#define LOAD_TILE(buf, k0) do { \
    __nv_bfloat16* ap = Asm + (buf) * STAGE_ELEMS; \
    __nv_bfloat16* wp = Wsm + (buf) * STAGE_ELEMS; \
    cp_async16(smem_u32(ap + ar0 * SSTR + ak0), A + (size_t)(bm + ar0) * Kp + (k0) + ak0); \
    cp_async16(smem_u32(ap + ar1 * SSTR + ak0), A + (size_t)(bm + ar1) * Kp + (k0) + ak0); \
    cp_async16(smem_u32(wp + ar0 * SSTR + ak0), W + (size_t)(bn + ar0) * Kp + (k0) + ak0); \
    cp_async16(smem_u32(wp + ar1 * SSTR + ak0), W + (size_t)(bn + ar1) * Kp + (k0) + ak0); \
} while (0)

    const int nc = Kp / BK;
    LOAD_TILE(0, 0); CP_COMMIT();
    LOAD_TILE(1, BK); CP_COMMIT();

    for (int c = 0; c < nc; c++) {
        CP_WAIT(1);
        __syncthreads();
        int nf = c + 2;
        if (nf < nc) LOAD_TILE(nf % NSTAGE, nf * BK);
        CP_COMMIT();

        const int buf = c % NSTAGE;
        const __nv_bfloat16* ab = Asm + buf * STAGE_ELEMS;
        const __nv_bfloat16* wb = Wsm + buf * STAGE_ELEMS;
        #pragma unroll
        for (int ks = 0; ks < 2; ks++) {
            uint32_t a[4][4];
            #pragma unroll
            for (int mt = 0; mt < 4; mt++) {
                int row = wm * 64 + mt * 16 + (lane & 15);
                int col = ks * 16 + (lane >> 4) * 8;
                uint32_t ad = smem_u32(ab + row * SSTR + col);
                asm volatile("ldmatrix.sync.aligned.m8n8.x4.shared.b16 {%0,%1,%2,%3}, [%4];"
                    : "=r"(a[mt][0]), "=r"(a[mt][1]), "=r"(a[mt][2]), "=r"(a[mt][3]) : "r"(ad));
            }
            uint32_t b[4][2];
            #pragma unroll
            for (int np = 0; np < 2; np++) {
                int grp = lane >> 3, wi = lane & 7;
                int row = wn * 32 + np * 16 + (grp >> 1) * 8 + wi;
                int col = ks * 16 + (grp & 1) * 8;
                uint32_t bd = smem_u32(wb + row * SSTR + col);
                asm volatile("ldmatrix.sync.aligned.m8n8.x4.shared.b16 {%0,%1,%2,%3}, [%4];"
                    : "=r"(b[np * 2][0]), "=r"(b[np * 2][1]),
                      "=r"(b[np * 2 + 1][0]), "=r"(b[np * 2 + 1][1]) : "r"(bd));
            }
            #pragma unroll
            for (int mt = 0; mt < 4; mt++)
                #pragma unroll
                for (int nt = 0; nt < 4; nt++)
                    asm volatile(
                        "mma.sync.aligned.m16n8k16.row.col.f32.bf16.bf16.f32 "
                        "{%0,%1,%2,%3}, {%4,%5,%6,%7}, {%8,%9}, {%0,%1,%2,%3};"
                        : "+f"(acc[mt][nt][0]), "+f"(acc[mt][nt][1]),
                          "+f"(acc[mt][nt][2]), "+f"(acc[mt][nt][3])
                        : "r"(a[mt][0]), "r"(a[mt][1]), "r"(a[mt][2]), "r"(a[mt][3]),
                          "r"(b[nt][0]), "r"(b[nt][1]));
        }
    }
#undef LOAD_TILE

    // epilogue
    #pragma unroll
    for (int mt = 0; mt < 4; mt++) {
        int r0 = bm + wm * 64 + mt * 16 + (lane >> 2);
        #pragma unroll
        for (int nt = 0; nt < 4; nt++) {
            int c0 = bn + wn * 32 + nt * 8 + (lane & 3) * 2;
            float* p0 = C + (size_t)r0 * N + c0;
            float* p1 = C + (size_t)(r0 + 8) * N + c0;
            if (EPI == 1) {
                p0[0] += acc[mt][nt][0]; p0[1] += acc[mt][nt][1];
                p1[0] += acc[mt][nt][2]; p1[1] += acc[mt][nt][3];
            } else {
                p0[0] = acc[mt][nt][0]; p0[1] = acc[mt][nt][1];
                p1[0] = acc[mt][nt][2]; p1[1] = acc[mt][nt][3];
            }
        }
    }
}

// ---------------- fp32 SGEMM for small shapes (x_proj, dt_proj) -------------
#define GBM 64
#define GBN 64
#define GBK 16
enum { EPI_NONE = 0, EPI_SOFTPLUS_BIAS = 1 };

// kbeg/kend: K range (multiple of GBK). If ATOMIC, accumulate into C with atomics.
template <int EPI, bool ATOMIC>
__global__ void __launch_bounds__(256)
gemm_tn_kernel(const float* __restrict__ A, int lda,
               const float* __restrict__ W, int ldw,
               float* __restrict__ C, int ldc,
               int M, int N, int kchunk,
               const float* __restrict__ bias)
{
    __shared__ float Asm[GBK][GBM + 1];
    __shared__ float Wsm[GBK][GBN + 1];

    int tid = threadIdx.x;
    int bm = blockIdx.y * GBM;
    int bn = blockIdx.x * GBN;
    int kbeg = blockIdx.z * kchunk;
    int kend = kbeg + kchunk;
    int lr = tid >> 2;
    int lk = (tid & 3) << 2;
    int ty = tid >> 4;
    int tx = tid & 15;

    float acc[4][4];
    #pragma unroll
    for (int i = 0; i < 4; i++)
        #pragma unroll
        for (int j = 0; j < 4; j++) acc[i][j] = 0.0f;

    for (int k0 = kbeg; k0 < kend; k0 += GBK) {
        {
            const float4 v = *(const float4*)(A + (size_t)(bm + lr) * lda + k0 + lk);
            Asm[lk + 0][lr] = v.x; Asm[lk + 1][lr] = v.y;
            Asm[lk + 2][lr] = v.z; Asm[lk + 3][lr] = v.w;
        }
        {
            float4 v = make_float4(0.f, 0.f, 0.f, 0.f);
            int row = bn + lr;
            if (row < N) v = *(const float4*)(W + (size_t)row * ldw + k0 + lk);
            Wsm[lk + 0][lr] = v.x; Wsm[lk + 1][lr] = v.y;
            Wsm[lk + 2][lr] = v.z; Wsm[lk + 3][lr] = v.w;
        }
        __syncthreads();
        #pragma unroll
        for (int kk = 0; kk < GBK; kk++) {
            float a[4], b[4];
            #pragma unroll
            for (int i = 0; i < 4; i++) a[i] = Asm[kk][ty * 4 + i];
            #pragma unroll
            for (int j = 0; j < 4; j++) b[j] = Wsm[kk][tx * 4 + j];
            #pragma unroll
            for (int i = 0; i < 4; i++)
                #pragma unroll
                for (int j = 0; j < 4; j++)
                    acc[i][j] = fmaf(a[i], b[j], acc[i][j]);
        }
        __syncthreads();
    }

    #pragma unroll
    for (int i = 0; i < 4; i++) {
        int row = bm + ty * 4 + i;
        #pragma unroll
        for (int j = 0; j < 4; j++) {
            int col = bn + tx * 4 + j;
            if (col < N) {
                float v = acc[i][j];
                if (ATOMIC) {
                    atomicAdd(&C[(size_t)row * ldc + col], v);
                } else {
                    if (EPI == EPI_SOFTPLUS_BIAS) v = softplusf(v + bias[col]);
                    C[(size_t)row * ldc + col] = v;
                }
            }
        }
    }
}

__global__ void zero_kernel(float* __restrict__ p, int n) {
    int i = blockIdx.x * blockDim.x + threadIdx.x;
    if (i < n) p[i] = 0.0f;
}

// ---------------- causal depthwise conv (width 4) + silu ----------------
__global__ void conv_silu_kernel(const float* __restrict__ proj,
                                 const float* __restrict__ cw,
                                 const float* __restrict__ cb,
                                 float* __restrict__ out)
{
    int idx = blockIdx.x * blockDim.x + threadIdx.x;
    if (idx >= TT * DI) return;
    int d = idx % DI;
    int t = idx / DI;
    int l = t % LL;
    float w0 = cw[d * 4 + 0], w1 = cw[d * 4 + 1], w2 = cw[d * 4 + 2], w3 = cw[d * 4 + 3];
    float acc = cb[d];
    if (l >= 3) acc = fmaf(w0, proj[(size_t)(t - 3) * (2 * DI) + d], acc);
    if (l >= 2) acc = fmaf(w1, proj[(size_t)(t - 2) * (2 * DI) + d], acc);
    if (l >= 1) acc = fmaf(w2, proj[(size_t)(t - 1) * (2 * DI) + d], acc);
    acc = fmaf(w3, proj[(size_t)t * (2 * DI) + d], acc);
    out[idx] = siluf(acc);
}

// ---------------- selective scan -> bf16x3 y [T, 3*DI] ----------------
__global__ void scan_kernel(const float* __restrict__ dt,
                            const float* __restrict__ hconv,
                            const float* __restrict__ ssm,
                            const float* __restrict__ proj,
                            const float* __restrict__ A_log,
                            const float* __restrict__ D_skip,
                            __nv_bfloat16* __restrict__ y)
{
    int s = threadIdx.x & 15;
    int d = blockIdx.x * 16 + (threadIdx.x >> 4);
    int b = blockIdx.y;

    float Aneg = -__expf(A_log[d * DS + s]);
    float Dk = D_skip[d];

    float state = 0.0f;
    for (int l = 0; l < LL; l++) {
        int t = b * LL + l;
        float dtv = dt[(size_t)t * DI + d];
        float hv  = hconv[(size_t)t * DI + d];
        float Bv  = ssm[(size_t)t * 80 + DTR + s];
        float Cv  = ssm[(size_t)t * 80 + DTR + DS + s];
        float a = __expf(dtv * Aneg);
        state = fmaf(a, state, dtv * hv * Bv);
        float p = state * Cv;
        p += __shfl_xor_sync(0xffffffffu, p, 8);
        p += __shfl_xor_sync(0xffffffffu, p, 4);
        p += __shfl_xor_sync(0xffffffffu, p, 2);
        p += __shfl_xor_sync(0xffffffffu, p, 1);
        if (s == 0) {
            float g = proj[(size_t)t * (2 * DI) + DI + d];
            float val = (p + Dk * hv) * siluf(g);
            __nv_bfloat16 hi, lo; split_bf16(val, hi, lo);
            __nv_bfloat16* dst = y + (size_t)t * (3 * DI);
            dst[d] = hi; dst[DI + d] = lo; dst[2 * DI + d] = hi;
        }
    }
}

// ---------------- launcher ----------------
extern "C" void kernel_launch(void* const* d_in, const int* in_sizes, int n_in,
                              void* d_out, int out_size)
{
    const int*   input_ids = (const int*)  d_in[0];
    const float* embed     = (const float*)d_in[1];
    const float* norm_f_w  = (const float*)d_in[2];
    const float* in_proj_w = (const float*)d_in[3];
    const float* conv_w    = (const float*)d_in[4];
    const float* conv_b    = (const float*)d_in[5];
    const float* x_proj_w  = (const float*)d_in[6];
    const float* dt_proj_w = (const float*)d_in[7];
    const float* dt_proj_b = (const float*)d_in[8];
    const float* A_log     = (const float*)d_in[9];
    const float* D_skip    = (const float*)d_in[10];
    const float* out_proj_w= (const float*)d_in[11];
    const float* norm_w    = (const float*)d_in[12];
    float* logits = (float*)d_out;

    float *ph, *pproj, *pconv, *pssm, *pdt;
    __nv_bfloat16 *pxn, *py, *pinw, *poutw, *pemb;
    cudaGetSymbolAddress((void**)&ph,    g_h);
    cudaGetSymbolAddress((void**)&pproj, g_proj);
    cudaGetSymbolAddress((void**)&pconv, g_conv);
    cudaGetSymbolAddress((void**)&pssm,  g_ssm);
    cudaGetSymbolAddress((void**)&pdt,   g_dt);
    cudaGetSymbolAddress((void**)&pxn,   g_xn_big);
    cudaGetSymbolAddress((void**)&py,    g_y_big);
    cudaGetSymbolAddress((void**)&pinw,  g_inw_big);
    cudaGetSymbolAddress((void**)&poutw, g_outw_big);
    cudaGetSymbolAddress((void**)&pemb,  g_embed_big);

    cudaFuncSetAttribute(hmma_gemm_kernel<0>, cudaFuncAttributeMaxDynamicSharedMemorySize, HMMA_SMEM);
    cudaFuncSetAttribute(hmma_gemm_kernel<1>, cudaFuncAttributeMaxDynamicSharedMemorySize, HMMA_SMEM);

    // embedding gather
    embed_kernel<<<TT, 256>>>(input_ids, embed, ph);

    // bulk weight conversions (all layers + lm head), fewer/bigger launches
    {
        dim3 ge((DM / 4 + 127) / 128, VOCAB);
        convert3_w_kernel<<<ge, 128>>>(embed, pemb, DM);
        dim3 gi((DM / 4 + 127) / 128, NL * 2 * DI);
        convert3_w_kernel<<<gi, 128>>>(in_proj_w, pinw, DM);
        dim3 go((DI / 4 + 127) / 128, NL * DM);
        convert3_w_kernel<<<go, 128>>>(out_proj_w, poutw, DI);
    }

    for (int i = 0; i < NL; i++) {
        const __nv_bfloat16* w_in3  = pinw  + (size_t)i * (2 * DI) * (3 * DM);
        const __nv_bfloat16* w_out3 = poutw + (size_t)i * DM * (3 * DI);
        const float* w_cv  = conv_w     + (size_t)i * DI * DCONV;
        const float* b_cv  = conv_b     + (size_t)i * DI;
        const float* w_xp  = x_proj_w   + (size_t)i * (DTR + 2 * DS) * DI;
        const float* w_dtp = dt_proj_w  + (size_t)i * DI * DTR;
        const float* b_dtp = dt_proj_b  + (size_t)i * DI;
        const float* a_log = A_log      + (size_t)i * DI * DS;
        const float* d_sk  = D_skip     + (size_t)i * DI;
        const float* w_nrm = norm_w     + (size_t)i * DM;

        // rmsnorm -> bf16x3
        rmsnorm3_kernel<<<TT, 256>>>(ph, w_nrm, pxn);

        // in_proj: [1024, 2304] @ [3072, 2304]^T -> proj [1024, 3072]
        {
            dim3 grid(TT / BM, (2 * DI) / BN);
            hmma_gemm_kernel<0><<<grid, 256, HMMA_SMEM>>>(pxn, w_in3, pproj, 3 * DM, 2 * DI);
        }

        // conv + silu
        conv_silu_kernel<<<(TT * DI + 255) / 256, 256>>>(pproj, w_cv, b_cv, pconv);

        // x_proj: [1024,1536] @ [80,1536]^T -> [1024,80]  (fp32, split-K=6 atomic)
        zero_kernel<<<(TT * 80 + 255) / 256, 256>>>(pssm, TT * 80);
        {
            dim3 grid((80 + GBN - 1) / GBN, TT / GBM, 6);
            gemm_tn_kernel<EPI_NONE, true><<<grid, 256>>>(
                pconv, DI, w_xp, DI, pssm, 80, TT, 80, DI / 6, nullptr);
        }

        // dt_proj + softplus: [1024,48(lda=80)] @ [1536,48]^T -> [1024,1536]
        {
            dim3 grid(DI / GBN, TT / GBM, 1);
            gemm_tn_kernel<EPI_SOFTPLUS_BIAS, false><<<grid, 256>>>(
                pssm, 80, w_dtp, DTR, pdt, DI, TT, DI, DTR, b_dtp);
        }

        // selective scan (+ D skip + gate silu) -> bf16x3 y
        {
            dim3 grid(DI / 16, BB);
            scan_kernel<<<grid, 256>>>(pdt, pconv, pssm, pproj, a_log, d_sk, py);
        }

        // out_proj + residual (in place): h += y @ w_out^T
        {
            dim3 grid(TT / BM, DM / BN);
            hmma_gemm_kernel<1><<<grid, 256, HMMA_SMEM>>>(py, w_out3, ph, 3 * DI, DM);
        }
    }

    // final rmsnorm -> bf16x3
    rmsnorm3_kernel<<<TT, 256>>>(ph, norm_f_w, pxn);

    // lm head: [1024, 2304] @ [32000, 2304]^T -> logits [1024, 32000]
    {
        dim3 grid(TT / BM, VOCAB / BN);
        hmma_gemm_kernel<0><<<grid, 256, HMMA_SMEM>>>(pxn, pemb, logits, 3 * DM, VOCAB);
    }
}

// round 5
// speedup vs baseline: 1.9050x; 1.1516x over previous
#include <cuda_runtime.h>
#include <cuda_bf16.h>
#include <cstdint>
#include <math.h>

// ---------------- problem constants ----------------
#define NL    4
#define DM    768
#define DI    1536
#define DS    16
#define DTR   48
#define DCONV 4
#define VOCAB 32000
#define BB    2
#define LL    512
#define TT    (BB*LL)          // 1024 tokens
#define EPS   1e-5f

// ---------------- scratch (static device memory; no allocations) -------------
__device__ float g_h   [TT * DM];            // residual stream (fp32)
__device__ float g_proj[TT * 2 * DI];        // in_proj output (h | gate)
__device__ float g_conv[TT * DI];            // conv + silu output
__device__ float g_ssm [TT * 80];            // x_proj output (dt_raw | B | C)
__device__ float g_dt  [TT * DI];            // softplus(dt)

// bf16x3 planes along K. Activations: [hi, lo, hi]; weights: [hi, hi, lo].
__device__ __nv_bfloat16 g_xn_big   [TT * 3 * DM];                  // rmsnorm out
__device__ __nv_bfloat16 g_y_big    [TT * 3 * DI];                  // scan out
__device__ __nv_bfloat16 g_inw_big  [(size_t)NL * (2*DI) * 3 * DM]; // all in_proj_w
__device__ __nv_bfloat16 g_outw_big [(size_t)NL * DM * 3 * DI];     // all out_proj_w
__device__ __nv_bfloat16 g_embed_big[(size_t)VOCAB * 3 * DM];       // embed (lm head)

// ---------------- helpers ----------------
__device__ __forceinline__ uint32_t smem_u32(const void* p) {
    uint32_t a;
    asm("{ .reg .u64 t; cvta.to.shared.u64 t, %1; cvt.u32.u64 %0, t; }" : "=r"(a) : "l"(p));
    return a;
}
__device__ __forceinline__ void cp_async16(uint32_t dst, const void* src) {
    asm volatile("cp.async.cg.shared.global [%0], [%1], 16;" :: "r"(dst), "l"(src));
}
#define CP_COMMIT() asm volatile("cp.async.commit_group;" ::: "memory")
#define CP_WAIT(n)  asm volatile("cp.async.wait_group %0;" :: "n"(n) : "memory")

__device__ __forceinline__ float siluf(float x) { return x / (1.0f + __expf(-x)); }
__device__ __forceinline__ float softplusf(float x) {
    return fmaxf(x, 0.0f) + log1pf(__expf(-fabsf(x)));
}
__device__ __forceinline__ void split_bf16(float v, __nv_bfloat16& hi, __nv_bfloat16& lo) {
    hi = __float2bfloat16(v);
    lo = __float2bfloat16(v - __bfloat162float(hi));
}

// ---------------- embedding gather ----------------
__global__ void embed_kernel(const int* __restrict__ ids,
                             const float* __restrict__ embed,
                             float* __restrict__ out) {
    int t = blockIdx.x;
    int id = ids[t];
    const float* src = embed + (size_t)id * DM;
    float* dst = out + (size_t)t * DM;
    for (int d = threadIdx.x; d < DM; d += blockDim.x) dst[d] = src[d];
}

// ---------------- rmsnorm -> bf16x3 activation planes [T, 3*DM] -------------
__global__ void rmsnorm3_kernel(const float* __restrict__ x,
                                const float* __restrict__ w,
                                __nv_bfloat16* __restrict__ out) {
    __shared__ float red[256];
    int t = blockIdx.x;
    const float* row = x + (size_t)t * DM;
    float s = 0.0f;
    for (int d = threadIdx.x; d < DM; d += blockDim.x) { float v = row[d]; s += v * v; }
    red[threadIdx.x] = s;
    __syncthreads();
    for (int off = 128; off > 0; off >>= 1) {
        if (threadIdx.x < off) red[threadIdx.x] += red[threadIdx.x + off];
        __syncthreads();
    }
    float scale = rsqrtf(red[0] / (float)DM + EPS);
    __nv_bfloat16* dst = out + (size_t)t * (3 * DM);
    for (int d = threadIdx.x; d < DM; d += blockDim.x) {
        float v = row[d] * scale * w[d];
        __nv_bfloat16 hi, lo; split_bf16(v, hi, lo);
        dst[d] = hi; dst[DM + d] = lo; dst[2 * DM + d] = hi;
    }
}

// ---------------- fp32 [R,C] -> bf16x3 weight planes [R,3C] (hi,hi,lo) ------
// C multiple of 4, R multiple of 4. grid: (ceil(C/4/128), R/4), 128 threads.
// 4 rows per thread for MLP.
__global__ void convert3_w_kernel(const float* __restrict__ src,
                                  __nv_bfloat16* __restrict__ dst,
                                  int C) {
    int c4 = blockIdx.x * blockDim.x + threadIdx.x;
    int C4 = C >> 2;
    if (c4 >= C4) return;
    int r0 = blockIdx.y * 4;
    #pragma unroll
    for (int rr = 0; rr < 4; rr++) {
        int r = r0 + rr;
        float4 v = *(const float4*)(src + (size_t)r * C + c4 * 4);
        __nv_bfloat16 h0, l0, h1, l1, h2, l2, h3, l3;
        split_bf16(v.x, h0, l0); split_bf16(v.y, h1, l1);
        split_bf16(v.z, h2, l2); split_bf16(v.w, h3, l3);
        __nv_bfloat162 hA = __halves2bfloat162(h0, h1);
        __nv_bfloat162 hB = __halves2bfloat162(h2, h3);
        __nv_bfloat162 lA = __halves2bfloat162(l0, l1);
        __nv_bfloat162 lB = __halves2bfloat162(l2, l3);
        __nv_bfloat16* d = dst + (size_t)r * (3 * (size_t)C) + c4 * 4;
        ((__nv_bfloat162*)d)[0] = hA;            ((__nv_bfloat162*)d)[1] = hB;
        ((__nv_bfloat162*)(d + C))[0] = hA;      ((__nv_bfloat162*)(d + C))[1] = hB;
        ((__nv_bfloat162*)(d + 2 * C))[0] = lA;  ((__nv_bfloat162*)(d + 2 * C))[1] = lB;
    }
}

// =============================================================================
// HMMA bf16 GEMM v2: C[M,N] (=/+=) A[M,Kp] @ W[N,Kp]^T
// 128x128 CTA tile, BK=32, 256 threads (8 warps: 2x4), mma.m16n8k16,
// 4-stage cp.async pipeline, precomputed smem offsets, 1 sync/iter,
// optional split-K via blockIdx.z (EPI=2: atomicAdd epilogue).
// =============================================================================
#define BM 128
#define BN 128
#define BK 32
#define SSTR 40                 // smem row stride in bf16 (32 + 8 pad)
#define NSTAGE 4
#define STAGE_ELEMS (BM * SSTR)          // 5120 bf16
#define STAGE_BYTES (STAGE_ELEMS * 2)    // 10240 B
#define HMMA_SMEM (NSTAGE * 2 * STAGE_BYTES)   // 81920 B

template <int EPI>  // 0 = store, 1 = in-place add, 2 = atomicAdd (split-K)
__global__ void __launch_bounds__(256, 2)
hmma_gemm_kernel(const __nv_bfloat16* __restrict__ A,
                 const __nv_bfloat16* __restrict__ W,
                 float* __restrict__ C, int Kp, int N, int kchunk)
{
    extern __shared__ __nv_bfloat16 dsm[];

    const int tid = threadIdx.x;
    const int lane = tid & 31;
    const int wid = tid >> 5;
    const int wm = wid >> 2;     // 0..1 -> 64 rows
    const int wn = wid & 3;      // 0..3 -> 32 cols
    const int bm = blockIdx.x * BM;
    const int bn = blockIdx.y * BN;
    const int kbeg = blockIdx.z * kchunk;

    const __nv_bfloat16* Ag = A + (size_t)bm * Kp + kbeg;
    const __nv_bfloat16* Wg = W + (size_t)bn * Kp + kbeg;

    const uint32_t sA = smem_u32(dsm);
    const uint32_t sW = sA + NSTAGE * STAGE_BYTES;

    // cp.async store offsets (bytes within a stage)
    const int ar0 = tid >> 2, ak0 = (tid & 3) * 8;
    const int ar1 = ar0 + 64;
    const uint32_t st0 = (uint32_t)(ar0 * SSTR + ak0) * 2;
    const uint32_t st1 = (uint32_t)(ar1 * SSTR + ak0) * 2;
    const __nv_bfloat16* Ag0 = Ag + (size_t)ar0 * Kp + ak0;
    const __nv_bfloat16* Ag1 = Ag + (size_t)ar1 * Kp + ak0;
    const __nv_bfloat16* Wg0 = Wg + (size_t)ar0 * Kp + ak0;
    const __nv_bfloat16* Wg1 = Wg + (size_t)ar1 * Kp + ak0;

    // ldmatrix byte offsets within a stage
    uint32_t a_off[2][4], b_off[2][2];
    {
        const int grp = lane >> 3, wi = lane & 7;
        #pragma unroll
        for (int ks = 0; ks < 2; ks++) {
            #pragma unroll
            for (int mt = 0; mt < 4; mt++) {
                int row = wm * 64 + mt * 16 + (lane & 15);
                int col = ks * 16 + (lane >> 4) * 8;
                a_off[ks][mt] = (uint32_t)(row * SSTR + col) * 2;
            }
            #pragma unroll
            for (int np = 0; np < 2; np++) {
                int row = wn * 32 + np * 16 + (grp >> 1) * 8 + wi;
                int col = ks * 16 + (grp & 1) * 8;
                b_off[ks][np] = (uint32_t)(row * SSTR + col) * 2;
            }
        }
    }

    float acc[4][4][4];
    #pragma unroll
    for (int i = 0; i < 4; i++)
        #pragma unroll
        for (int j = 0; j < 4; j++)
            #pragma unroll
            for (int k = 0; k < 4; k++) acc[i][j][k] = 0.0f;

#define LOAD_TILE(buf, k0) do { \
    uint32_t ab = sA + (buf) * STAGE_BYTES; \
    uint32_t wb = sW + (buf) * STAGE_BYTES; \
    cp_async16(ab + st0, Ag0 + (k0)); \
    cp_async16(ab + st1, Ag1 + (k0)); \
    cp_async16(wb + st0, Wg0 + (k0)); \
    cp_async16(wb + st1, Wg1 + (k0)); \
} while (0)

    const int nc = kchunk / BK;
    #pragma unroll
    for (int s = 0; s < NSTAGE - 1; s++) {
        if (s < nc) LOAD_TILE(s, s * BK);
        CP_COMMIT();
    }

    for (int c = 0; c < nc; c++) {
        CP_WAIT(2);
        __syncthreads();
        int nf = c + NSTAGE - 1;
        if (nf < nc) LOAD_TILE(nf & (NSTAGE - 1), nf * BK);
        CP_COMMIT();

        const uint32_t ab = sA + (c & (NSTAGE - 1)) * STAGE_BYTES;
        const uint32_t wb = sW + (c & (NSTAGE - 1)) * STAGE_BYTES;
        #pragma unroll
        for (int ks = 0; ks < 2; ks++) {
            uint32_t a[4][4];
            #pragma unroll
            for (int mt = 0; mt < 4; mt++)
                asm volatile("ldmatrix.sync.aligned.m8n8.x4.shared.b16 {%0,%1,%2,%3}, [%4];"
                    : "=r"(a[mt][0]), "=r"(a[mt][1]), "=r"(a[mt][2]), "=r"(a[mt][3])
                    : "r"(ab + a_off[ks][mt]));
            uint32_t b[4][2];
            #pragma unroll
            for (int np = 0; np < 2; np++)
                asm volatile("ldmatrix.sync.aligned.m8n8.x4.shared.b16 {%0,%1,%2,%3}, [%4];"
                    : "=r"(b[np * 2][0]), "=r"(b[np * 2][1]),
                      "=r"(b[np * 2 + 1][0]), "=r"(b[np * 2 + 1][1])
                    : "r"(wb + b_off[ks][np]));
            #pragma unroll
            for (int mt = 0; mt < 4; mt++)
                #pragma unroll
                for (int nt = 0; nt < 4; nt++)
                    asm volatile(
                        "mma.sync.aligned.m16n8k16.row.col.f32.bf16.bf16.f32 "
                        "{%0,%1,%2,%3}, {%4,%5,%6,%7}, {%8,%9}, {%0,%1,%2,%3};"
                        : "+f"(acc[mt][nt][0]), "+f"(acc[mt][nt][1]),
                          "+f"(acc[mt][nt][2]), "+f"(acc[mt][nt][3])
                        : "r"(a[mt][0]), "r"(a[mt][1]), "r"(a[mt][2]), "r"(a[mt][3]),
                          "r"(b[nt][0]), "r"(b[nt][1]));
        }
    }
#undef LOAD_TILE

    // epilogue
    #pragma unroll
    for (int mt = 0; mt < 4; mt++) {
        int r0 = bm + wm * 64 + mt * 16 + (lane >> 2);
        #pragma unroll
        for (int nt = 0; nt < 4; nt++) {
            int c0 = bn + wn * 32 + nt * 8 + (lane & 3) * 2;
            float* p0 = C + (size_t)r0 * N + c0;
            float* p1 = C + (size_t)(r0 + 8) * N + c0;
            if (EPI == 2) {
                atomicAdd(p0 + 0, acc[mt][nt][0]); atomicAdd(p0 + 1, acc[mt][nt][1]);
                atomicAdd(p1 + 0, acc[mt][nt][2]); atomicAdd(p1 + 1, acc[mt][nt][3]);
            } else if (EPI == 1) {
                p0[0] += acc[mt][nt][0]; p0[1] += acc[mt][nt][1];
                p1[0] += acc[mt][nt][2]; p1[1] += acc[mt][nt][3];
            } else {
                p0[0] = acc[mt][nt][0]; p0[1] = acc[mt][nt][1];
                p1[0] = acc[mt][nt][2]; p1[1] = acc[mt][nt][3];
            }
        }
    }
}

// ---------------- fp32 SGEMM for small shapes (x_proj, dt_proj) -------------
#define GBM 64
#define GBN 64
#define GBK 16
enum { EPI_NONE = 0, EPI_SOFTPLUS_BIAS = 1 };

template <int EPI, bool ATOMIC>
__global__ void __launch_bounds__(256)
gemm_tn_kernel(const float* __restrict__ A, int lda,
               const float* __restrict__ W, int ldw,
               float* __restrict__ C, int ldc,
               int M, int N, int kchunk,
               const float* __restrict__ bias)
{
    __shared__ float Asm[GBK][GBM + 1];
    __shared__ float Wsm[GBK][GBN + 1];

    int tid = threadIdx.x;
    int bm = blockIdx.y * GBM;
    int bn = blockIdx.x * GBN;
    int kbeg = blockIdx.z * kchunk;
    int kend = kbeg + kchunk;
    int lr = tid >> 2;
    int lk = (tid & 3) << 2;
    int ty = tid >> 4;
    int tx = tid & 15;

    float acc[4][4];
    #pragma unroll
    for (int i = 0; i < 4; i++)
        #pragma unroll
        for (int j = 0; j < 4; j++) acc[i][j] = 0.0f;

    for (int k0 = kbeg; k0 < kend; k0 += GBK) {
        {
            const float4 v = *(const float4*)(A + (size_t)(bm + lr) * lda + k0 + lk);
            Asm[lk + 0][lr] = v.x; Asm[lk + 1][lr] = v.y;
            Asm[lk + 2][lr] = v.z; Asm[lk + 3][lr] = v.w;
        }
        {
            float4 v = make_float4(0.f, 0.f, 0.f, 0.f);
            int row = bn + lr;
            if (row < N) v = *(const float4*)(W + (size_t)row * ldw + k0 + lk);
            Wsm[lk + 0][lr] = v.x; Wsm[lk + 1][lr] = v.y;
            Wsm[lk + 2][lr] = v.z; Wsm[lk + 3][lr] = v.w;
        }
        __syncthreads();
        #pragma unroll
        for (int kk = 0; kk < GBK; kk++) {
            float a[4], b[4];
            #pragma unroll
            for (int i = 0; i < 4; i++) a[i] = Asm[kk][ty * 4 + i];
            #pragma unroll
            for (int j = 0; j < 4; j++) b[j] = Wsm[kk][tx * 4 + j];
            #pragma unroll
            for (int i = 0; i < 4; i++)
                #pragma unroll
                for (int j = 0; j < 4; j++)
                    acc[i][j] = fmaf(a[i], b[j], acc[i][j]);
        }
        __syncthreads();
    }

    #pragma unroll
    for (int i = 0; i < 4; i++) {
        int row = bm + ty * 4 + i;
        #pragma unroll
        for (int j = 0; j < 4; j++) {
            int col = bn + tx * 4 + j;
            if (col < N) {
                float v = acc[i][j];
                if (ATOMIC) {
                    atomicAdd(&C[(size_t)row * ldc + col], v);
                } else {
                    if (EPI == EPI_SOFTPLUS_BIAS) v = softplusf(v + bias[col]);
                    C[(size_t)row * ldc + col] = v;
                }
            }
        }
    }
}

__global__ void zero_kernel(float* __restrict__ p, int n) {
    int i = blockIdx.x * blockDim.x + threadIdx.x;
    if (i < n) p[i] = 0.0f;
}

// ---------------- causal depthwise conv (width 4) + silu ----------------
__global__ void conv_silu_kernel(const float* __restrict__ proj,
                                 const float* __restrict__ cw,
                                 const float* __restrict__ cb,
                                 float* __restrict__ out)
{
    int idx = blockIdx.x * blockDim.x + threadIdx.x;
    if (idx >= TT * DI) return;
    int d = idx % DI;
    int t = idx / DI;
    int l = t % LL;
    float w0 = cw[d * 4 + 0], w1 = cw[d * 4 + 1], w2 = cw[d * 4 + 2], w3 = cw[d * 4 + 3];
    float acc = cb[d];
    if (l >= 3) acc = fmaf(w0, proj[(size_t)(t - 3) * (2 * DI) + d], acc);
    if (l >= 2) acc = fmaf(w1, proj[(size_t)(t - 2) * (2 * DI) + d], acc);
    if (l >= 1) acc = fmaf(w2, proj[(size_t)(t - 1) * (2 * DI) + d], acc);
    acc = fmaf(w3, proj[(size_t)t * (2 * DI) + d], acc);
    out[idx] = siluf(acc);
}

// ---------------- selective scan -> bf16x3 y [T, 3*DI] ----------------
__global__ void scan_kernel(const float* __restrict__ dt,
                            const float* __restrict__ hconv,
                            const float* __restrict__ ssm,
                            const float* __restrict__ proj,
                            const float* __restrict__ A_log,
                            const float* __restrict__ D_skip,
                            __nv_bfloat16* __restrict__ y)
{
    int s = threadIdx.x & 15;
    int d = blockIdx.x * 16 + (threadIdx.x >> 4);
    int b = blockIdx.y;

    float Aneg = -__expf(A_log[d * DS + s]);
    float Dk = D_skip[d];

    float state = 0.0f;
    for (int l = 0; l < LL; l++) {
        int t = b * LL + l;
        float dtv = dt[(size_t)t * DI + d];
        float hv  = hconv[(size_t)t * DI + d];
        float Bv  = ssm[(size_t)t * 80 + DTR + s];
        float Cv  = ssm[(size_t)t * 80 + DTR + DS + s];
        float a = __expf(dtv * Aneg);
        state = fmaf(a, state, dtv * hv * Bv);
        float p = state * Cv;
        p += __shfl_xor_sync(0xffffffffu, p, 8);
        p += __shfl_xor_sync(0xffffffffu, p, 4);
        p += __shfl_xor_sync(0xffffffffu, p, 2);
        p += __shfl_xor_sync(0xffffffffu, p, 1);
        if (s == 0) {
            float g = proj[(size_t)t * (2 * DI) + DI + d];
            float val = (p + Dk * hv) * siluf(g);
            __nv_bfloat16 hi, lo; split_bf16(val, hi, lo);
            __nv_bfloat16* dst = y + (size_t)t * (3 * DI);
            dst[d] = hi; dst[DI + d] = lo; dst[2 * DI + d] = hi;
        }
    }
}

// ---------------- launcher ----------------
extern "C" void kernel_launch(void* const* d_in, const int* in_sizes, int n_in,
                              void* d_out, int out_size)
{
    const int*   input_ids = (const int*)  d_in[0];
    const float* embed     = (const float*)d_in[1];
    const float* norm_f_w  = (const float*)d_in[2];
    const float* in_proj_w = (const float*)d_in[3];
    const float* conv_w    = (const float*)d_in[4];
    const float* conv_b    = (const float*)d_in[5];
    const float* x_proj_w  = (const float*)d_in[6];
    const float* dt_proj_w = (const float*)d_in[7];
    const float* dt_proj_b = (const float*)d_in[8];
    const float* A_log     = (const float*)d_in[9];
    const float* D_skip    = (const float*)d_in[10];
    const float* out_proj_w= (const float*)d_in[11];
    const float* norm_w    = (const float*)d_in[12];
    float* logits = (float*)d_out;

    float *ph, *pproj, *pconv, *pssm, *pdt;
    __nv_bfloat16 *pxn, *py, *pinw, *poutw, *pemb;
    cudaGetSymbolAddress((void**)&ph,    g_h);
    cudaGetSymbolAddress((void**)&pproj, g_proj);
    cudaGetSymbolAddress((void**)&pconv, g_conv);
    cudaGetSymbolAddress((void**)&pssm,  g_ssm);
    cudaGetSymbolAddress((void**)&pdt,   g_dt);
    cudaGetSymbolAddress((void**)&pxn,   g_xn_big);
    cudaGetSymbolAddress((void**)&py,    g_y_big);
    cudaGetSymbolAddress((void**)&pinw,  g_inw_big);
    cudaGetSymbolAddress((void**)&poutw, g_outw_big);
    cudaGetSymbolAddress((void**)&pemb,  g_embed_big);

    cudaFuncSetAttribute(hmma_gemm_kernel<0>, cudaFuncAttributeMaxDynamicSharedMemorySize, HMMA_SMEM);
    cudaFuncSetAttribute(hmma_gemm_kernel<1>, cudaFuncAttributeMaxDynamicSharedMemorySize, HMMA_SMEM);
    cudaFuncSetAttribute(hmma_gemm_kernel<2>, cudaFuncAttributeMaxDynamicSharedMemorySize, HMMA_SMEM);

    // embedding gather
    embed_kernel<<<TT, 256>>>(input_ids, embed, ph);

    // bulk weight conversions (all layers + lm head)
    {
        dim3 ge((DM / 4 + 127) / 128, VOCAB / 4);
        convert3_w_kernel<<<ge, 128>>>(embed, pemb, DM);
        dim3 gi((DM / 4 + 127) / 128, (NL * 2 * DI) / 4);
        convert3_w_kernel<<<gi, 128>>>(in_proj_w, pinw, DM);
        dim3 go((DI / 4 + 127) / 128, (NL * DM) / 4);
        convert3_w_kernel<<<go, 128>>>(out_proj_w, poutw, DI);
    }

    for (int i = 0; i < NL; i++) {
        const __nv_bfloat16* w_in3  = pinw  + (size_t)i * (2 * DI) * (3 * DM);
        const __nv_bfloat16* w_out3 = poutw + (size_t)i * DM * (3 * DI);
        const float* w_cv  = conv_w     + (size_t)i * DI * DCONV;
        const float* b_cv  = conv_b     + (size_t)i * DI;
        const float* w_xp  = x_proj_w   + (size_t)i * (DTR + 2 * DS) * DI;
        const float* w_dtp = dt_proj_w  + (size_t)i * DI * DTR;
        const float* b_dtp = dt_proj_b  + (size_t)i * DI;
        const float* a_log = A_log      + (size_t)i * DI * DS;
        const float* d_sk  = D_skip     + (size_t)i * DI;
        const float* w_nrm = norm_w     + (size_t)i * DM;

        // rmsnorm -> bf16x3
        rmsnorm3_kernel<<<TT, 256>>>(ph, w_nrm, pxn);

        // in_proj: [1024, 2304] @ [3072, 2304]^T -> proj [1024, 3072]
        {
            dim3 grid(TT / BM, (2 * DI) / BN, 1);
            hmma_gemm_kernel<0><<<grid, 256, HMMA_SMEM>>>(pxn, w_in3, pproj, 3 * DM, 2 * DI, 3 * DM);
        }

        // conv + silu
        conv_silu_kernel<<<(TT * DI + 255) / 256, 256>>>(pproj, w_cv, b_cv, pconv);

        // x_proj: [1024,1536] @ [80,1536]^T -> [1024,80]  (fp32, split-K=6 atomic)
        zero_kernel<<<(TT * 80 + 255) / 256, 256>>>(pssm, TT * 80);
        {
            dim3 grid((80 + GBN - 1) / GBN, TT / GBM, 6);
            gemm_tn_kernel<EPI_NONE, true><<<grid, 256>>>(
                pconv, DI, w_xp, DI, pssm, 80, TT, 80, DI / 6, nullptr);
        }

        // dt_proj + softplus: [1024,48(lda=80)] @ [1536,48]^T -> [1024,1536]
        {
            dim3 grid(DI / GBN, TT / GBM, 1);
            gemm_tn_kernel<EPI_SOFTPLUS_BIAS, false><<<grid, 256>>>(
                pssm, 80, w_dtp, DTR, pdt, DI, TT, DI, DTR, b_dtp);
        }

        // selective scan (+ D skip + gate silu) -> bf16x3 y
        {
            dim3 grid(DI / 16, BB);
            scan_kernel<<<grid, 256>>>(pdt, pconv, pssm, pproj, a_log, d_sk, py);
        }

        // out_proj + residual: h += y @ w_out^T, split-K=4 (atomicAdd into h)
        {
            dim3 grid(TT / BM, DM / BN, 4);
            hmma_gemm_kernel<2><<<grid, 256, HMMA_SMEM>>>(py, w_out3, ph, 3 * DI, DM, (3 * DI) / 4);
        }
    }

    // final rmsnorm -> bf16x3
    rmsnorm3_kernel<<<TT, 256>>>(ph, norm_f_w, pxn);

    // lm head: [1024, 2304] @ [32000, 2304]^T -> logits [1024, 32000]
    {
        dim3 grid(TT / BM, VOCAB / BN, 1);
        hmma_gemm_kernel<0><<<grid, 256, HMMA_SMEM>>>(pxn, pemb, logits, 3 * DM, VOCAB, 3 * DM);
    }
}

// round 7
// speedup vs baseline: 2.0141x; 1.0573x over previous
#include <cuda_runtime.h>
#include <cuda_bf16.h>
#include <cstdint>
#include <math.h>

// ---------------- problem constants ----------------
#define NL    4
#define DM    768
#define DI    1536
#define DS    16
#define DTR   48
#define DCONV 4
#define VOCAB 32000
#define BB    2
#define LL    512
#define TT    (BB*LL)          // 1024 tokens
#define EPS   1e-5f

// ---------------- scratch (static device memory; no allocations) -------------
__device__ float g_h   [TT * DM];            // residual stream (fp32)
__device__ float g_proj[TT * 2 * DI];        // in_proj output (h | gate)
__device__ float g_conv[TT * DI];            // conv + silu output
__device__ float g_ssm [TT * 80];            // x_proj output (dt_raw | B | C)
__device__ float g_dt  [TT * DI];            // softplus(dt)

// bf16x3 planes along K. Activations: [hi, lo, hi]; weights: [hi, hi, lo].
__device__ __nv_bfloat16 g_xn_big   [TT * 3 * DM];                  // rmsnorm out
__device__ __nv_bfloat16 g_y_big    [TT * 3 * DI];                  // scan out
__device__ __nv_bfloat16 g_inw_big  [(size_t)NL * (2*DI) * 3 * DM]; // all in_proj_w
__device__ __nv_bfloat16 g_outw_big [(size_t)NL * DM * 3 * DI];     // all out_proj_w
__device__ __nv_bfloat16 g_embed_big[(size_t)VOCAB * 3 * DM];       // embed (lm head)

// ---------------- helpers ----------------
__device__ __forceinline__ uint32_t smem_u32(const void* p) {
    uint32_t a;
    asm("{ .reg .u64 t; cvta.to.shared.u64 t, %1; cvt.u32.u64 %0, t; }" : "=r"(a) : "l"(p));
    return a;
}
__device__ __forceinline__ void cp_async16(uint32_t dst, const void* src) {
    asm volatile("cp.async.cg.shared.global [%0], [%1], 16;" :: "r"(dst), "l"(src));
}
#define CP_COMMIT() asm volatile("cp.async.commit_group;" ::: "memory")
#define CP_WAIT(n)  asm volatile("cp.async.wait_group %0;" :: "n"(n) : "memory")

__device__ __forceinline__ float siluf(float x) { return x / (1.0f + __expf(-x)); }
__device__ __forceinline__ float softplusf(float x) {
    return fmaxf(x, 0.0f) + log1pf(__expf(-fabsf(x)));
}
__device__ __forceinline__ void split_bf16(float v, __nv_bfloat16& hi, __nv_bfloat16& lo) {
    hi = __float2bfloat16(v);
    lo = __float2bfloat16(v - __bfloat162float(hi));
}

// ---------------- embedding gather ----------------
__global__ void embed_kernel(const int* __restrict__ ids,
                             const float* __restrict__ embed,
                             float* __restrict__ out) {
    int t = blockIdx.x;
    int id = ids[t];
    const float* src = embed + (size_t)id * DM;
    float* dst = out + (size_t)t * DM;
    for (int d = threadIdx.x; d < DM; d += blockDim.x) dst[d] = src[d];
}

// ---------------- rmsnorm -> bf16x3 activation planes [T, 3*DM] -------------
__global__ void rmsnorm3_kernel(const float* __restrict__ x,
                                const float* __restrict__ w,
                                __nv_bfloat16* __restrict__ out) {
    __shared__ float red[256];
    int t = blockIdx.x;
    const float* row = x + (size_t)t * DM;
    float s = 0.0f;
    for (int d = threadIdx.x; d < DM; d += blockDim.x) { float v = row[d]; s += v * v; }
    red[threadIdx.x] = s;
    __syncthreads();
    for (int off = 128; off > 0; off >>= 1) {
        if (threadIdx.x < off) red[threadIdx.x] += red[threadIdx.x + off];
        __syncthreads();
    }
    float scale = rsqrtf(red[0] / (float)DM + EPS);
    __nv_bfloat16* dst = out + (size_t)t * (3 * DM);
    for (int d = threadIdx.x; d < DM; d += blockDim.x) {
        float v = row[d] * scale * w[d];
        __nv_bfloat16 hi, lo; split_bf16(v, hi, lo);
        dst[d] = hi; dst[DM + d] = lo; dst[2 * DM + d] = hi;
    }
}

// ---------------- fp32 [R,C] -> bf16x3 weight planes [R,3C] (hi,hi,lo) ------
// C multiple of 8, R multiple of 4. 8 cols x 4 rows per thread, 16B stores.
__global__ void convert3_w_kernel(const float* __restrict__ src,
                                  __nv_bfloat16* __restrict__ dst,
                                  int C) {
    int c8 = blockIdx.x * blockDim.x + threadIdx.x;
    int C8 = C >> 3;
    if (c8 >= C8) return;
    int r0 = blockIdx.y * 4;
    #pragma unroll
    for (int rr = 0; rr < 4; rr++) {
        int r = r0 + rr;
        const float* s = src + (size_t)r * C + c8 * 8;
        float4 v0 = *(const float4*)(s);
        float4 v1 = *(const float4*)(s + 4);
        __nv_bfloat16 h[8], l[8];
        split_bf16(v0.x, h[0], l[0]); split_bf16(v0.y, h[1], l[1]);
        split_bf16(v0.z, h[2], l[2]); split_bf16(v0.w, h[3], l[3]);
        split_bf16(v1.x, h[4], l[4]); split_bf16(v1.y, h[5], l[5]);
        split_bf16(v1.z, h[6], l[6]); split_bf16(v1.w, h[7], l[7]);
        uint4 hv, lv;
        ((__nv_bfloat162*)&hv)[0] = __halves2bfloat162(h[0], h[1]);
        ((__nv_bfloat162*)&hv)[1] = __halves2bfloat162(h[2], h[3]);
        ((__nv_bfloat162*)&hv)[2] = __halves2bfloat162(h[4], h[5]);
        ((__nv_bfloat162*)&hv)[3] = __halves2bfloat162(h[6], h[7]);
        ((__nv_bfloat162*)&lv)[0] = __halves2bfloat162(l[0], l[1]);
        ((__nv_bfloat162*)&lv)[1] = __halves2bfloat162(l[2], l[3]);
        ((__nv_bfloat162*)&lv)[2] = __halves2bfloat162(l[4], l[5]);
        ((__nv_bfloat162*)&lv)[3] = __halves2bfloat162(l[6], l[7]);
        __nv_bfloat16* d = dst + (size_t)r * (3 * (size_t)C) + c8 * 8;
        *(uint4*)(d)         = hv;
        *(uint4*)(d + C)     = hv;
        *(uint4*)(d + 2 * C) = lv;
    }
}

// =============================================================================
// HMMA bf16 GEMM v3: C[M,N] (=/+=) A[M,Kp] @ W[N,Kp]^T
// 128x128 CTA tile, BK=64, 256 threads (8 warps: 2x4), mma.m16n8k16,
// 3-stage cp.async pipeline with ROTATING buffer counters, 1 sync/iter,
// split-K via blockIdx.z (EPI=2: atomicAdd epilogue).
// =============================================================================
#define BM 128
#define BN 128
#define BK 64
#define SSTR 72                 // smem row stride in bf16 (64 + 8 pad)
#define NSTAGE 3
#define STAGE_ELEMS (BM * SSTR)          // 9216 bf16
#define STAGE_BYTES (STAGE_ELEMS * 2)    // 18432 B
#define HMMA_SMEM (NSTAGE * 2 * STAGE_BYTES)   // 110592 B

template <int EPI>  // 0 = store, 1 = in-place add, 2 = atomicAdd (split-K)
__global__ void __launch_bounds__(256, 2)
hmma_gemm_kernel(const __nv_bfloat16* __restrict__ A,
                 const __nv_bfloat16* __restrict__ W,
                 float* __restrict__ C, int Kp, int N, int kchunk)
{
    extern __shared__ __nv_bfloat16 dsm[];

    const int tid = threadIdx.x;
    const int lane = tid & 31;
    const int wid = tid >> 5;
    const int wm = wid >> 2;     // 0..1 -> 64 rows
    const int wn = wid & 3;      // 0..3 -> 32 cols
    const int bm = blockIdx.x * BM;
    const int bn = blockIdx.y * BN;
    const int kbeg = blockIdx.z * kchunk;

    const uint32_t sA = smem_u32(dsm);
    const uint32_t sW = sA + NSTAGE * STAGE_BYTES;

    // cp.async: 64 bf16 per row = 8 x 16B chunks. thread -> (row tid>>3, chunk tid&7)
    const int ar0 = tid >> 3;            // 0..31
    const int ak0 = (tid & 7) * 8;       // 0..56
    const __nv_bfloat16* Ag = A + (size_t)bm * Kp + kbeg + ak0;
    const __nv_bfloat16* Wg = W + (size_t)bn * Kp + kbeg + ak0;
    uint32_t stoff[4];
    const __nv_bfloat16 *Agp[4], *Wgp[4];
    #pragma unroll
    for (int q = 0; q < 4; q++) {
        int row = ar0 + q * 32;
        stoff[q] = (uint32_t)(row * SSTR + ak0) * 2;
        Agp[q] = Ag + (size_t)row * Kp;
        Wgp[q] = Wg + (size_t)row * Kp;
    }

    // ldmatrix byte offsets (base at ks=0; add ks*32 bytes per 16-deep k-step)
    uint32_t a_base[4], b_base[2];
    {
        const int grp = lane >> 3, wi = lane & 7;
        #pragma unroll
        for (int mt = 0; mt < 4; mt++) {
            int row = wm * 64 + mt * 16 + (lane & 15);
            int col = (lane >> 4) * 8;
            a_base[mt] = (uint32_t)(row * SSTR + col) * 2;
        }
        #pragma unroll
        for (int np = 0; np < 2; np++) {
            int row = wn * 32 + np * 16 + (grp >> 1) * 8 + wi;
            int col = (grp & 1) * 8;
            b_base[np] = (uint32_t)(row * SSTR + col) * 2;
        }
    }

    float acc[4][4][4];
    #pragma unroll
    for (int i = 0; i < 4; i++)
        #pragma unroll
        for (int j = 0; j < 4; j++)
            #pragma unroll
            for (int k = 0; k < 4; k++) acc[i][j][k] = 0.0f;

#define LOAD_TILE(buf, k0) do { \
    uint32_t ab_ = sA + (buf) * STAGE_BYTES; \
    uint32_t wb_ = sW + (buf) * STAGE_BYTES; \
    _Pragma("unroll") \
    for (int q = 0; q < 4; q++) { \
        cp_async16(ab_ + stoff[q], Agp[q] + (k0)); \
        cp_async16(wb_ + stoff[q], Wgp[q] + (k0)); \
    } \
} while (0)

    const int nc = kchunk / BK;
    LOAD_TILE(0, 0); CP_COMMIT();
    LOAD_TILE(1, BK); CP_COMMIT();

    int load_buf = 2;   // next buffer to fill (rotating 0..NSTAGE-1)
    int cons_buf = 0;   // buffer consumed this iteration

    for (int c = 0; c < nc; c++) {
        CP_WAIT(1);
        __syncthreads();
        int nf = c + 2;
        if (nf < nc) LOAD_TILE(load_buf, nf * BK);
        CP_COMMIT();
        if (++load_buf == NSTAGE) load_buf = 0;

        const uint32_t ab = sA + cons_buf * STAGE_BYTES;
        const uint32_t wb = sW + cons_buf * STAGE_BYTES;
        if (++cons_buf == NSTAGE) cons_buf = 0;

        #pragma unroll
        for (int ks = 0; ks < 4; ks++) {
            uint32_t a[4][4];
            #pragma unroll
            for (int mt = 0; mt < 4; mt++)
                asm volatile("ldmatrix.sync.aligned.m8n8.x4.shared.b16 {%0,%1,%2,%3}, [%4];"
                    : "=r"(a[mt][0]), "=r"(a[mt][1]), "=r"(a[mt][2]), "=r"(a[mt][3])
                    : "r"(ab + a_base[mt] + ks * 32));
            uint32_t b[4][2];
            #pragma unroll
            for (int np = 0; np < 2; np++)
                asm volatile("ldmatrix.sync.aligned.m8n8.x4.shared.b16 {%0,%1,%2,%3}, [%4];"
                    : "=r"(b[np * 2][0]), "=r"(b[np * 2][1]),
                      "=r"(b[np * 2 + 1][0]), "=r"(b[np * 2 + 1][1])
                    : "r"(wb + b_base[np] + ks * 32));
            #pragma unroll
            for (int mt = 0; mt < 4; mt++)
                #pragma unroll
                for (int nt = 0; nt < 4; nt++)
                    asm volatile(
                        "mma.sync.aligned.m16n8k16.row.col.f32.bf16.bf16.f32 "
                        "{%0,%1,%2,%3}, {%4,%5,%6,%7}, {%8,%9}, {%0,%1,%2,%3};"
                        : "+f"(acc[mt][nt][0]), "+f"(acc[mt][nt][1]),
                          "+f"(acc[mt][nt][2]), "+f"(acc[mt][nt][3])
                        : "r"(a[mt][0]), "r"(a[mt][1]), "r"(a[mt][2]), "r"(a[mt][3]),
                          "r"(b[nt][0]), "r"(b[nt][1]));
        }
    }
#undef LOAD_TILE

    // epilogue
    #pragma unroll
    for (int mt = 0; mt < 4; mt++) {
        int r0 = bm + wm * 64 + mt * 16 + (lane >> 2);
        #pragma unroll
        for (int nt = 0; nt < 4; nt++) {
            int c0 = bn + wn * 32 + nt * 8 + (lane & 3) * 2;
            float* p0 = C + (size_t)r0 * N + c0;
            float* p1 = C + (size_t)(r0 + 8) * N + c0;
            if (EPI == 2) {
                atomicAdd(p0 + 0, acc[mt][nt][0]); atomicAdd(p0 + 1, acc[mt][nt][1]);
                atomicAdd(p1 + 0, acc[mt][nt][2]); atomicAdd(p1 + 1, acc[mt][nt][3]);
            } else if (EPI == 1) {
                p0[0] += acc[mt][nt][0]; p0[1] += acc[mt][nt][1];
                p1[0] += acc[mt][nt][2]; p1[1] += acc[mt][nt][3];
            } else {
                p0[0] = acc[mt][nt][0]; p0[1] = acc[mt][nt][1];
                p1[0] = acc[mt][nt][2]; p1[1] = acc[mt][nt][3];
            }
        }
    }
}

// ---------------- fp32 SGEMM for small shapes (x_proj, dt_proj) -------------
#define GBM 64
#define GBN 64
#define GBK 16
enum { EPI_NONE = 0, EPI_SOFTPLUS_BIAS = 1 };

template <int EPI, bool ATOMIC>
__global__ void __launch_bounds__(256)
gemm_tn_kernel(const float* __restrict__ A, int lda,
               const float* __restrict__ W, int ldw,
               float* __restrict__ C, int ldc,
               int M, int N, int kchunk,
               const float* __restrict__ bias)
{
    __shared__ float Asm[GBK][GBM + 1];
    __shared__ float Wsm[GBK][GBN + 1];

    int tid = threadIdx.x;
    int bm = blockIdx.y * GBM;
    int bn = blockIdx.x * GBN;
    int kbeg = blockIdx.z * kchunk;
    int kend = kbeg + kchunk;
    int lr = tid >> 2;
    int lk = (tid & 3) << 2;
    int ty = tid >> 4;
    int tx = tid & 15;

    float acc[4][4];
    #pragma unroll
    for (int i = 0; i < 4; i++)
        #pragma unroll
        for (int j = 0; j < 4; j++) acc[i][j] = 0.0f;

    for (int k0 = kbeg; k0 < kend; k0 += GBK) {
        {
            const float4 v = *(const float4*)(A + (size_t)(bm + lr) * lda + k0 + lk);
            Asm[lk + 0][lr] = v.x; Asm[lk + 1][lr] = v.y;
            Asm[lk + 2][lr] = v.z; Asm[lk + 3][lr] = v.w;
        }
        {
            float4 v = make_float4(0.f, 0.f, 0.f, 0.f);
            int row = bn + lr;
            if (row < N) v = *(const float4*)(W + (size_t)row * ldw + k0 + lk);
            Wsm[lk + 0][lr] = v.x; Wsm[lk + 1][lr] = v.y;
            Wsm[lk + 2][lr] = v.z; Wsm[lk + 3][lr] = v.w;
        }
        __syncthreads();
        #pragma unroll
        for (int kk = 0; kk < GBK; kk++) {
            float a[4], b[4];
            #pragma unroll
            for (int i = 0; i < 4; i++) a[i] = Asm[kk][ty * 4 + i];
            #pragma unroll
            for (int j = 0; j < 4; j++) b[j] = Wsm[kk][tx * 4 + j];
            #pragma unroll
            for (int i = 0; i < 4; i++)
                #pragma unroll
                for (int j = 0; j < 4; j++)
                    acc[i][j] = fmaf(a[i], b[j], acc[i][j]);
        }
        __syncthreads();
    }

    #pragma unroll
    for (int i = 0; i < 4; i++) {
        int row = bm + ty * 4 + i;
        #pragma unroll
        for (int j = 0; j < 4; j++) {
            int col = bn + tx * 4 + j;
            if (col < N) {
                float v = acc[i][j];
                if (ATOMIC) {
                    atomicAdd(&C[(size_t)row * ldc + col], v);
                } else {
                    if (EPI == EPI_SOFTPLUS_BIAS) v = softplusf(v + bias[col]);
                    C[(size_t)row * ldc + col] = v;
                }
            }
        }
    }
}

__global__ void zero_kernel(float* __restrict__ p, int n) {
    int i = blockIdx.x * blockDim.x + threadIdx.x;
    if (i < n) p[i] = 0.0f;
}

// ---------------- causal depthwise conv (width 4) + silu ----------------
__global__ void conv_silu_kernel(const float* __restrict__ proj,
                                 const float* __restrict__ cw,
                                 const float* __restrict__ cb,
                                 float* __restrict__ out)
{
    int idx = blockIdx.x * blockDim.x + threadIdx.x;
    if (idx >= TT * DI) return;
    int d = idx % DI;
    int t = idx / DI;
    int l = t % LL;
    float w0 = cw[d * 4 + 0], w1 = cw[d * 4 + 1], w2 = cw[d * 4 + 2], w3 = cw[d * 4 + 3];
    float acc = cb[d];
    if (l >= 3) acc = fmaf(w0, proj[(size_t)(t - 3) * (2 * DI) + d], acc);
    if (l >= 2) acc = fmaf(w1, proj[(size_t)(t - 2) * (2 * DI) + d], acc);
    if (l >= 1) acc = fmaf(w2, proj[(size_t)(t - 1) * (2 * DI) + d], acc);
    acc = fmaf(w3, proj[(size_t)t * (2 * DI) + d], acc);
    out[idx] = siluf(acc);
}

// ---------------- selective scan -> bf16x3 y [T, 3*DI] ----------------
__global__ void scan_kernel(const float* __restrict__ dt,
                            const float* __restrict__ hconv,
                            const float* __restrict__ ssm,
                            const float* __restrict__ proj,
                            const float* __restrict__ A_log,
                            const float* __restrict__ D_skip,
                            __nv_bfloat16* __restrict__ y)
{
    int s = threadIdx.x & 15;
    int d = blockIdx.x * 16 + (threadIdx.x >> 4);
    int b = blockIdx.y;

    float Aneg = -__expf(A_log[d * DS + s]);
    float Dk = D_skip[d];

    float state = 0.0f;
    for (int l = 0; l < LL; l++) {
        int t = b * LL + l;
        float dtv = dt[(size_t)t * DI + d];
        float hv  = hconv[(size_t)t * DI + d];
        float Bv  = ssm[(size_t)t * 80 + DTR + s];
        float Cv  = ssm[(size_t)t * 80 + DTR + DS + s];
        float a = __expf(dtv * Aneg);
        state = fmaf(a, state, dtv * hv * Bv);
        float p = state * Cv;
        p += __shfl_xor_sync(0xffffffffu, p, 8);
        p += __shfl_xor_sync(0xffffffffu, p, 4);
        p += __shfl_xor_sync(0xffffffffu, p, 2);
        p += __shfl_xor_sync(0xffffffffu, p, 1);
        if (s == 0) {
            float g = proj[(size_t)t * (2 * DI) + DI + d];
            float val = (p + Dk * hv) * siluf(g);
            __nv_bfloat16 hi, lo; split_bf16(val, hi, lo);
            __nv_bfloat16* dst = y + (size_t)t * (3 * DI);
            dst[d] = hi; dst[DI + d] = lo; dst[2 * DI + d] = hi;
        }
    }
}

// ---------------- launcher ----------------
extern "C" void kernel_launch(void* const* d_in, const int* in_sizes, int n_in,
                              void* d_out, int out_size)
{
    const int*   input_ids = (const int*)  d_in[0];
    const float* embed     = (const float*)d_in[1];
    const float* norm_f_w  = (const float*)d_in[2];
    const float* in_proj_w = (const float*)d_in[3];
    const float* conv_w    = (const float*)d_in[4];
    const float* conv_b    = (const float*)d_in[5];
    const float* x_proj_w  = (const float*)d_in[6];
    const float* dt_proj_w = (const float*)d_in[7];
    const float* dt_proj_b = (const float*)d_in[8];
    const float* A_log     = (const float*)d_in[9];
    const float* D_skip    = (const float*)d_in[10];
    const float* out_proj_w= (const float*)d_in[11];
    const float* norm_w    = (const float*)d_in[12];
    float* logits = (float*)d_out;

    float *ph, *pproj, *pconv, *pssm, *pdt;
    __nv_bfloat16 *pxn, *py, *pinw, *poutw, *pemb;
    cudaGetSymbolAddress((void**)&ph,    g_h);
    cudaGetSymbolAddress((void**)&pproj, g_proj);
    cudaGetSymbolAddress((void**)&pconv, g_conv);
    cudaGetSymbolAddress((void**)&pssm,  g_ssm);
    cudaGetSymbolAddress((void**)&pdt,   g_dt);
    cudaGetSymbolAddress((void**)&pxn,   g_xn_big);
    cudaGetSymbolAddress((void**)&py,    g_y_big);
    cudaGetSymbolAddress((void**)&pinw,  g_inw_big);
    cudaGetSymbolAddress((void**)&poutw, g_outw_big);
    cudaGetSymbolAddress((void**)&pemb,  g_embed_big);

    cudaFuncSetAttribute(hmma_gemm_kernel<0>, cudaFuncAttributeMaxDynamicSharedMemorySize, HMMA_SMEM);
    cudaFuncSetAttribute(hmma_gemm_kernel<1>, cudaFuncAttributeMaxDynamicSharedMemorySize, HMMA_SMEM);
    cudaFuncSetAttribute(hmma_gemm_kernel<2>, cudaFuncAttributeMaxDynamicSharedMemorySize, HMMA_SMEM);

    // embedding gather
    embed_kernel<<<TT, 256>>>(input_ids, embed, ph);

    // bulk weight conversions (all layers + lm head)
    {
        dim3 ge((DM / 8 + 127) / 128, VOCAB / 4);
        convert3_w_kernel<<<ge, 128>>>(embed, pemb, DM);
        dim3 gi((DM / 8 + 127) / 128, (NL * 2 * DI) / 4);
        convert3_w_kernel<<<gi, 128>>>(in_proj_w, pinw, DM);
        dim3 go((DI / 8 + 127) / 128, (NL * DM) / 4);
        convert3_w_kernel<<<go, 128>>>(out_proj_w, poutw, DI);
    }

    for (int i = 0; i < NL; i++) {
        const __nv_bfloat16* w_in3  = pinw  + (size_t)i * (2 * DI) * (3 * DM);
        const __nv_bfloat16* w_out3 = poutw + (size_t)i * DM * (3 * DI);
        const float* w_cv  = conv_w     + (size_t)i * DI * DCONV;
        const float* b_cv  = conv_b     + (size_t)i * DI;
        const float* w_xp  = x_proj_w   + (size_t)i * (DTR + 2 * DS) * DI;
        const float* w_dtp = dt_proj_w  + (size_t)i * DI * DTR;
        const float* b_dtp = dt_proj_b  + (size_t)i * DI;
        const float* a_log = A_log      + (size_t)i * DI * DS;
        const float* d_sk  = D_skip     + (size_t)i * DI;
        const float* w_nrm = norm_w     + (size_t)i * DM;

        // rmsnorm -> bf16x3
        rmsnorm3_kernel<<<TT, 256>>>(ph, w_nrm, pxn);

        // in_proj: [1024, 2304] @ [3072, 2304]^T -> proj [1024, 3072]
        // split-K=3 (576 CTAs ~ 2 full waves), atomic accumulate into zeroed proj
        zero_kernel<<<(TT * 2 * DI + 255) / 256, 256>>>(pproj, TT * 2 * DI);
        {
            dim3 grid(TT / BM, (2 * DI) / BN, 3);
            hmma_gemm_kernel<2><<<grid, 256, HMMA_SMEM>>>(pxn, w_in3, pproj, 3 * DM, 2 * DI, (3 * DM) / 3);
        }

        // conv + silu
        conv_silu_kernel<<<(TT * DI + 255) / 256, 256>>>(pproj, w_cv, b_cv, pconv);

        // x_proj: [1024,1536] @ [80,1536]^T -> [1024,80]  (fp32, split-K=6 atomic)
        zero_kernel<<<(TT * 80 + 255) / 256, 256>>>(pssm, TT * 80);
        {
            dim3 grid((80 + GBN - 1) / GBN, TT / GBM, 6);
            gemm_tn_kernel<EPI_NONE, true><<<grid, 256>>>(
                pconv, DI, w_xp, DI, pssm, 80, TT, 80, DI / 6, nullptr);
        }

        // dt_proj + softplus: [1024,48(lda=80)] @ [1536,48]^T -> [1024,1536]
        {
            dim3 grid(DI / GBN, TT / GBM, 1);
            gemm_tn_kernel<EPI_SOFTPLUS_BIAS, false><<<grid, 256>>>(
                pssm, 80, w_dtp, DTR, pdt, DI, TT, DI, DTR, b_dtp);
        }

        // selective scan (+ D skip + gate silu) -> bf16x3 y
        {
            dim3 grid(DI / 16, BB);
            scan_kernel<<<grid, 256>>>(pdt, pconv, pssm, pproj, a_log, d_sk, py);
        }

        // out_proj + residual: h += y @ w_out^T, split-K=6 (288 CTAs ~ 1 wave)
        {
            dim3 grid(TT / BM, DM / BN, 6);
            hmma_gemm_kernel<2><<<grid, 256, HMMA_SMEM>>>(py, w_out3, ph, 3 * DI, DM, (3 * DI) / 6);
        }
    }

    // final rmsnorm -> bf16x3
    rmsnorm3_kernel<<<TT, 256>>>(ph, norm_f_w, pxn);

    // lm head: [1024, 2304] @ [32000, 2304]^T -> logits [1024, 32000]
    {
        dim3 grid(TT / BM, VOCAB / BN, 1);
        hmma_gemm_kernel<0><<<grid, 256, HMMA_SMEM>>>(pxn, pemb, logits, 3 * DM, VOCAB, 3 * DM);
    }
}

// round 9
// speedup vs baseline: 2.1161x; 1.0506x over previous
#include <cuda_runtime.h>
#include <cuda_bf16.h>
#include <cuda_fp16.h>
#include <cstdint>
#include <math.h>

// ---------------- problem constants ----------------
#define NL    4
#define DM    768
#define DI    1536
#define DS    16
#define DTR   48
#define DCONV 4
#define VOCAB 32000
#define BB    2
#define LL    512
#define TT    (BB*LL)          // 1024 tokens
#define EPS   1e-5f

// ---------------- scratch (static device memory; no allocations) -------------
__device__ float g_h   [TT * DM];            // residual stream (fp32)
__device__ float g_proj[TT * 2 * DI];        // in_proj output (h | gate)
__device__ float g_conv[TT * DI];            // conv + silu output
__device__ float g_ssm [TT * 80];            // x_proj output (dt_raw | B | C)
__device__ float g_dt  [TT * DI];            // softplus(dt)

// Layer GEMMs: bf16x3 planes along K. Activations [hi,lo,hi]; weights [hi,hi,lo].
__device__ __nv_bfloat16 g_xn_big   [TT * 3 * DM];                  // rmsnorm out (layers)
__device__ __nv_bfloat16 g_y_big    [TT * 3 * DI];                  // scan out
__device__ __nv_bfloat16 g_inw_big  [(size_t)NL * (2*DI) * 3 * DM]; // all in_proj_w
__device__ __nv_bfloat16 g_outw_big [(size_t)NL * DM * 3 * DI];     // all out_proj_w
// lm head: fp16 2-plane. Activations [hi, lo]; weights [hi, hi].
__device__ __half g_xn_half   [TT * 2 * DM];                        // final rmsnorm out
__device__ __half g_embed_half[(size_t)VOCAB * 2 * DM];             // embed (lm head)

// ---------------- helpers ----------------
__device__ __forceinline__ uint32_t smem_u32(const void* p) {
    uint32_t a;
    asm("{ .reg .u64 t; cvta.to.shared.u64 t, %1; cvt.u32.u64 %0, t; }" : "=r"(a) : "l"(p));
    return a;
}
__device__ __forceinline__ void cp_async16(uint32_t dst, const void* src) {
    asm volatile("cp.async.cg.shared.global [%0], [%1], 16;" :: "r"(dst), "l"(src));
}
#define CP_COMMIT() asm volatile("cp.async.commit_group;" ::: "memory")
#define CP_WAIT(n)  asm volatile("cp.async.wait_group %0;" :: "n"(n) : "memory")

__device__ __forceinline__ float siluf(float x) { return x / (1.0f + __expf(-x)); }
__device__ __forceinline__ float softplusf(float x) {
    return fmaxf(x, 0.0f) + log1pf(__expf(-fabsf(x)));
}
__device__ __forceinline__ void split_bf16(float v, __nv_bfloat16& hi, __nv_bfloat16& lo) {
    hi = __float2bfloat16(v);
    lo = __float2bfloat16(v - __bfloat162float(hi));
}

// ---------------- embedding gather ----------------
__global__ void embed_kernel(const int* __restrict__ ids,
                             const float* __restrict__ embed,
                             float* __restrict__ out) {
    int t = blockIdx.x;
    int id = ids[t];
    const float* src = embed + (size_t)id * DM;
    float* dst = out + (size_t)t * DM;
    for (int d = threadIdx.x; d < DM; d += blockDim.x) dst[d] = src[d];
}

// ---------------- rmsnorm -> bf16x3 activation planes [T, 3*DM] -------------
__global__ void rmsnorm3_kernel(const float* __restrict__ x,
                                const float* __restrict__ w,
                                __nv_bfloat16* __restrict__ out) {
    __shared__ float red[256];
    int t = blockIdx.x;
    const float* row = x + (size_t)t * DM;
    float s = 0.0f;
    for (int d = threadIdx.x; d < DM; d += blockDim.x) { float v = row[d]; s += v * v; }
    red[threadIdx.x] = s;
    __syncthreads();
    for (int off = 128; off > 0; off >>= 1) {
        if (threadIdx.x < off) red[threadIdx.x] += red[threadIdx.x + off];
        __syncthreads();
    }
    float scale = rsqrtf(red[0] / (float)DM + EPS);
    __nv_bfloat16* dst = out + (size_t)t * (3 * DM);
    for (int d = threadIdx.x; d < DM; d += blockDim.x) {
        float v = row[d] * scale * w[d];
        __nv_bfloat16 hi, lo; split_bf16(v, hi, lo);
        dst[d] = hi; dst[DM + d] = lo; dst[2 * DM + d] = hi;
    }
}

// ---------------- final rmsnorm -> fp16x2 planes [T, 2*DM] (hi, lo) ---------
__global__ void rmsnorm2h_kernel(const float* __restrict__ x,
                                 const float* __restrict__ w,
                                 __half* __restrict__ out) {
    __shared__ float red[256];
    int t = blockIdx.x;
    const float* row = x + (size_t)t * DM;
    float s = 0.0f;
    for (int d = threadIdx.x; d < DM; d += blockDim.x) { float v = row[d]; s += v * v; }
    red[threadIdx.x] = s;
    __syncthreads();
    for (int off = 128; off > 0; off >>= 1) {
        if (threadIdx.x < off) red[threadIdx.x] += red[threadIdx.x + off];
        __syncthreads();
    }
    float scale = rsqrtf(red[0] / (float)DM + EPS);
    __half* dst = out + (size_t)t * (2 * DM);
    for (int d = threadIdx.x; d < DM; d += blockDim.x) {
        float v = row[d] * scale * w[d];
        __half hi = __float2half(v);
        __half lo = __float2half(v - __half2float(hi));
        dst[d] = hi; dst[DM + d] = lo;
    }
}

// ---------------- fp32 [R,C] -> bf16x3 weight planes [R,3C] (hi,hi,lo) ------
__global__ void convert3_w_kernel(const float* __restrict__ src,
                                  __nv_bfloat16* __restrict__ dst,
                                  int C) {
    int c8 = blockIdx.x * blockDim.x + threadIdx.x;
    int C8 = C >> 3;
    if (c8 >= C8) return;
    int r0 = blockIdx.y * 4;
    #pragma unroll
    for (int rr = 0; rr < 4; rr++) {
        int r = r0 + rr;
        const float* s = src + (size_t)r * C + c8 * 8;
        float4 v0 = *(const float4*)(s);
        float4 v1 = *(const float4*)(s + 4);
        __nv_bfloat16 h[8], l[8];
        split_bf16(v0.x, h[0], l[0]); split_bf16(v0.y, h[1], l[1]);
        split_bf16(v0.z, h[2], l[2]); split_bf16(v0.w, h[3], l[3]);
        split_bf16(v1.x, h[4], l[4]); split_bf16(v1.y, h[5], l[5]);
        split_bf16(v1.z, h[6], l[6]); split_bf16(v1.w, h[7], l[7]);
        uint4 hv, lv;
        ((__nv_bfloat162*)&hv)[0] = __halves2bfloat162(h[0], h[1]);
        ((__nv_bfloat162*)&hv)[1] = __halves2bfloat162(h[2], h[3]);
        ((__nv_bfloat162*)&hv)[2] = __halves2bfloat162(h[4], h[5]);
        ((__nv_bfloat162*)&hv)[3] = __halves2bfloat162(h[6], h[7]);
        ((__nv_bfloat162*)&lv)[0] = __halves2bfloat162(l[0], l[1]);
        ((__nv_bfloat162*)&lv)[1] = __halves2bfloat162(l[2], l[3]);
        ((__nv_bfloat162*)&lv)[2] = __halves2bfloat162(l[4], l[5]);
        ((__nv_bfloat162*)&lv)[3] = __halves2bfloat162(l[6], l[7]);
        __nv_bfloat16* d = dst + (size_t)r * (3 * (size_t)C) + c8 * 8;
        *(uint4*)(d)         = hv;
        *(uint4*)(d + C)     = hv;
        *(uint4*)(d + 2 * C) = lv;
    }
}

// ---------------- fp32 [R,C] -> fp16x2 planes [R,2C] (hi,hi) — lm head ------
__global__ void convert2h_w_kernel(const float* __restrict__ src,
                                   __half* __restrict__ dst,
                                   int C) {
    int c8 = blockIdx.x * blockDim.x + threadIdx.x;
    int C8 = C >> 3;
    if (c8 >= C8) return;
    int r0 = blockIdx.y * 4;
    #pragma unroll
    for (int rr = 0; rr < 4; rr++) {
        int r = r0 + rr;
        const float* s = src + (size_t)r * C + c8 * 8;
        float4 v0 = *(const float4*)(s);
        float4 v1 = *(const float4*)(s + 4);
        uint4 hv;
        ((__half2*)&hv)[0] = __halves2half2(__float2half(v0.x), __float2half(v0.y));
        ((__half2*)&hv)[1] = __halves2half2(__float2half(v0.z), __float2half(v0.w));
        ((__half2*)&hv)[2] = __halves2half2(__float2half(v1.x), __float2half(v1.y));
        ((__half2*)&hv)[3] = __halves2half2(__float2half(v1.z), __float2half(v1.w));
        __half* d = dst + (size_t)r * (2 * (size_t)C) + c8 * 8;
        *(uint4*)(d)     = hv;
        *(uint4*)(d + C) = hv;
    }
}

// =============================================================================
// HMMA 16-bit GEMM: C[M,N] (=/+=) A[M,:] @ W[N,:]^T over kchunk K-cols starting
// at blockIdx.z*kchunk. FP16=0: bf16 operands; FP16=1: fp16 operands.
// 128x128 CTA tile, BK=64, 256 threads (8 warps: 2x4), mma.m16n8k16,
// 3-stage cp.async pipeline with rotating buffer counters, 1 sync/iter.
// =============================================================================
#define BM 128
#define BN 128
#define BK 64
#define SSTR 72                 // smem row stride in 16-bit elems (64 + 8 pad)
#define NSTAGE 3
#define STAGE_ELEMS (BM * SSTR)          // 9216
#define STAGE_BYTES (STAGE_ELEMS * 2)    // 18432 B
#define HMMA_SMEM (NSTAGE * 2 * STAGE_BYTES)   // 110592 B

template <int EPI, int FP16, typename T>   // EPI: 0 store, 1 add, 2 atomicAdd
__global__ void __launch_bounds__(256, 2)
hmma_gemm_kernel(const T* __restrict__ A,
                 const T* __restrict__ W,
                 float* __restrict__ C, int lda, int ldw, int N, int kchunk)
{
    extern __shared__ char dsm_raw[];
    T* dsm = (T*)dsm_raw;

    const int tid = threadIdx.x;
    const int lane = tid & 31;
    const int wid = tid >> 5;
    const int wm = wid >> 2;     // 0..1 -> 64 rows
    const int wn = wid & 3;      // 0..3 -> 32 cols
    const int bm = blockIdx.x * BM;
    const int bn = blockIdx.y * BN;
    const int kbeg = blockIdx.z * kchunk;

    const uint32_t sA = smem_u32(dsm);
    const uint32_t sW = sA + NSTAGE * STAGE_BYTES;

    // cp.async: 64 elems per row = 8 x 16B chunks. thread -> (row tid>>3, chunk tid&7)
    const int ar0 = tid >> 3;            // 0..31
    const int ak0 = (tid & 7) * 8;       // 0..56
    const T* Ag = A + (size_t)bm * lda + kbeg + ak0;
    const T* Wg = W + (size_t)bn * ldw + kbeg + ak0;
    uint32_t stoff[4];
    const T *Agp[4], *Wgp[4];
    #pragma unroll
    for (int q = 0; q < 4; q++) {
        int row = ar0 + q * 32;
        stoff[q] = (uint32_t)(row * SSTR + ak0) * 2;
        Agp[q] = Ag + (size_t)row * lda;
        Wgp[q] = Wg + (size_t)row * ldw;
    }

    // ldmatrix byte offsets (base at ks=0; add ks*32 bytes per 16-deep k-step)
    uint32_t a_base[4], b_base[2];
    {
        const int grp = lane >> 3, wi = lane & 7;
        #pragma unroll
        for (int mt = 0; mt < 4; mt++) {
            int row = wm * 64 + mt * 16 + (lane & 15);
            int col = (lane >> 4) * 8;
            a_base[mt] = (uint32_t)(row * SSTR + col) * 2;
        }
        #pragma unroll
        for (int np = 0; np < 2; np++) {
            int row = wn * 32 + np * 16 + (grp >> 1) * 8 + wi;
            int col = (grp & 1) * 8;
            b_base[np] = (uint32_t)(row * SSTR + col) * 2;
        }
    }

    float acc[4][4][4];
    #pragma unroll
    for (int i = 0; i < 4; i++)
        #pragma unroll
        for (int j = 0; j < 4; j++)
            #pragma unroll
            for (int k = 0; k < 4; k++) acc[i][j][k] = 0.0f;

#define LOAD_TILE(buf, k0) do { \
    uint32_t ab_ = sA + (buf) * STAGE_BYTES; \
    uint32_t wb_ = sW + (buf) * STAGE_BYTES; \
    _Pragma("unroll") \
    for (int q = 0; q < 4; q++) { \
        cp_async16(ab_ + stoff[q], Agp[q] + (k0)); \
        cp_async16(wb_ + stoff[q], Wgp[q] + (k0)); \
    } \
} while (0)

    const int nc = kchunk / BK;
    LOAD_TILE(0, 0); CP_COMMIT();
    LOAD_TILE(1, BK); CP_COMMIT();

    int load_buf = 2;   // next buffer to fill (rotating)
    int cons_buf = 0;   // buffer consumed this iteration

    for (int c = 0; c < nc; c++) {
        CP_WAIT(1);
        __syncthreads();
        int nf = c + 2;
        if (nf < nc) LOAD_TILE(load_buf, nf * BK);
        CP_COMMIT();
        if (++load_buf == NSTAGE) load_buf = 0;

        const uint32_t ab = sA + cons_buf * STAGE_BYTES;
        const uint32_t wb = sW + cons_buf * STAGE_BYTES;
        if (++cons_buf == NSTAGE) cons_buf = 0;

        #pragma unroll
        for (int ks = 0; ks < 4; ks++) {
            uint32_t a[4][4];
            #pragma unroll
            for (int mt = 0; mt < 4; mt++)
                asm volatile("ldmatrix.sync.aligned.m8n8.x4.shared.b16 {%0,%1,%2,%3}, [%4];"
                    : "=r"(a[mt][0]), "=r"(a[mt][1]), "=r"(a[mt][2]), "=r"(a[mt][3])
                    : "r"(ab + a_base[mt] + ks * 32));
            uint32_t b[4][2];
            #pragma unroll
            for (int np = 0; np < 2; np++)
                asm volatile("ldmatrix.sync.aligned.m8n8.x4.shared.b16 {%0,%1,%2,%3}, [%4];"
                    : "=r"(b[np * 2][0]), "=r"(b[np * 2][1]),
                      "=r"(b[np * 2 + 1][0]), "=r"(b[np * 2 + 1][1])
                    : "r"(wb + b_base[np] + ks * 32));
            #pragma unroll
            for (int mt = 0; mt < 4; mt++)
                #pragma unroll
                for (int nt = 0; nt < 4; nt++) {
                    if (FP16)
                        asm volatile(
                            "mma.sync.aligned.m16n8k16.row.col.f32.f16.f16.f32 "
                            "{%0,%1,%2,%3}, {%4,%5,%6,%7}, {%8,%9}, {%0,%1,%2,%3};"
                            : "+f"(acc[mt][nt][0]), "+f"(acc[mt][nt][1]),
                              "+f"(acc[mt][nt][2]), "+f"(acc[mt][nt][3])
                            : "r"(a[mt][0]), "r"(a[mt][1]), "r"(a[mt][2]), "r"(a[mt][3]),
                              "r"(b[nt][0]), "r"(b[nt][1]));
                    else
                        asm volatile(
                            "mma.sync.aligned.m16n8k16.row.col.f32.bf16.bf16.f32 "
                            "{%0,%1,%2,%3}, {%4,%5,%6,%7}, {%8,%9}, {%0,%1,%2,%3};"
                            : "+f"(acc[mt][nt][0]), "+f"(acc[mt][nt][1]),
                              "+f"(acc[mt][nt][2]), "+f"(acc[mt][nt][3])
                            : "r"(a[mt][0]), "r"(a[mt][1]), "r"(a[mt][2]), "r"(a[mt][3]),
                              "r"(b[nt][0]), "r"(b[nt][1]));
                }
        }
    }
#undef LOAD_TILE

    // epilogue
    #pragma unroll
    for (int mt = 0; mt < 4; mt++) {
        int r0 = bm + wm * 64 + mt * 16 + (lane >> 2);
        #pragma unroll
        for (int nt = 0; nt < 4; nt++) {
            int c0 = bn + wn * 32 + nt * 8 + (lane & 3) * 2;
            float* p0 = C + (size_t)r0 * N + c0;
            float* p1 = C + (size_t)(r0 + 8) * N + c0;
            if (EPI == 2) {
                atomicAdd(p0 + 0, acc[mt][nt][0]); atomicAdd(p0 + 1, acc[mt][nt][1]);
                atomicAdd(p1 + 0, acc[mt][nt][2]); atomicAdd(p1 + 1, acc[mt][nt][3]);
            } else if (EPI == 1) {
                p0[0] += acc[mt][nt][0]; p0[1] += acc[mt][nt][1];
                p1[0] += acc[mt][nt][2]; p1[1] += acc[mt][nt][3];
            } else {
                p0[0] = acc[mt][nt][0]; p0[1] = acc[mt][nt][1];
                p1[0] = acc[mt][nt][2]; p1[1] = acc[mt][nt][3];
            }
        }
    }
}

// ---------------- fp32 SGEMM for small shapes (x_proj, dt_proj) -------------
#define GBM 64
#define GBN 64
#define GBK 16
enum { EPI_NONE = 0, EPI_SOFTPLUS_BIAS = 1 };

template <int EPI, bool ATOMIC>
__global__ void __launch_bounds__(256)
gemm_tn_kernel(const float* __restrict__ A, int lda,
               const float* __restrict__ W, int ldw,
               float* __restrict__ C, int ldc,
               int M, int N, int kchunk,
               const float* __restrict__ bias)
{
    __shared__ float Asm[GBK][GBM + 1];
    __shared__ float Wsm[GBK][GBN + 1];

    int tid = threadIdx.x;
    int bm = blockIdx.y * GBM;
    int bn = blockIdx.x * GBN;
    int kbeg = blockIdx.z * kchunk;
    int kend = kbeg + kchunk;
    int lr = tid >> 2;
    int lk = (tid & 3) << 2;
    int ty = tid >> 4;
    int tx = tid & 15;

    float acc[4][4];
    #pragma unroll
    for (int i = 0; i < 4; i++)
        #pragma unroll
        for (int j = 0; j < 4; j++) acc[i][j] = 0.0f;

    for (int k0 = kbeg; k0 < kend; k0 += GBK) {
        {
            const float4 v = *(const float4*)(A + (size_t)(bm + lr) * lda + k0 + lk);
            Asm[lk + 0][lr] = v.x; Asm[lk + 1][lr] = v.y;
            Asm[lk + 2][lr] = v.z; Asm[lk + 3][lr] = v.w;
        }
        {
            float4 v = make_float4(0.f, 0.f, 0.f, 0.f);
            int row = bn + lr;
            if (row < N) v = *(const float4*)(W + (size_t)row * ldw + k0 + lk);
            Wsm[lk + 0][lr] = v.x; Wsm[lk + 1][lr] = v.y;
            Wsm[lk + 2][lr] = v.z; Wsm[lk + 3][lr] = v.w;
        }
        __syncthreads();
        #pragma unroll
        for (int kk = 0; kk < GBK; kk++) {
            float a[4], b[4];
            #pragma unroll
            for (int i = 0; i < 4; i++) a[i] = Asm[kk][ty * 4 + i];
            #pragma unroll
            for (int j = 0; j < 4; j++) b[j] = Wsm[kk][tx * 4 + j];
            #pragma unroll
            for (int i = 0; i < 4; i++)
                #pragma unroll
                for (int j = 0; j < 4; j++)
                    acc[i][j] = fmaf(a[i], b[j], acc[i][j]);
        }
        __syncthreads();
    }

    #pragma unroll
    for (int i = 0; i < 4; i++) {
        int row = bm + ty * 4 + i;
        #pragma unroll
        for (int j = 0; j < 4; j++) {
            int col = bn + tx * 4 + j;
            if (col < N) {
                float v = acc[i][j];
                if (ATOMIC) {
                    atomicAdd(&C[(size_t)row * ldc + col], v);
                } else {
                    if (EPI == EPI_SOFTPLUS_BIAS) v = softplusf(v + bias[col]);
                    C[(size_t)row * ldc + col] = v;
                }
            }
        }
    }
}

__global__ void zero_kernel(float* __restrict__ p, int n) {
    int i = blockIdx.x * blockDim.x + threadIdx.x;
    if (i < n) p[i] = 0.0f;
}

// ---------------- causal depthwise conv (width 4) + silu ----------------
__global__ void conv_silu_kernel(const float* __restrict__ proj,
                                 const float* __restrict__ cw,
                                 const float* __restrict__ cb,
                                 float* __restrict__ out)
{
    int idx = blockIdx.x * blockDim.x + threadIdx.x;
    if (idx >= TT * DI) return;
    int d = idx % DI;
    int t = idx / DI;
    int l = t % LL;
    float w0 = cw[d * 4 + 0], w1 = cw[d * 4 + 1], w2 = cw[d * 4 + 2], w3 = cw[d * 4 + 3];
    float acc = cb[d];
    if (l >= 3) acc = fmaf(w0, proj[(size_t)(t - 3) * (2 * DI) + d], acc);
    if (l >= 2) acc = fmaf(w1, proj[(size_t)(t - 2) * (2 * DI) + d], acc);
    if (l >= 1) acc = fmaf(w2, proj[(size_t)(t - 1) * (2 * DI) + d], acc);
    acc = fmaf(w3, proj[(size_t)t * (2 * DI) + d], acc);
    out[idx] = siluf(acc);
}

// ---------------- selective scan -> bf16x3 y [T, 3*DI] ----------------
__global__ void scan_kernel(const float* __restrict__ dt,
                            const float* __restrict__ hconv,
                            const float* __restrict__ ssm,
                            const float* __restrict__ proj,
                            const float* __restrict__ A_log,
                            const float* __restrict__ D_skip,
                            __nv_bfloat16* __restrict__ y)
{
    int s = threadIdx.x & 15;
    int d = blockIdx.x * 16 + (threadIdx.x >> 4);
    int b = blockIdx.y;

    float Aneg = -__expf(A_log[d * DS + s]);
    float Dk = D_skip[d];

    float state = 0.0f;
    for (int l = 0; l < LL; l++) {
        int t = b * LL + l;
        float dtv = dt[(size_t)t * DI + d];
        float hv  = hconv[(size_t)t * DI + d];
        float Bv  = ssm[(size_t)t * 80 + DTR + s];
        float Cv  = ssm[(size_t)t * 80 + DTR + DS + s];
        float a = __expf(dtv * Aneg);
        state = fmaf(a, state, dtv * hv * Bv);
        float p = state * Cv;
        p += __shfl_xor_sync(0xffffffffu, p, 8);
        p += __shfl_xor_sync(0xffffffffu, p, 4);
        p += __shfl_xor_sync(0xffffffffu, p, 2);
        p += __shfl_xor_sync(0xffffffffu, p, 1);
        if (s == 0) {
            float g = proj[(size_t)t * (2 * DI) + DI + d];
            float val = (p + Dk * hv) * siluf(g);
            __nv_bfloat16 hi, lo; split_bf16(val, hi, lo);
            __nv_bfloat16* dst = y + (size_t)t * (3 * DI);
            dst[d] = hi; dst[DI + d] = lo; dst[2 * DI + d] = hi;
        }
    }
}

// ---------------- launcher ----------------
extern "C" void kernel_launch(void* const* d_in, const int* in_sizes, int n_in,
                              void* d_out, int out_size)
{
    const int*   input_ids = (const int*)  d_in[0];
    const float* embed     = (const float*)d_in[1];
    const float* norm_f_w  = (const float*)d_in[2];
    const float* in_proj_w = (const float*)d_in[3];
    const float* conv_w    = (const float*)d_in[4];
    const float* conv_b    = (const float*)d_in[5];
    const float* x_proj_w  = (const float*)d_in[6];
    const float* dt_proj_w = (const float*)d_in[7];
    const float* dt_proj_b = (const float*)d_in[8];
    const float* A_log     = (const float*)d_in[9];
    const float* D_skip    = (const float*)d_in[10];
    const float* out_proj_w= (const float*)d_in[11];
    const float* norm_w    = (const float*)d_in[12];
    float* logits = (float*)d_out;

    float *ph, *pproj, *pconv, *pssm, *pdt;
    __nv_bfloat16 *pxn, *py, *pinw, *poutw;
    __half *pxnh, *pembh;
    cudaGetSymbolAddress((void**)&ph,    g_h);
    cudaGetSymbolAddress((void**)&pproj, g_proj);
    cudaGetSymbolAddress((void**)&pconv, g_conv);
    cudaGetSymbolAddress((void**)&pssm,  g_ssm);
    cudaGetSymbolAddress((void**)&pdt,   g_dt);
    cudaGetSymbolAddress((void**)&pxn,   g_xn_big);
    cudaGetSymbolAddress((void**)&py,    g_y_big);
    cudaGetSymbolAddress((void**)&pinw,  g_inw_big);
    cudaGetSymbolAddress((void**)&poutw, g_outw_big);
    cudaGetSymbolAddress((void**)&pxnh,  g_xn_half);
    cudaGetSymbolAddress((void**)&pembh, g_embed_half);

    cudaFuncSetAttribute((const void*)hmma_gemm_kernel<0, 0, __nv_bfloat16>,
                         cudaFuncAttributeMaxDynamicSharedMemorySize, HMMA_SMEM);
    cudaFuncSetAttribute((const void*)hmma_gemm_kernel<2, 0, __nv_bfloat16>,
                         cudaFuncAttributeMaxDynamicSharedMemorySize, HMMA_SMEM);
    cudaFuncSetAttribute((const void*)hmma_gemm_kernel<0, 1, __half>,
                         cudaFuncAttributeMaxDynamicSharedMemorySize, HMMA_SMEM);

    // embedding gather
    embed_kernel<<<TT, 256>>>(input_ids, embed, ph);

    // bulk weight conversions (all layers + lm head)
    {
        dim3 ge((DM / 8 + 127) / 128, VOCAB / 4);
        convert2h_w_kernel<<<ge, 128>>>(embed, pembh, DM);          // lm head: fp16 [hi,hi]
        dim3 gi((DM / 8 + 127) / 128, (NL * 2 * DI) / 4);
        convert3_w_kernel<<<gi, 128>>>(in_proj_w, pinw, DM);
        dim3 go((DI / 8 + 127) / 128, (NL * DM) / 4);
        convert3_w_kernel<<<go, 128>>>(out_proj_w, poutw, DI);
    }

    for (int i = 0; i < NL; i++) {
        const __nv_bfloat16* w_in3  = pinw  + (size_t)i * (2 * DI) * (3 * DM);
        const __nv_bfloat16* w_out3 = poutw + (size_t)i * DM * (3 * DI);
        const float* w_cv  = conv_w     + (size_t)i * DI * DCONV;
        const float* b_cv  = conv_b     + (size_t)i * DI;
        const float* w_xp  = x_proj_w   + (size_t)i * (DTR + 2 * DS) * DI;
        const float* w_dtp = dt_proj_w  + (size_t)i * DI * DTR;
        const float* b_dtp = dt_proj_b  + (size_t)i * DI;
        const float* a_log = A_log      + (size_t)i * DI * DS;
        const float* d_sk  = D_skip     + (size_t)i * DI;
        const float* w_nrm = norm_w     + (size_t)i * DM;

        // rmsnorm -> bf16x3
        rmsnorm3_kernel<<<TT, 256>>>(ph, w_nrm, pxn);

        // in_proj: [1024, 2304] @ [3072, 2304]^T -> proj [1024, 3072]
        // split-K=3, atomic accumulate into zeroed proj
        zero_kernel<<<(TT * 2 * DI + 255) / 256, 256>>>(pproj, TT * 2 * DI);
        {
            dim3 grid(TT / BM, (2 * DI) / BN, 3);
            hmma_gemm_kernel<2, 0><<<grid, 256, HMMA_SMEM>>>(
                pxn, w_in3, pproj, 3 * DM, 3 * DM, 2 * DI, (3 * DM) / 3);
        }

        // conv + silu
        conv_silu_kernel<<<(TT * DI + 255) / 256, 256>>>(pproj, w_cv, b_cv, pconv);

        // x_proj: [1024,1536] @ [80,1536]^T -> [1024,80]  (fp32, split-K=6 atomic)
        zero_kernel<<<(TT * 80 + 255) / 256, 256>>>(pssm, TT * 80);
        {
            dim3 grid((80 + GBN - 1) / GBN, TT / GBM, 6);
            gemm_tn_kernel<EPI_NONE, true><<<grid, 256>>>(
                pconv, DI, w_xp, DI, pssm, 80, TT, 80, DI / 6, nullptr);
        }

        // dt_proj + softplus: [1024,48(lda=80)] @ [1536,48]^T -> [1024,1536]
        {
            dim3 grid(DI / GBN, TT / GBM, 1);
            gemm_tn_kernel<EPI_SOFTPLUS_BIAS, false><<<grid, 256>>>(
                pssm, 80, w_dtp, DTR, pdt, DI, TT, DI, DTR, b_dtp);
        }

        // selective scan (+ D skip + gate silu) -> bf16x3 y
        {
            dim3 grid(DI / 16, BB);
            scan_kernel<<<grid, 256>>>(pdt, pconv, pssm, pproj, a_log, d_sk, py);
        }

        // out_proj + residual: h += y @ w_out^T, split-K=6 (288 CTAs ~ 1 wave)
        {
            dim3 grid(TT / BM, DM / BN, 6);
            hmma_gemm_kernel<2, 0><<<grid, 256, HMMA_SMEM>>>(
                py, w_out3, ph, 3 * DI, 3 * DI, DM, (3 * DI) / 6);
        }
    }

    // final rmsnorm -> fp16x2 [hi, lo]
    rmsnorm2h_kernel<<<TT, 256>>>(ph, norm_f_w, pxnh);

    // lm head (fp16 2-plane): [1024, 1536] @ [32000, 1536]^T -> logits
    // captures hi*hi + lo_a*hi_w; missing hi_a*lo_w ~ 2^-12 rel (fp16).
    {
        dim3 grid(TT / BM, VOCAB / BN, 1);
        hmma_gemm_kernel<0, 1><<<grid, 256, HMMA_SMEM>>>(
            pxnh, pembh, logits, 2 * DM, 2 * DM, VOCAB, 2 * DM);
    }
}

// round 10
// speedup vs baseline: 2.1572x; 1.0194x over previous
#include <cuda_runtime.h>
#include <cuda_bf16.h>
#include <cuda_fp16.h>
#include <cstdint>
#include <math.h>

// ---------------- problem constants ----------------
#define NL    4
#define DM    768
#define DI    1536
#define DS    16
#define DTR   48
#define DCONV 4
#define VOCAB 32000
#define BB    2
#define LL    512
#define TT    (BB*LL)          // 1024 tokens
#define EPS   1e-5f

// ---------------- scratch (static device memory; no allocations) -------------
__device__ float g_h   [TT * DM];            // residual stream (fp32)
__device__ float g_proj[TT * 2 * DI];        // in_proj output (h | gate)
__device__ float g_conv[TT * DI];            // conv + silu output
__device__ float g_ssm [TT * 80];            // x_proj output (dt_raw | B | C)
__device__ float g_dt  [TT * DI];            // softplus(dt)

// in_proj: bf16x3 planes. Activations [hi,lo,hi]; weights [hi,hi,lo].
__device__ __nv_bfloat16 g_xn_big   [TT * 3 * DM];                  // rmsnorm out (layers)
__device__ __nv_bfloat16 g_inw_big  [(size_t)NL * (2*DI) * 3 * DM]; // all in_proj_w
// out_proj + lm head: fp16 2-plane. Activations [hi,lo]; weights [hi,hi].
__device__ __half g_y_half    [TT * 2 * DI];                        // scan out
__device__ __half g_outw_half [(size_t)NL * DM * 2 * DI];           // all out_proj_w
__device__ __half g_xn_half   [TT * 2 * DM];                        // final rmsnorm out
__device__ __half g_embed_half[(size_t)VOCAB * 2 * DM];             // embed (lm head)

// ---------------- helpers ----------------
__device__ __forceinline__ uint32_t smem_u32(const void* p) {
    uint32_t a;
    asm("{ .reg .u64 t; cvta.to.shared.u64 t, %1; cvt.u32.u64 %0, t; }" : "=r"(a) : "l"(p));
    return a;
}
__device__ __forceinline__ void cp_async16(uint32_t dst, const void* src) {
    asm volatile("cp.async.cg.shared.global [%0], [%1], 16;" :: "r"(dst), "l"(src));
}
#define CP_COMMIT() asm volatile("cp.async.commit_group;" ::: "memory")
#define CP_WAIT(n)  asm volatile("cp.async.wait_group %0;" :: "n"(n) : "memory")

__device__ __forceinline__ float siluf(float x) { return x / (1.0f + __expf(-x)); }
__device__ __forceinline__ float softplusf(float x) {
    return fmaxf(x, 0.0f) + log1pf(__expf(-fabsf(x)));
}
__device__ __forceinline__ void split_bf16(float v, __nv_bfloat16& hi, __nv_bfloat16& lo) {
    hi = __float2bfloat16(v);
    lo = __float2bfloat16(v - __bfloat162float(hi));
}

// ---------------- fused embed gather + rmsnorm -> h and bf16x3 planes -------
__global__ void embed_rmsnorm3_kernel(const int* __restrict__ ids,
                                      const float* __restrict__ embed,
                                      const float* __restrict__ w,
                                      float* __restrict__ hout,
                                      __nv_bfloat16* __restrict__ out) {
    __shared__ float red[256];
    int t = blockIdx.x;
    int id = ids[t];
    const float* src = embed + (size_t)id * DM;
    float* hdst = hout + (size_t)t * DM;
    float vals[3];
    float s = 0.0f;
    #pragma unroll
    for (int q = 0; q < 3; q++) {
        int d = threadIdx.x + q * 256;
        float v = src[d];
        vals[q] = v;
        hdst[d] = v;
        s += v * v;
    }
    red[threadIdx.x] = s;
    __syncthreads();
    for (int off = 128; off > 0; off >>= 1) {
        if (threadIdx.x < off) red[threadIdx.x] += red[threadIdx.x + off];
        __syncthreads();
    }
    float scale = rsqrtf(red[0] / (float)DM + EPS);
    __nv_bfloat16* dst = out + (size_t)t * (3 * DM);
    #pragma unroll
    for (int q = 0; q < 3; q++) {
        int d = threadIdx.x + q * 256;
        float v = vals[q] * scale * w[d];
        __nv_bfloat16 hi, lo; split_bf16(v, hi, lo);
        dst[d] = hi; dst[DM + d] = lo; dst[2 * DM + d] = hi;
    }
}

// ---------------- rmsnorm -> bf16x3 activation planes [T, 3*DM] -------------
__global__ void rmsnorm3_kernel(const float* __restrict__ x,
                                const float* __restrict__ w,
                                __nv_bfloat16* __restrict__ out) {
    __shared__ float red[256];
    int t = blockIdx.x;
    const float* row = x + (size_t)t * DM;
    float s = 0.0f;
    for (int d = threadIdx.x; d < DM; d += blockDim.x) { float v = row[d]; s += v * v; }
    red[threadIdx.x] = s;
    __syncthreads();
    for (int off = 128; off > 0; off >>= 1) {
        if (threadIdx.x < off) red[threadIdx.x] += red[threadIdx.x + off];
        __syncthreads();
    }
    float scale = rsqrtf(red[0] / (float)DM + EPS);
    __nv_bfloat16* dst = out + (size_t)t * (3 * DM);
    for (int d = threadIdx.x; d < DM; d += blockDim.x) {
        float v = row[d] * scale * w[d];
        __nv_bfloat16 hi, lo; split_bf16(v, hi, lo);
        dst[d] = hi; dst[DM + d] = lo; dst[2 * DM + d] = hi;
    }
}

// ---------------- final rmsnorm -> fp16x2 planes [T, 2*DM] (hi, lo) ---------
__global__ void rmsnorm2h_kernel(const float* __restrict__ x,
                                 const float* __restrict__ w,
                                 __half* __restrict__ out) {
    __shared__ float red[256];
    int t = blockIdx.x;
    const float* row = x + (size_t)t * DM;
    float s = 0.0f;
    for (int d = threadIdx.x; d < DM; d += blockDim.x) { float v = row[d]; s += v * v; }
    red[threadIdx.x] = s;
    __syncthreads();
    for (int off = 128; off > 0; off >>= 1) {
        if (threadIdx.x < off) red[threadIdx.x] += red[threadIdx.x + off];
        __syncthreads();
    }
    float scale = rsqrtf(red[0] / (float)DM + EPS);
    __half* dst = out + (size_t)t * (2 * DM);
    for (int d = threadIdx.x; d < DM; d += blockDim.x) {
        float v = row[d] * scale * w[d];
        __half hi = __float2half(v);
        __half lo = __float2half(v - __half2float(hi));
        dst[d] = hi; dst[DM + d] = lo;
    }
}

// ---------------- fp32 [R,C] -> bf16x3 weight planes [R,3C] (hi,hi,lo) ------
__global__ void convert3_w_kernel(const float* __restrict__ src,
                                  __nv_bfloat16* __restrict__ dst,
                                  int C) {
    int c8 = blockIdx.x * blockDim.x + threadIdx.x;
    int C8 = C >> 3;
    if (c8 >= C8) return;
    int r0 = blockIdx.y * 4;
    #pragma unroll
    for (int rr = 0; rr < 4; rr++) {
        int r = r0 + rr;
        const float* s = src + (size_t)r * C + c8 * 8;
        float4 v0 = *(const float4*)(s);
        float4 v1 = *(const float4*)(s + 4);
        __nv_bfloat16 h[8], l[8];
        split_bf16(v0.x, h[0], l[0]); split_bf16(v0.y, h[1], l[1]);
        split_bf16(v0.z, h[2], l[2]); split_bf16(v0.w, h[3], l[3]);
        split_bf16(v1.x, h[4], l[4]); split_bf16(v1.y, h[5], l[5]);
        split_bf16(v1.z, h[6], l[6]); split_bf16(v1.w, h[7], l[7]);
        uint4 hv, lv;
        ((__nv_bfloat162*)&hv)[0] = __halves2bfloat162(h[0], h[1]);
        ((__nv_bfloat162*)&hv)[1] = __halves2bfloat162(h[2], h[3]);
        ((__nv_bfloat162*)&hv)[2] = __halves2bfloat162(h[4], h[5]);
        ((__nv_bfloat162*)&hv)[3] = __halves2bfloat162(h[6], h[7]);
        ((__nv_bfloat162*)&lv)[0] = __halves2bfloat162(l[0], l[1]);
        ((__nv_bfloat162*)&lv)[1] = __halves2bfloat162(l[2], l[3]);
        ((__nv_bfloat162*)&lv)[2] = __halves2bfloat162(l[4], l[5]);
        ((__nv_bfloat162*)&lv)[3] = __halves2bfloat162(l[6], l[7]);
        __nv_bfloat16* d = dst + (size_t)r * (3 * (size_t)C) + c8 * 8;
        *(uint4*)(d)         = hv;
        *(uint4*)(d + C)     = hv;
        *(uint4*)(d + 2 * C) = lv;
    }
}

// ---------------- fp32 [R,C] -> fp16x2 planes [R,2C] (hi,hi) ----------------
__global__ void convert2h_w_kernel(const float* __restrict__ src,
                                   __half* __restrict__ dst,
                                   int C) {
    int c8 = blockIdx.x * blockDim.x + threadIdx.x;
    int C8 = C >> 3;
    if (c8 >= C8) return;
    int r0 = blockIdx.y * 4;
    #pragma unroll
    for (int rr = 0; rr < 4; rr++) {
        int r = r0 + rr;
        const float* s = src + (size_t)r * C + c8 * 8;
        float4 v0 = *(const float4*)(s);
        float4 v1 = *(const float4*)(s + 4);
        uint4 hv;
        ((__half2*)&hv)[0] = __halves2half2(__float2half(v0.x), __float2half(v0.y));
        ((__half2*)&hv)[1] = __halves2half2(__float2half(v0.z), __float2half(v0.w));
        ((__half2*)&hv)[2] = __halves2half2(__float2half(v1.x), __float2half(v1.y));
        ((__half2*)&hv)[3] = __halves2half2(__float2half(v1.z), __float2half(v1.w));
        __half* d = dst + (size_t)r * (2 * (size_t)C) + c8 * 8;
        *(uint4*)(d)     = hv;
        *(uint4*)(d + C) = hv;
    }
}

// =============================================================================
// HMMA 16-bit GEMM: C[M,N] (=/+=) A[M,:] @ W[N,:]^T over kchunk K-cols starting
// at blockIdx.z*kchunk. FP16=0: bf16 operands; FP16=1: fp16 operands.
// 128x128 CTA tile, BK=64, 256 threads (8 warps: 2x4), mma.m16n8k16,
// 3-stage cp.async pipeline with rotating buffer counters, 1 sync/iter.
// =============================================================================
#define BM 128
#define BN 128
#define BK 64
#define SSTR 72                 // smem row stride in 16-bit elems (64 + 8 pad)
#define NSTAGE 3
#define STAGE_ELEMS (BM * SSTR)          // 9216
#define STAGE_BYTES (STAGE_ELEMS * 2)    // 18432 B
#define HMMA_SMEM (NSTAGE * 2 * STAGE_BYTES)   // 110592 B

template <int EPI, int FP16, typename T>   // EPI: 0 store, 1 add, 2 atomicAdd
__global__ void __launch_bounds__(256, 2)
hmma_gemm_kernel(const T* __restrict__ A,
                 const T* __restrict__ W,
                 float* __restrict__ C, int lda, int ldw, int N, int kchunk)
{
    extern __shared__ char dsm_raw[];
    T* dsm = (T*)dsm_raw;

    const int tid = threadIdx.x;
    const int lane = tid & 31;
    const int wid = tid >> 5;
    const int wm = wid >> 2;     // 0..1 -> 64 rows
    const int wn = wid & 3;      // 0..3 -> 32 cols
    const int bm = blockIdx.x * BM;
    const int bn = blockIdx.y * BN;
    const int kbeg = blockIdx.z * kchunk;

    const uint32_t sA = smem_u32(dsm);
    const uint32_t sW = sA + NSTAGE * STAGE_BYTES;

    const int ar0 = tid >> 3;            // 0..31
    const int ak0 = (tid & 7) * 8;       // 0..56
    const T* Ag = A + (size_t)bm * lda + kbeg + ak0;
    const T* Wg = W + (size_t)bn * ldw + kbeg + ak0;
    uint32_t stoff[4];
    const T *Agp[4], *Wgp[4];
    #pragma unroll
    for (int q = 0; q < 4; q++) {
        int row = ar0 + q * 32;
        stoff[q] = (uint32_t)(row * SSTR + ak0) * 2;
        Agp[q] = Ag + (size_t)row * lda;
        Wgp[q] = Wg + (size_t)row * ldw;
    }

    uint32_t a_base[4], b_base[2];
    {
        const int grp = lane >> 3, wi = lane & 7;
        #pragma unroll
        for (int mt = 0; mt < 4; mt++) {
            int row = wm * 64 + mt * 16 + (lane & 15);
            int col = (lane >> 4) * 8;
            a_base[mt] = (uint32_t)(row * SSTR + col) * 2;
        }
        #pragma unroll
        for (int np = 0; np < 2; np++) {
            int row = wn * 32 + np * 16 + (grp >> 1) * 8 + wi;
            int col = (grp & 1) * 8;
            b_base[np] = (uint32_t)(row * SSTR + col) * 2;
        }
    }

    float acc[4][4][4];
    #pragma unroll
    for (int i = 0; i < 4; i++)
        #pragma unroll
        for (int j = 0; j < 4; j++)
            #pragma unroll
            for (int k = 0; k < 4; k++) acc[i][j][k] = 0.0f;

#define LOAD_TILE(buf, k0) do { \
    uint32_t ab_ = sA + (buf) * STAGE_BYTES; \
    uint32_t wb_ = sW + (buf) * STAGE_BYTES; \
    _Pragma("unroll") \
    for (int q = 0; q < 4; q++) { \
        cp_async16(ab_ + stoff[q], Agp[q] + (k0)); \
        cp_async16(wb_ + stoff[q], Wgp[q] + (k0)); \
    } \
} while (0)

    const int nc = kchunk / BK;
    LOAD_TILE(0, 0); CP_COMMIT();
    LOAD_TILE(1, BK); CP_COMMIT();

    int load_buf = 2;
    int cons_buf = 0;

    for (int c = 0; c < nc; c++) {
        CP_WAIT(1);
        __syncthreads();
        int nf = c + 2;
        if (nf < nc) LOAD_TILE(load_buf, nf * BK);
        CP_COMMIT();
        if (++load_buf == NSTAGE) load_buf = 0;

        const uint32_t ab = sA + cons_buf * STAGE_BYTES;
        const uint32_t wb = sW + cons_buf * STAGE_BYTES;
        if (++cons_buf == NSTAGE) cons_buf = 0;

        #pragma unroll
        for (int ks = 0; ks < 4; ks++) {
            uint32_t a[4][4];
            #pragma unroll
            for (int mt = 0; mt < 4; mt++)
                asm volatile("ldmatrix.sync.aligned.m8n8.x4.shared.b16 {%0,%1,%2,%3}, [%4];"
                    : "=r"(a[mt][0]), "=r"(a[mt][1]), "=r"(a[mt][2]), "=r"(a[mt][3])
                    : "r"(ab + a_base[mt] + ks * 32));
            uint32_t b[4][2];
            #pragma unroll
            for (int np = 0; np < 2; np++)
                asm volatile("ldmatrix.sync.aligned.m8n8.x4.shared.b16 {%0,%1,%2,%3}, [%4];"
                    : "=r"(b[np * 2][0]), "=r"(b[np * 2][1]),
                      "=r"(b[np * 2 + 1][0]), "=r"(b[np * 2 + 1][1])
                    : "r"(wb + b_base[np] + ks * 32));
            #pragma unroll
            for (int mt = 0; mt < 4; mt++)
                #pragma unroll
                for (int nt = 0; nt < 4; nt++) {
                    if (FP16)
                        asm volatile(
                            "mma.sync.aligned.m16n8k16.row.col.f32.f16.f16.f32 "
                            "{%0,%1,%2,%3}, {%4,%5,%6,%7}, {%8,%9}, {%0,%1,%2,%3};"
                            : "+f"(acc[mt][nt][0]), "+f"(acc[mt][nt][1]),
                              "+f"(acc[mt][nt][2]), "+f"(acc[mt][nt][3])
                            : "r"(a[mt][0]), "r"(a[mt][1]), "r"(a[mt][2]), "r"(a[mt][3]),
                              "r"(b[nt][0]), "r"(b[nt][1]));
                    else
                        asm volatile(
                            "mma.sync.aligned.m16n8k16.row.col.f32.bf16.bf16.f32 "
                            "{%0,%1,%2,%3}, {%4,%5,%6,%7}, {%8,%9}, {%0,%1,%2,%3};"
                            : "+f"(acc[mt][nt][0]), "+f"(acc[mt][nt][1]),
                              "+f"(acc[mt][nt][2]), "+f"(acc[mt][nt][3])
                            : "r"(a[mt][0]), "r"(a[mt][1]), "r"(a[mt][2]), "r"(a[mt][3]),
                              "r"(b[nt][0]), "r"(b[nt][1]));
                }
        }
    }
#undef LOAD_TILE

    // epilogue
    #pragma unroll
    for (int mt = 0; mt < 4; mt++) {
        int r0 = bm + wm * 64 + mt * 16 + (lane >> 2);
        #pragma unroll
        for (int nt = 0; nt < 4; nt++) {
            int c0 = bn + wn * 32 + nt * 8 + (lane & 3) * 2;
            float* p0 = C + (size_t)r0 * N + c0;
            float* p1 = C + (size_t)(r0 + 8) * N + c0;
            if (EPI == 2) {
                atomicAdd(p0 + 0, acc[mt][nt][0]); atomicAdd(p0 + 1, acc[mt][nt][1]);
                atomicAdd(p1 + 0, acc[mt][nt][2]); atomicAdd(p1 + 1, acc[mt][nt][3]);
            } else if (EPI == 1) {
                p0[0] += acc[mt][nt][0]; p0[1] += acc[mt][nt][1];
                p1[0] += acc[mt][nt][2]; p1[1] += acc[mt][nt][3];
            } else {
                p0[0] = acc[mt][nt][0]; p0[1] = acc[mt][nt][1];
                p1[0] = acc[mt][nt][2]; p1[1] = acc[mt][nt][3];
            }
        }
    }
}

// ---------------- fp32 SGEMM for small shapes (x_proj, dt_proj) -------------
#define GBM 64
#define GBN 64
#define GBK 16
enum { EPI_NONE = 0, EPI_SOFTPLUS_BIAS = 1 };

template <int EPI, bool ATOMIC>
__global__ void __launch_bounds__(256)
gemm_tn_kernel(const float* __restrict__ A, int lda,
               const float* __restrict__ W, int ldw,
               float* __restrict__ C, int ldc,
               int M, int N, int kchunk,
               const float* __restrict__ bias)
{
    __shared__ float Asm[GBK][GBM + 1];
    __shared__ float Wsm[GBK][GBN + 1];

    int tid = threadIdx.x;
    int bm = blockIdx.y * GBM;
    int bn = blockIdx.x * GBN;
    int kbeg = blockIdx.z * kchunk;
    int kend = kbeg + kchunk;
    int lr = tid >> 2;
    int lk = (tid & 3) << 2;
    int ty = tid >> 4;
    int tx = tid & 15;

    float acc[4][4];
    #pragma unroll
    for (int i = 0; i < 4; i++)
        #pragma unroll
        for (int j = 0; j < 4; j++) acc[i][j] = 0.0f;

    for (int k0 = kbeg; k0 < kend; k0 += GBK) {
        {
            const float4 v = *(const float4*)(A + (size_t)(bm + lr) * lda + k0 + lk);
            Asm[lk + 0][lr] = v.x; Asm[lk + 1][lr] = v.y;
            Asm[lk + 2][lr] = v.z; Asm[lk + 3][lr] = v.w;
        }
        {
            float4 v = make_float4(0.f, 0.f, 0.f, 0.f);
            int row = bn + lr;
            if (row < N) v = *(const float4*)(W + (size_t)row * ldw + k0 + lk);
            Wsm[lk + 0][lr] = v.x; Wsm[lk + 1][lr] = v.y;
            Wsm[lk + 2][lr] = v.z; Wsm[lk + 3][lr] = v.w;
        }
        __syncthreads();
        #pragma unroll
        for (int kk = 0; kk < GBK; kk++) {
            float a[4], b[4];
            #pragma unroll
            for (int i = 0; i < 4; i++) a[i] = Asm[kk][ty * 4 + i];
            #pragma unroll
            for (int j = 0; j < 4; j++) b[j] = Wsm[kk][tx * 4 + j];
            #pragma unroll
            for (int i = 0; i < 4; i++)
                #pragma unroll
                for (int j = 0; j < 4; j++)
                    acc[i][j] = fmaf(a[i], b[j], acc[i][j]);
        }
        __syncthreads();
    }

    #pragma unroll
    for (int i = 0; i < 4; i++) {
        int row = bm + ty * 4 + i;
        #pragma unroll
        for (int j = 0; j < 4; j++) {
            int col = bn + tx * 4 + j;
            if (col < N) {
                float v = acc[i][j];
                if (ATOMIC) {
                    atomicAdd(&C[(size_t)row * ldc + col], v);
                } else {
                    if (EPI == EPI_SOFTPLUS_BIAS) v = softplusf(v + bias[col]);
                    C[(size_t)row * ldc + col] = v;
                }
            }
        }
    }
}

__global__ void zero_kernel(float* __restrict__ p, int n) {
    int i = blockIdx.x * blockDim.x + threadIdx.x;
    if (i < n) p[i] = 0.0f;
}

// ---------------- causal depthwise conv (width 4) + silu ----------------
__global__ void conv_silu_kernel(const float* __restrict__ proj,
                                 const float* __restrict__ cw,
                                 const float* __restrict__ cb,
                                 float* __restrict__ out)
{
    int idx = blockIdx.x * blockDim.x + threadIdx.x;
    if (idx >= TT * DI) return;
    int d = idx % DI;
    int t = idx / DI;
    int l = t % LL;
    float w0 = cw[d * 4 + 0], w1 = cw[d * 4 + 1], w2 = cw[d * 4 + 2], w3 = cw[d * 4 + 3];
    float acc = cb[d];
    if (l >= 3) acc = fmaf(w0, proj[(size_t)(t - 3) * (2 * DI) + d], acc);
    if (l >= 2) acc = fmaf(w1, proj[(size_t)(t - 2) * (2 * DI) + d], acc);
    if (l >= 1) acc = fmaf(w2, proj[(size_t)(t - 1) * (2 * DI) + d], acc);
    acc = fmaf(w3, proj[(size_t)t * (2 * DI) + d], acc);
    out[idx] = siluf(acc);
}

// ---------------- selective scan -> fp16x2 y [T, 2*DI] ----------------
__global__ void scan_kernel(const float* __restrict__ dt,
                            const float* __restrict__ hconv,
                            const float* __restrict__ ssm,
                            const float* __restrict__ proj,
                            const float* __restrict__ A_log,
                            const float* __restrict__ D_skip,
                            __half* __restrict__ y)
{
    int s = threadIdx.x & 15;
    int d = blockIdx.x * 16 + (threadIdx.x >> 4);
    int b = blockIdx.y;

    float Aneg = -__expf(A_log[d * DS + s]);
    float Dk = D_skip[d];

    float state = 0.0f;
    for (int l = 0; l < LL; l++) {
        int t = b * LL + l;
        float dtv = dt[(size_t)t * DI + d];
        float hv  = hconv[(size_t)t * DI + d];
        float Bv  = ssm[(size_t)t * 80 + DTR + s];
        float Cv  = ssm[(size_t)t * 80 + DTR + DS + s];
        float a = __expf(dtv * Aneg);
        state = fmaf(a, state, dtv * hv * Bv);
        float p = state * Cv;
        p += __shfl_xor_sync(0xffffffffu, p, 8);
        p += __shfl_xor_sync(0xffffffffu, p, 4);
        p += __shfl_xor_sync(0xffffffffu, p, 2);
        p += __shfl_xor_sync(0xffffffffu, p, 1);
        if (s == 0) {
            float g = proj[(size_t)t * (2 * DI) + DI + d];
            float val = (p + Dk * hv) * siluf(g);
            __half hi = __float2half(val);
            __half lo = __float2half(val - __half2float(hi));
            __half* dst = y + (size_t)t * (2 * DI);
            dst[d] = hi; dst[DI + d] = lo;
        }
    }
}

// ---------------- launcher ----------------
extern "C" void kernel_launch(void* const* d_in, const int* in_sizes, int n_in,
                              void* d_out, int out_size)
{
    const int*   input_ids = (const int*)  d_in[0];
    const float* embed     = (const float*)d_in[1];
    const float* norm_f_w  = (const float*)d_in[2];
    const float* in_proj_w = (const float*)d_in[3];
    const float* conv_w    = (const float*)d_in[4];
    const float* conv_b    = (const float*)d_in[5];
    const float* x_proj_w  = (const float*)d_in[6];
    const float* dt_proj_w = (const float*)d_in[7];
    const float* dt_proj_b = (const float*)d_in[8];
    const float* A_log     = (const float*)d_in[9];
    const float* D_skip    = (const float*)d_in[10];
    const float* out_proj_w= (const float*)d_in[11];
    const float* norm_w    = (const float*)d_in[12];
    float* logits = (float*)d_out;

    float *ph, *pproj, *pconv, *pssm, *pdt;
    __nv_bfloat16 *pxn, *pinw;
    __half *py, *poutw, *pxnh, *pembh;
    cudaGetSymbolAddress((void**)&ph,    g_h);
    cudaGetSymbolAddress((void**)&pproj, g_proj);
    cudaGetSymbolAddress((void**)&pconv, g_conv);
    cudaGetSymbolAddress((void**)&pssm,  g_ssm);
    cudaGetSymbolAddress((void**)&pdt,   g_dt);
    cudaGetSymbolAddress((void**)&pxn,   g_xn_big);
    cudaGetSymbolAddress((void**)&pinw,  g_inw_big);
    cudaGetSymbolAddress((void**)&py,    g_y_half);
    cudaGetSymbolAddress((void**)&poutw, g_outw_half);
    cudaGetSymbolAddress((void**)&pxnh,  g_xn_half);
    cudaGetSymbolAddress((void**)&pembh, g_embed_half);

    cudaFuncSetAttribute((const void*)hmma_gemm_kernel<2, 0, __nv_bfloat16>,
                         cudaFuncAttributeMaxDynamicSharedMemorySize, HMMA_SMEM);
    cudaFuncSetAttribute((const void*)hmma_gemm_kernel<2, 1, __half>,
                         cudaFuncAttributeMaxDynamicSharedMemorySize, HMMA_SMEM);
    cudaFuncSetAttribute((const void*)hmma_gemm_kernel<0, 1, __half>,
                         cudaFuncAttributeMaxDynamicSharedMemorySize, HMMA_SMEM);

    // 1: fused embed gather + layer-0 rmsnorm
    embed_rmsnorm3_kernel<<<TT, 256>>>(input_ids, embed, norm_w, ph, pxn);

    // 2-4: bulk weight conversions
    {
        dim3 ge((DM / 8 + 127) / 128, VOCAB / 4);
        convert2h_w_kernel<<<ge, 128>>>(embed, pembh, DM);            // lm head fp16 [hi,hi]
        dim3 gi((DM / 8 + 127) / 128, (NL * 2 * DI) / 4);
        convert3_w_kernel<<<gi, 128>>>(in_proj_w, pinw, DM);          // in_proj bf16x3
        dim3 go((DI / 8 + 127) / 128, (NL * DM) / 4);
        convert2h_w_kernel<<<go, 128>>>(out_proj_w, poutw, DI);       // out_proj fp16 [hi,hi]
    }

    // 5: zero proj for layer 0 (launch #6 = in_proj GEMM -> ncu captures it)
    zero_kernel<<<(TT * 2 * DI + 255) / 256, 256>>>(pproj, TT * 2 * DI);

    for (int i = 0; i < NL; i++) {
        const __nv_bfloat16* w_in3  = pinw  + (size_t)i * (2 * DI) * (3 * DM);
        const __half*        w_out2 = poutw + (size_t)i * DM * (2 * DI);
        const float* w_cv  = conv_w     + (size_t)i * DI * DCONV;
        const float* b_cv  = conv_b     + (size_t)i * DI;
        const float* w_xp  = x_proj_w   + (size_t)i * (DTR + 2 * DS) * DI;
        const float* w_dtp = dt_proj_w  + (size_t)i * DI * DTR;
        const float* b_dtp = dt_proj_b  + (size_t)i * DI;
        const float* a_log = A_log      + (size_t)i * DI * DS;
        const float* d_sk  = D_skip     + (size_t)i * DI;
        const float* w_nrm = norm_w     + (size_t)i * DM;

        if (i > 0) {
            rmsnorm3_kernel<<<TT, 256>>>(ph, w_nrm, pxn);
            zero_kernel<<<(TT * 2 * DI + 255) / 256, 256>>>(pproj, TT * 2 * DI);
        }

        // in_proj (bf16x3): [1024, 2304] @ [3072, 2304]^T -> proj, split-K=3 atomic
        {
            dim3 grid(TT / BM, (2 * DI) / BN, 3);
            hmma_gemm_kernel<2, 0><<<grid, 256, HMMA_SMEM>>>(
                pxn, w_in3, pproj, 3 * DM, 3 * DM, 2 * DI, (3 * DM) / 3);
        }

        // conv + silu
        conv_silu_kernel<<<(TT * DI + 255) / 256, 256>>>(pproj, w_cv, b_cv, pconv);

        // x_proj: fp32, split-K=6 atomic
        zero_kernel<<<(TT * 80 + 255) / 256, 256>>>(pssm, TT * 80);
        {
            dim3 grid((80 + GBN - 1) / GBN, TT / GBM, 6);
            gemm_tn_kernel<EPI_NONE, true><<<grid, 256>>>(
                pconv, DI, w_xp, DI, pssm, 80, TT, 80, DI / 6, nullptr);
        }

        // dt_proj + softplus
        {
            dim3 grid(DI / GBN, TT / GBM, 1);
            gemm_tn_kernel<EPI_SOFTPLUS_BIAS, false><<<grid, 256>>>(
                pssm, 80, w_dtp, DTR, pdt, DI, TT, DI, DTR, b_dtp);
        }

        // selective scan -> fp16x2 y
        {
            dim3 grid(DI / 16, BB);
            scan_kernel<<<grid, 256>>>(pdt, pconv, pssm, pproj, a_log, d_sk, py);
        }

        // out_proj (fp16x2) + residual: h += y @ w_out^T, split-K=6 (288 CTAs)
        {
            dim3 grid(TT / BM, DM / BN, 6);
            hmma_gemm_kernel<2, 1><<<grid, 256, HMMA_SMEM>>>(
                py, w_out2, ph, 2 * DI, 2 * DI, DM, (2 * DI) / 6);
        }
    }

    // final rmsnorm -> fp16x2 [hi, lo]
    rmsnorm2h_kernel<<<TT, 256>>>(ph, norm_f_w, pxnh);

    // lm head (fp16 2-plane): [1024, 1536] @ [32000, 1536]^T -> logits
    {
        dim3 grid(TT / BM, VOCAB / BN, 1);
        hmma_gemm_kernel<0, 1><<<grid, 256, HMMA_SMEM>>>(
            pxnh, pembh, logits, 2 * DM, 2 * DM, VOCAB, 2 * DM);
    }
}

// round 11
// speedup vs baseline: 3.2135x; 1.4897x over previous
#include <cuda_runtime.h>
#include <cuda_bf16.h>
#include <cuda_fp16.h>
#include <cstdint>
#include <math.h>

// ---------------- problem constants ----------------
#define NL    4
#define DM    768
#define DI    1536
#define DS    16
#define DTR   48
#define DCONV 4
#define VOCAB 32000
#define BB    2
#define LL    512
#define TT    (BB*LL)          // 1024 tokens
#define EPS   1e-5f

// ---------------- scratch (static device memory; no allocations) -------------
__device__ float g_h   [TT * DM];            // residual stream (fp32)
__device__ float g_proj[TT * 2 * DI];        // in_proj output (h | gate)
__device__ float g_conv[TT * DI];            // conv + silu output
__device__ float g_ssm [TT * 80];            // x_proj output (dt_raw | B | C)
__device__ float g_dt  [TT * DI];            // softplus(dt)

// in_proj: bf16x3 planes. Activations [hi,lo,hi]; weights [hi,hi,lo].
__device__ __nv_bfloat16 g_xn_big   [TT * 3 * DM];                  // rmsnorm out (layers)
__device__ __nv_bfloat16 g_inw_big  [(size_t)NL * (2*DI) * 3 * DM]; // all in_proj_w
// out_proj + lm head: fp16 2-plane. Activations [hi,lo]; weights [hi,hi].
__device__ __half g_y_half    [TT * 2 * DI];                        // scan out
__device__ __half g_outw_half [(size_t)NL * DM * 2 * DI];           // all out_proj_w
__device__ __half g_xn_half   [TT * 2 * DM];                        // final rmsnorm out
__device__ __half g_embed_half[(size_t)VOCAB * 2 * DM];             // embed (lm head)

// ---------------- helpers ----------------
__device__ __forceinline__ uint32_t smem_u32(const void* p) {
    uint32_t a;
    asm("{ .reg .u64 t; cvta.to.shared.u64 t, %1; cvt.u32.u64 %0, t; }" : "=r"(a) : "l"(p));
    return a;
}
__device__ __forceinline__ void cp_async16(uint32_t dst, const void* src) {
    asm volatile("cp.async.cg.shared.global [%0], [%1], 16;" :: "r"(dst), "l"(src));
}
#define CP_COMMIT() asm volatile("cp.async.commit_group;" ::: "memory")
#define CP_WAIT(n)  asm volatile("cp.async.wait_group %0;" :: "n"(n) : "memory")

__device__ __forceinline__ float siluf(float x) { return x / (1.0f + __expf(-x)); }
__device__ __forceinline__ float softplusf(float x) {
    return fmaxf(x, 0.0f) + log1pf(__expf(-fabsf(x)));
}
__device__ __forceinline__ void split_bf16(float v, __nv_bfloat16& hi, __nv_bfloat16& lo) {
    hi = __float2bfloat16(v);
    lo = __float2bfloat16(v - __bfloat162float(hi));
}

// ---------------- fused embed gather + rmsnorm (+ zero pproj slice) ---------
__global__ void embed_rmsnorm3_kernel(const int* __restrict__ ids,
                                      const float* __restrict__ embed,
                                      const float* __restrict__ w,
                                      float* __restrict__ hout,
                                      __nv_bfloat16* __restrict__ out,
                                      float4* __restrict__ zbuf) {
    __shared__ float red[256];
    int t = blockIdx.x;
    // zero 3072 floats of proj per CTA (TT CTAs cover TT*2*DI)
    {
        float4 z = make_float4(0.f, 0.f, 0.f, 0.f);
        float4* zp = zbuf + (size_t)t * 768;
        #pragma unroll
        for (int q = 0; q < 3; q++) zp[threadIdx.x + q * 256] = z;
    }
    int id = ids[t];
    const float* src = embed + (size_t)id * DM;
    float* hdst = hout + (size_t)t * DM;
    float vals[3];
    float s = 0.0f;
    #pragma unroll
    for (int q = 0; q < 3; q++) {
        int d = threadIdx.x + q * 256;
        float v = src[d];
        vals[q] = v;
        hdst[d] = v;
        s += v * v;
    }
    red[threadIdx.x] = s;
    __syncthreads();
    for (int off = 128; off > 0; off >>= 1) {
        if (threadIdx.x < off) red[threadIdx.x] += red[threadIdx.x + off];
        __syncthreads();
    }
    float scale = rsqrtf(red[0] / (float)DM + EPS);
    __nv_bfloat16* dst = out + (size_t)t * (3 * DM);
    #pragma unroll
    for (int q = 0; q < 3; q++) {
        int d = threadIdx.x + q * 256;
        float v = vals[q] * scale * w[d];
        __nv_bfloat16 hi, lo; split_bf16(v, hi, lo);
        dst[d] = hi; dst[DM + d] = lo; dst[2 * DM + d] = hi;
    }
}

// ---------------- rmsnorm -> bf16x3 (+ zero pproj slice) --------------------
__global__ void rmsnorm3_kernel(const float* __restrict__ x,
                                const float* __restrict__ w,
                                __nv_bfloat16* __restrict__ out,
                                float4* __restrict__ zbuf) {
    __shared__ float red[256];
    int t = blockIdx.x;
    {
        float4 z = make_float4(0.f, 0.f, 0.f, 0.f);
        float4* zp = zbuf + (size_t)t * 768;
        #pragma unroll
        for (int q = 0; q < 3; q++) zp[threadIdx.x + q * 256] = z;
    }
    const float* row = x + (size_t)t * DM;
    float vals[3];
    float s = 0.0f;
    #pragma unroll
    for (int q = 0; q < 3; q++) {
        int d = threadIdx.x + q * 256;
        float v = row[d];
        vals[q] = v;
        s += v * v;
    }
    red[threadIdx.x] = s;
    __syncthreads();
    for (int off = 128; off > 0; off >>= 1) {
        if (threadIdx.x < off) red[threadIdx.x] += red[threadIdx.x + off];
        __syncthreads();
    }
    float scale = rsqrtf(red[0] / (float)DM + EPS);
    __nv_bfloat16* dst = out + (size_t)t * (3 * DM);
    #pragma unroll
    for (int q = 0; q < 3; q++) {
        int d = threadIdx.x + q * 256;
        float v = vals[q] * scale * w[d];
        __nv_bfloat16 hi, lo; split_bf16(v, hi, lo);
        dst[d] = hi; dst[DM + d] = lo; dst[2 * DM + d] = hi;
    }
}

// ---------------- final rmsnorm -> fp16x2 planes [T, 2*DM] (hi, lo) ---------
__global__ void rmsnorm2h_kernel(const float* __restrict__ x,
                                 const float* __restrict__ w,
                                 __half* __restrict__ out) {
    __shared__ float red[256];
    int t = blockIdx.x;
    const float* row = x + (size_t)t * DM;
    float s = 0.0f;
    for (int d = threadIdx.x; d < DM; d += blockDim.x) { float v = row[d]; s += v * v; }
    red[threadIdx.x] = s;
    __syncthreads();
    for (int off = 128; off > 0; off >>= 1) {
        if (threadIdx.x < off) red[threadIdx.x] += red[threadIdx.x + off];
        __syncthreads();
    }
    float scale = rsqrtf(red[0] / (float)DM + EPS);
    __half* dst = out + (size_t)t * (2 * DM);
    for (int d = threadIdx.x; d < DM; d += blockDim.x) {
        float v = row[d] * scale * w[d];
        __half hi = __float2half(v);
        __half lo = __float2half(v - __half2float(hi));
        dst[d] = hi; dst[DM + d] = lo;
    }
}

// ---------------- fp32 [R,C] -> bf16x3 weight planes (1 row/thread-chunk) ---
__global__ void convert3_w_kernel(const float* __restrict__ src,
                                  __nv_bfloat16* __restrict__ dst,
                                  int C) {
    int c8 = blockIdx.x * blockDim.x + threadIdx.x;
    int C8 = C >> 3;
    if (c8 >= C8) return;
    int r = blockIdx.y;
    const float* s = src + (size_t)r * C + c8 * 8;
    float4 v0 = *(const float4*)(s);
    float4 v1 = *(const float4*)(s + 4);
    __nv_bfloat16 h[8], l[8];
    split_bf16(v0.x, h[0], l[0]); split_bf16(v0.y, h[1], l[1]);
    split_bf16(v0.z, h[2], l[2]); split_bf16(v0.w, h[3], l[3]);
    split_bf16(v1.x, h[4], l[4]); split_bf16(v1.y, h[5], l[5]);
    split_bf16(v1.z, h[6], l[6]); split_bf16(v1.w, h[7], l[7]);
    uint4 hv, lv;
    ((__nv_bfloat162*)&hv)[0] = __halves2bfloat162(h[0], h[1]);
    ((__nv_bfloat162*)&hv)[1] = __halves2bfloat162(h[2], h[3]);
    ((__nv_bfloat162*)&hv)[2] = __halves2bfloat162(h[4], h[5]);
    ((__nv_bfloat162*)&hv)[3] = __halves2bfloat162(h[6], h[7]);
    ((__nv_bfloat162*)&lv)[0] = __halves2bfloat162(l[0], l[1]);
    ((__nv_bfloat162*)&lv)[1] = __halves2bfloat162(l[2], l[3]);
    ((__nv_bfloat162*)&lv)[2] = __halves2bfloat162(l[4], l[5]);
    ((__nv_bfloat162*)&lv)[3] = __halves2bfloat162(l[6], l[7]);
    __nv_bfloat16* d = dst + (size_t)r * (3 * (size_t)C) + c8 * 8;
    *(uint4*)(d)         = hv;
    *(uint4*)(d + C)     = hv;
    *(uint4*)(d + 2 * C) = lv;
}

// ---------------- fp32 [R,C] -> fp16x2 planes (1 row/thread-chunk) ----------
__global__ void convert2h_w_kernel(const float* __restrict__ src,
                                   __half* __restrict__ dst,
                                   int C) {
    int c8 = blockIdx.x * blockDim.x + threadIdx.x;
    int C8 = C >> 3;
    if (c8 >= C8) return;
    int r = blockIdx.y;
    const float* s = src + (size_t)r * C + c8 * 8;
    float4 v0 = *(const float4*)(s);
    float4 v1 = *(const float4*)(s + 4);
    uint4 hv;
    ((__half2*)&hv)[0] = __halves2half2(__float2half(v0.x), __float2half(v0.y));
    ((__half2*)&hv)[1] = __halves2half2(__float2half(v0.z), __float2half(v0.w));
    ((__half2*)&hv)[2] = __halves2half2(__float2half(v1.x), __float2half(v1.y));
    ((__half2*)&hv)[3] = __halves2half2(__float2half(v1.z), __float2half(v1.w));
    __half* d = dst + (size_t)r * (2 * (size_t)C) + c8 * 8;
    *(uint4*)(d)     = hv;
    *(uint4*)(d + C) = hv;
}

// =============================================================================
// HMMA 16-bit GEMM: C[M,N] (=/+=) A[M,:] @ W[N,:]^T over kchunk K-cols starting
// at blockIdx.z*kchunk. FP16=0: bf16 operands; FP16=1: fp16 operands.
// 128x128 CTA tile, BK=64, 256 threads (8 warps: 2x4), mma.m16n8k16,
// 3-stage cp.async pipeline with rotating buffer counters, 1 sync/iter.
// =============================================================================
#define BM 128
#define BN 128
#define BK 64
#define SSTR 72                 // smem row stride in 16-bit elems (64 + 8 pad)
#define NSTAGE 3
#define STAGE_ELEMS (BM * SSTR)          // 9216
#define STAGE_BYTES (STAGE_ELEMS * 2)    // 18432 B
#define HMMA_SMEM (NSTAGE * 2 * STAGE_BYTES)   // 110592 B

template <int EPI, int FP16, typename T>   // EPI: 0 store, 1 add, 2 atomicAdd
__global__ void __launch_bounds__(256, 2)
hmma_gemm_kernel(const T* __restrict__ A,
                 const T* __restrict__ W,
                 float* __restrict__ C, int lda, int ldw, int N, int kchunk)
{
    extern __shared__ char dsm_raw[];
    T* dsm = (T*)dsm_raw;

    const int tid = threadIdx.x;
    const int lane = tid & 31;
    const int wid = tid >> 5;
    const int wm = wid >> 2;     // 0..1 -> 64 rows
    const int wn = wid & 3;      // 0..3 -> 32 cols
    const int bm = blockIdx.x * BM;
    const int bn = blockIdx.y * BN;
    const int kbeg = blockIdx.z * kchunk;

    const uint32_t sA = smem_u32(dsm);
    const uint32_t sW = sA + NSTAGE * STAGE_BYTES;

    const int ar0 = tid >> 3;            // 0..31
    const int ak0 = (tid & 7) * 8;       // 0..56
    const T* Ag = A + (size_t)bm * lda + kbeg + ak0;
    const T* Wg = W + (size_t)bn * ldw + kbeg + ak0;
    uint32_t stoff[4];
    const T *Agp[4], *Wgp[4];
    #pragma unroll
    for (int q = 0; q < 4; q++) {
        int row = ar0 + q * 32;
        stoff[q] = (uint32_t)(row * SSTR + ak0) * 2;
        Agp[q] = Ag + (size_t)row * lda;
        Wgp[q] = Wg + (size_t)row * ldw;
    }

    uint32_t a_base[4], b_base[2];
    {
        const int grp = lane >> 3, wi = lane & 7;
        #pragma unroll
        for (int mt = 0; mt < 4; mt++) {
            int row = wm * 64 + mt * 16 + (lane & 15);
            int col = (lane >> 4) * 8;
            a_base[mt] = (uint32_t)(row * SSTR + col) * 2;
        }
        #pragma unroll
        for (int np = 0; np < 2; np++) {
            int row = wn * 32 + np * 16 + (grp >> 1) * 8 + wi;
            int col = (grp & 1) * 8;
            b_base[np] = (uint32_t)(row * SSTR + col) * 2;
        }
    }

    float acc[4][4][4];
    #pragma unroll
    for (int i = 0; i < 4; i++)
        #pragma unroll
        for (int j = 0; j < 4; j++)
            #pragma unroll
            for (int k = 0; k < 4; k++) acc[i][j][k] = 0.0f;

#define LOAD_TILE(buf, k0) do { \
    uint32_t ab_ = sA + (buf) * STAGE_BYTES; \
    uint32_t wb_ = sW + (buf) * STAGE_BYTES; \
    _Pragma("unroll") \
    for (int q = 0; q < 4; q++) { \
        cp_async16(ab_ + stoff[q], Agp[q] + (k0)); \
        cp_async16(wb_ + stoff[q], Wgp[q] + (k0)); \
    } \
} while (0)

    const int nc = kchunk / BK;
    LOAD_TILE(0, 0); CP_COMMIT();
    LOAD_TILE(1, BK); CP_COMMIT();

    int load_buf = 2;
    int cons_buf = 0;

    for (int c = 0; c < nc; c++) {
        CP_WAIT(1);
        __syncthreads();
        int nf = c + 2;
        if (nf < nc) LOAD_TILE(load_buf, nf * BK);
        CP_COMMIT();
        if (++load_buf == NSTAGE) load_buf = 0;

        const uint32_t ab = sA + cons_buf * STAGE_BYTES;
        const uint32_t wb = sW + cons_buf * STAGE_BYTES;
        if (++cons_buf == NSTAGE) cons_buf = 0;

        #pragma unroll
        for (int ks = 0; ks < 4; ks++) {
            uint32_t a[4][4];
            #pragma unroll
            for (int mt = 0; mt < 4; mt++)
                asm volatile("ldmatrix.sync.aligned.m8n8.x4.shared.b16 {%0,%1,%2,%3}, [%4];"
                    : "=r"(a[mt][0]), "=r"(a[mt][1]), "=r"(a[mt][2]), "=r"(a[mt][3])
                    : "r"(ab + a_base[mt] + ks * 32));
            uint32_t b[4][2];
            #pragma unroll
            for (int np = 0; np < 2; np++)
                asm volatile("ldmatrix.sync.aligned.m8n8.x4.shared.b16 {%0,%1,%2,%3}, [%4];"
                    : "=r"(b[np * 2][0]), "=r"(b[np * 2][1]),
                      "=r"(b[np * 2 + 1][0]), "=r"(b[np * 2 + 1][1])
                    : "r"(wb + b_base[np] + ks * 32));
            #pragma unroll
            for (int mt = 0; mt < 4; mt++)
                #pragma unroll
                for (int nt = 0; nt < 4; nt++) {
                    if (FP16)
                        asm volatile(
                            "mma.sync.aligned.m16n8k16.row.col.f32.f16.f16.f32 "
                            "{%0,%1,%2,%3}, {%4,%5,%6,%7}, {%8,%9}, {%0,%1,%2,%3};"
                            : "+f"(acc[mt][nt][0]), "+f"(acc[mt][nt][1]),
                              "+f"(acc[mt][nt][2]), "+f"(acc[mt][nt][3])
                            : "r"(a[mt][0]), "r"(a[mt][1]), "r"(a[mt][2]), "r"(a[mt][3]),
                              "r"(b[nt][0]), "r"(b[nt][1]));
                    else
                        asm volatile(
                            "mma.sync.aligned.m16n8k16.row.col.f32.bf16.bf16.f32 "
                            "{%0,%1,%2,%3}, {%4,%5,%6,%7}, {%8,%9}, {%0,%1,%2,%3};"
                            : "+f"(acc[mt][nt][0]), "+f"(acc[mt][nt][1]),
                              "+f"(acc[mt][nt][2]), "+f"(acc[mt][nt][3])
                            : "r"(a[mt][0]), "r"(a[mt][1]), "r"(a[mt][2]), "r"(a[mt][3]),
                              "r"(b[nt][0]), "r"(b[nt][1]));
                }
        }
    }
#undef LOAD_TILE

    // epilogue
    #pragma unroll
    for (int mt = 0; mt < 4; mt++) {
        int r0 = bm + wm * 64 + mt * 16 + (lane >> 2);
        #pragma unroll
        for (int nt = 0; nt < 4; nt++) {
            int c0 = bn + wn * 32 + nt * 8 + (lane & 3) * 2;
            float* p0 = C + (size_t)r0 * N + c0;
            float* p1 = C + (size_t)(r0 + 8) * N + c0;
            if (EPI == 2) {
                atomicAdd(p0 + 0, acc[mt][nt][0]); atomicAdd(p0 + 1, acc[mt][nt][1]);
                atomicAdd(p1 + 0, acc[mt][nt][2]); atomicAdd(p1 + 1, acc[mt][nt][3]);
            } else if (EPI == 1) {
                p0[0] += acc[mt][nt][0]; p0[1] += acc[mt][nt][1];
                p1[0] += acc[mt][nt][2]; p1[1] += acc[mt][nt][3];
            } else {
                p0[0] = acc[mt][nt][0]; p0[1] = acc[mt][nt][1];
                p1[0] = acc[mt][nt][2]; p1[1] = acc[mt][nt][3];
            }
        }
    }
}

// ---------------- fp32 SGEMM for small shapes (x_proj, dt_proj) -------------
#define GBM 64
#define GBN 64
#define GBK 16
enum { EPI_NONE = 0, EPI_SOFTPLUS_BIAS = 1 };

template <int EPI, bool ATOMIC>
__global__ void __launch_bounds__(256)
gemm_tn_kernel(const float* __restrict__ A, int lda,
               const float* __restrict__ W, int ldw,
               float* __restrict__ C, int ldc,
               int M, int N, int kchunk,
               const float* __restrict__ bias)
{
    __shared__ float Asm[GBK][GBM + 1];
    __shared__ float Wsm[GBK][GBN + 1];

    int tid = threadIdx.x;
    int bm = blockIdx.y * GBM;
    int bn = blockIdx.x * GBN;
    int kbeg = blockIdx.z * kchunk;
    int kend = kbeg + kchunk;
    int lr = tid >> 2;
    int lk = (tid & 3) << 2;
    int ty = tid >> 4;
    int tx = tid & 15;

    float acc[4][4];
    #pragma unroll
    for (int i = 0; i < 4; i++)
        #pragma unroll
        for (int j = 0; j < 4; j++) acc[i][j] = 0.0f;

    for (int k0 = kbeg; k0 < kend; k0 += GBK) {
        {
            const float4 v = *(const float4*)(A + (size_t)(bm + lr) * lda + k0 + lk);
            Asm[lk + 0][lr] = v.x; Asm[lk + 1][lr] = v.y;
            Asm[lk + 2][lr] = v.z; Asm[lk + 3][lr] = v.w;
        }
        {
            float4 v = make_float4(0.f, 0.f, 0.f, 0.f);
            int row = bn + lr;
            if (row < N) v = *(const float4*)(W + (size_t)row * ldw + k0 + lk);
            Wsm[lk + 0][lr] = v.x; Wsm[lk + 1][lr] = v.y;
            Wsm[lk + 2][lr] = v.z; Wsm[lk + 3][lr] = v.w;
        }
        __syncthreads();
        #pragma unroll
        for (int kk = 0; kk < GBK; kk++) {
            float a[4], b[4];
            #pragma unroll
            for (int i = 0; i < 4; i++) a[i] = Asm[kk][ty * 4 + i];
            #pragma unroll
            for (int j = 0; j < 4; j++) b[j] = Wsm[kk][tx * 4 + j];
            #pragma unroll
            for (int i = 0; i < 4; i++)
                #pragma unroll
                for (int j = 0; j < 4; j++)
                    acc[i][j] = fmaf(a[i], b[j], acc[i][j]);
        }
        __syncthreads();
    }

    #pragma unroll
    for (int i = 0; i < 4; i++) {
        int row = bm + ty * 4 + i;
        #pragma unroll
        for (int j = 0; j < 4; j++) {
            int col = bn + tx * 4 + j;
            if (col < N) {
                float v = acc[i][j];
                if (ATOMIC) {
                    atomicAdd(&C[(size_t)row * ldc + col], v);
                } else {
                    if (EPI == EPI_SOFTPLUS_BIAS) v = softplusf(v + bias[col]);
                    C[(size_t)row * ldc + col] = v;
                }
            }
        }
    }
}

__global__ void zero_kernel(float* __restrict__ p, int n) {
    int i = blockIdx.x * blockDim.x + threadIdx.x;
    if (i < n) p[i] = 0.0f;
}

// ---------------- causal depthwise conv (width 4) + silu ----------------
__global__ void conv_silu_kernel(const float* __restrict__ proj,
                                 const float* __restrict__ cw,
                                 const float* __restrict__ cb,
                                 float* __restrict__ out)
{
    int idx = blockIdx.x * blockDim.x + threadIdx.x;
    if (idx >= TT * DI) return;
    int d = idx % DI;
    int t = idx / DI;
    int l = t % LL;
    float w0 = cw[d * 4 + 0], w1 = cw[d * 4 + 1], w2 = cw[d * 4 + 2], w3 = cw[d * 4 + 3];
    float acc = cb[d];
    if (l >= 3) acc = fmaf(w0, proj[(size_t)(t - 3) * (2 * DI) + d], acc);
    if (l >= 2) acc = fmaf(w1, proj[(size_t)(t - 2) * (2 * DI) + d], acc);
    if (l >= 1) acc = fmaf(w2, proj[(size_t)(t - 1) * (2 * DI) + d], acc);
    acc = fmaf(w3, proj[(size_t)t * (2 * DI) + d], acc);
    out[idx] = siluf(acc);
}

// ---------------- selective scan (prefetched) -> fp16x2 y [T, 2*DI] ---------
__global__ void scan_kernel(const float* __restrict__ dt,
                            const float* __restrict__ hconv,
                            const float* __restrict__ ssm,
                            const float* __restrict__ proj,
                            const float* __restrict__ A_log,
                            const float* __restrict__ D_skip,
                            __half* __restrict__ y)
{
    int s = threadIdx.x & 15;
    int d = blockIdx.x * 16 + (threadIdx.x >> 4);
    int b = blockIdx.y;

    float Aneg = -__expf(A_log[d * DS + s]);
    float Dk = D_skip[d];

    const int t0 = b * LL;
    // preload iteration 0
    float dtv = dt[(size_t)t0 * DI + d];
    float hv  = hconv[(size_t)t0 * DI + d];
    float Bv  = ssm[(size_t)t0 * 80 + DTR + s];
    float Cv  = ssm[(size_t)t0 * 80 + DTR + DS + s];
    float gv  = proj[(size_t)t0 * (2 * DI) + DI + d];

    float state = 0.0f;
    for (int l = 0; l < LL; l++) {
        int t = t0 + l;
        int tn = t + ((l + 1 < LL) ? 1 : 0);
        // prefetch next iteration (off the critical chain)
        float n_dtv = dt[(size_t)tn * DI + d];
        float n_hv  = hconv[(size_t)tn * DI + d];
        float n_Bv  = ssm[(size_t)tn * 80 + DTR + s];
        float n_Cv  = ssm[(size_t)tn * 80 + DTR + DS + s];
        float n_gv  = proj[(size_t)tn * (2 * DI) + DI + d];

        float a = __expf(dtv * Aneg);
        state = fmaf(a, state, dtv * hv * Bv);
        float p = state * Cv;
        p += __shfl_xor_sync(0xffffffffu, p, 8);
        p += __shfl_xor_sync(0xffffffffu, p, 4);
        p += __shfl_xor_sync(0xffffffffu, p, 2);
        p += __shfl_xor_sync(0xffffffffu, p, 1);
        if (s == 0) {
            float val = (p + Dk * hv) * siluf(gv);
            __half hi = __float2half(val);
            __half lo = __float2half(val - __half2float(hi));
            __half* dst = y + (size_t)t * (2 * DI);
            dst[d] = hi; dst[DI + d] = lo;
        }
        dtv = n_dtv; hv = n_hv; Bv = n_Bv; Cv = n_Cv; gv = n_gv;
    }
}

// ---------------- launcher ----------------
extern "C" void kernel_launch(void* const* d_in, const int* in_sizes, int n_in,
                              void* d_out, int out_size)
{
    const int*   input_ids = (const int*)  d_in[0];
    const float* embed     = (const float*)d_in[1];
    const float* norm_f_w  = (const float*)d_in[2];
    const float* in_proj_w = (const float*)d_in[3];
    const float* conv_w    = (const float*)d_in[4];
    const float* conv_b    = (const float*)d_in[5];
    const float* x_proj_w  = (const float*)d_in[6];
    const float* dt_proj_w = (const float*)d_in[7];
    const float* dt_proj_b = (const float*)d_in[8];
    const float* A_log     = (const float*)d_in[9];
    const float* D_skip    = (const float*)d_in[10];
    const float* out_proj_w= (const float*)d_in[11];
    const float* norm_w    = (const float*)d_in[12];
    float* logits = (float*)d_out;

    float *ph, *pproj, *pconv, *pssm, *pdt;
    __nv_bfloat16 *pxn, *pinw;
    __half *py, *poutw, *pxnh, *pembh;
    cudaGetSymbolAddress((void**)&ph,    g_h);
    cudaGetSymbolAddress((void**)&pproj, g_proj);
    cudaGetSymbolAddress((void**)&pconv, g_conv);
    cudaGetSymbolAddress((void**)&pssm,  g_ssm);
    cudaGetSymbolAddress((void**)&pdt,   g_dt);
    cudaGetSymbolAddress((void**)&pxn,   g_xn_big);
    cudaGetSymbolAddress((void**)&pinw,  g_inw_big);
    cudaGetSymbolAddress((void**)&py,    g_y_half);
    cudaGetSymbolAddress((void**)&poutw, g_outw_half);
    cudaGetSymbolAddress((void**)&pxnh,  g_xn_half);
    cudaGetSymbolAddress((void**)&pembh, g_embed_half);

    cudaFuncSetAttribute((const void*)hmma_gemm_kernel<2, 0, __nv_bfloat16>,
                         cudaFuncAttributeMaxDynamicSharedMemorySize, HMMA_SMEM);
    cudaFuncSetAttribute((const void*)hmma_gemm_kernel<2, 1, __half>,
                         cudaFuncAttributeMaxDynamicSharedMemorySize, HMMA_SMEM);
    cudaFuncSetAttribute((const void*)hmma_gemm_kernel<0, 1, __half>,
                         cudaFuncAttributeMaxDynamicSharedMemorySize, HMMA_SMEM);

    // 1-3: bulk weight conversions (1 row per thread-chunk, high MLP)
    {
        dim3 ge((DM / 8 + 127) / 128, VOCAB);
        convert2h_w_kernel<<<ge, 128>>>(embed, pembh, DM);            // lm head fp16 [hi,hi]
        dim3 gi((DM / 8 + 127) / 128, NL * 2 * DI);
        convert3_w_kernel<<<gi, 128>>>(in_proj_w, pinw, DM);          // in_proj bf16x3
        dim3 go((DI / 8 + 127) / 128, NL * DM);
        convert2h_w_kernel<<<go, 128>>>(out_proj_w, poutw, DI);       // out_proj fp16 [hi,hi]
    }

    // 4: fused embed gather + layer-0 rmsnorm + zero(pproj)
    embed_rmsnorm3_kernel<<<TT, 256>>>(input_ids, embed, norm_w, ph, pxn, (float4*)pproj);
    // 5: zero pssm (so launch #6 = in_proj GEMM for ncu -s 5 -c 1)
    zero_kernel<<<(TT * 80 + 255) / 256, 256>>>(pssm, TT * 80);

    for (int i = 0; i < NL; i++) {
        const __nv_bfloat16* w_in3  = pinw  + (size_t)i * (2 * DI) * (3 * DM);
        const __half*        w_out2 = poutw + (size_t)i * DM * (2 * DI);
        const float* w_cv  = conv_w     + (size_t)i * DI * DCONV;
        const float* b_cv  = conv_b     + (size_t)i * DI;
        const float* w_xp  = x_proj_w   + (size_t)i * (DTR + 2 * DS) * DI;
        const float* w_dtp = dt_proj_w  + (size_t)i * DI * DTR;
        const float* b_dtp = dt_proj_b  + (size_t)i * DI;
        const float* a_log = A_log      + (size_t)i * DI * DS;
        const float* d_sk  = D_skip     + (size_t)i * DI;
        const float* w_nrm = norm_w     + (size_t)i * DM;

        if (i > 0) {
            rmsnorm3_kernel<<<TT, 256>>>(ph, w_nrm, pxn, (float4*)pproj);
            zero_kernel<<<(TT * 80 + 255) / 256, 256>>>(pssm, TT * 80);
        }

        // in_proj (bf16x3): [1024, 2304] @ [3072, 2304]^T -> proj, split-K=3 atomic
        {
            dim3 grid(TT / BM, (2 * DI) / BN, 3);
            hmma_gemm_kernel<2, 0><<<grid, 256, HMMA_SMEM>>>(
                pxn, w_in3, pproj, 3 * DM, 3 * DM, 2 * DI, (3 * DM) / 3);
        }

        // conv + silu
        conv_silu_kernel<<<(TT * DI + 255) / 256, 256>>>(pproj, w_cv, b_cv, pconv);

        // x_proj: fp32, split-K=6 atomic (pssm zeroed above)
        {
            dim3 grid((80 + GBN - 1) / GBN, TT / GBM, 6);
            gemm_tn_kernel<EPI_NONE, true><<<grid, 256>>>(
                pconv, DI, w_xp, DI, pssm, 80, TT, 80, DI / 6, nullptr);
        }

        // dt_proj + softplus
        {
            dim3 grid(DI / GBN, TT / GBM, 1);
            gemm_tn_kernel<EPI_SOFTPLUS_BIAS, false><<<grid, 256>>>(
                pssm, 80, w_dtp, DTR, pdt, DI, TT, DI, DTR, b_dtp);
        }

        // selective scan -> fp16x2 y
        {
            dim3 grid(DI / 16, BB);
            scan_kernel<<<grid, 256>>>(pdt, pconv, pssm, pproj, a_log, d_sk, py);
        }

        // out_proj (fp16x2) + residual: h += y @ w_out^T, split-K=6 (288 CTAs)
        {
            dim3 grid(TT / BM, DM / BN, 6);
            hmma_gemm_kernel<2, 1><<<grid, 256, HMMA_SMEM>>>(
                py, w_out2, ph, 2 * DI, 2 * DI, DM, (2 * DI) / 6);
        }
    }

    // final rmsnorm -> fp16x2 [hi, lo]
    rmsnorm2h_kernel<<<TT, 256>>>(ph, norm_f_w, pxnh);

    // lm head (fp16 2-plane): [1024, 1536] @ [32000, 1536]^T -> logits
    {
        dim3 grid(TT / BM, VOCAB / BN, 1);
        hmma_gemm_kernel<0, 1><<<grid, 256, HMMA_SMEM>>>(
            pxnh, pembh, logits, 2 * DM, 2 * DM, VOCAB, 2 * DM);
    }
}

// round 12
// speedup vs baseline: 3.3258x; 1.0349x over previous
#include <cuda_runtime.h>
#include <cuda_bf16.h>
#include <cuda_fp16.h>
#include <cstdint>
#include <math.h>

// ---------------- problem constants ----------------
#define NL    4
#define DM    768
#define DI    1536
#define DS    16
#define DTR   48
#define DCONV 4
#define VOCAB 32000
#define BB    2
#define LL    512
#define TT    (BB*LL)          // 1024 tokens
#define EPS   1e-5f

// ---------------- scratch (static device memory; no allocations) -------------
__device__ float g_h   [TT * DM];            // residual stream (fp32)
__device__ float g_proj[TT * 2 * DI];        // in_proj output (h | gate)
__device__ float g_conv[TT * DI];            // conv + silu output
__device__ float g_ssm [TT * 80];            // x_proj output (dt_raw | B | C)
__device__ float g_dt  [TT * DI];            // softplus(dt)

// All big GEMMs: fp16 2-plane. Activations [hi,lo]; weights [hi,hi].
__device__ __half g_xn_half   [TT * 2 * DM];                        // rmsnorm out (layers + final)
__device__ __half g_inw_half  [(size_t)NL * (2*DI) * 2 * DM];       // all in_proj_w
__device__ __half g_y_half    [TT * 2 * DI];                        // scan out
__device__ __half g_outw_half [(size_t)NL * DM * 2 * DI];           // all out_proj_w
__device__ __half g_embed_half[(size_t)VOCAB * 2 * DM];             // embed (lm head)

// ---------------- helpers ----------------
__device__ __forceinline__ uint32_t smem_u32(const void* p) {
    uint32_t a;
    asm("{ .reg .u64 t; cvta.to.shared.u64 t, %1; cvt.u32.u64 %0, t; }" : "=r"(a) : "l"(p));
    return a;
}
__device__ __forceinline__ void cp_async16(uint32_t dst, const void* src) {
    asm volatile("cp.async.cg.shared.global [%0], [%1], 16;" :: "r"(dst), "l"(src));
}
#define CP_COMMIT() asm volatile("cp.async.commit_group;" ::: "memory")
#define CP_WAIT(n)  asm volatile("cp.async.wait_group %0;" :: "n"(n) : "memory")

__device__ __forceinline__ float siluf(float x) { return x / (1.0f + __expf(-x)); }
__device__ __forceinline__ float softplusf(float x) {
    return fmaxf(x, 0.0f) + log1pf(__expf(-fabsf(x)));
}
__device__ __forceinline__ void split_half(float v, __half& hi, __half& lo) {
    hi = __float2half(v);
    lo = __float2half(v - __half2float(hi));
}

// ---------------- fused embed gather + rmsnorm -> fp16x2 (+ zero pproj) -----
__global__ void embed_rmsnorm2h_kernel(const int* __restrict__ ids,
                                       const float* __restrict__ embed,
                                       const float* __restrict__ w,
                                       float* __restrict__ hout,
                                       __half* __restrict__ out,
                                       float4* __restrict__ zbuf) {
    __shared__ float red[256];
    int t = blockIdx.x;
    {
        float4 z = make_float4(0.f, 0.f, 0.f, 0.f);
        float4* zp = zbuf + (size_t)t * 768;
        #pragma unroll
        for (int q = 0; q < 3; q++) zp[threadIdx.x + q * 256] = z;
    }
    int id = ids[t];
    const float* src = embed + (size_t)id * DM;
    float* hdst = hout + (size_t)t * DM;
    float vals[3];
    float s = 0.0f;
    #pragma unroll
    for (int q = 0; q < 3; q++) {
        int d = threadIdx.x + q * 256;
        float v = src[d];
        vals[q] = v;
        hdst[d] = v;
        s += v * v;
    }
    red[threadIdx.x] = s;
    __syncthreads();
    for (int off = 128; off > 0; off >>= 1) {
        if (threadIdx.x < off) red[threadIdx.x] += red[threadIdx.x + off];
        __syncthreads();
    }
    float scale = rsqrtf(red[0] / (float)DM + EPS);
    __half* dst = out + (size_t)t * (2 * DM);
    #pragma unroll
    for (int q = 0; q < 3; q++) {
        int d = threadIdx.x + q * 256;
        float v = vals[q] * scale * w[d];
        __half hi, lo; split_half(v, hi, lo);
        dst[d] = hi; dst[DM + d] = lo;
    }
}

// ---------------- rmsnorm -> fp16x2 (+ zero pproj slice) --------------------
__global__ void rmsnorm2h_zero_kernel(const float* __restrict__ x,
                                      const float* __restrict__ w,
                                      __half* __restrict__ out,
                                      float4* __restrict__ zbuf) {
    __shared__ float red[256];
    int t = blockIdx.x;
    {
        float4 z = make_float4(0.f, 0.f, 0.f, 0.f);
        float4* zp = zbuf + (size_t)t * 768;
        #pragma unroll
        for (int q = 0; q < 3; q++) zp[threadIdx.x + q * 256] = z;
    }
    const float* row = x + (size_t)t * DM;
    float vals[3];
    float s = 0.0f;
    #pragma unroll
    for (int q = 0; q < 3; q++) {
        int d = threadIdx.x + q * 256;
        float v = row[d];
        vals[q] = v;
        s += v * v;
    }
    red[threadIdx.x] = s;
    __syncthreads();
    for (int off = 128; off > 0; off >>= 1) {
        if (threadIdx.x < off) red[threadIdx.x] += red[threadIdx.x + off];
        __syncthreads();
    }
    float scale = rsqrtf(red[0] / (float)DM + EPS);
    __half* dst = out + (size_t)t * (2 * DM);
    #pragma unroll
    for (int q = 0; q < 3; q++) {
        int d = threadIdx.x + q * 256;
        float v = vals[q] * scale * w[d];
        __half hi, lo; split_half(v, hi, lo);
        dst[d] = hi; dst[DM + d] = lo;
    }
}

// ---------------- final rmsnorm -> fp16x2 (no zero) -------------------------
__global__ void rmsnorm2h_kernel(const float* __restrict__ x,
                                 const float* __restrict__ w,
                                 __half* __restrict__ out) {
    __shared__ float red[256];
    int t = blockIdx.x;
    const float* row = x + (size_t)t * DM;
    float s = 0.0f;
    for (int d = threadIdx.x; d < DM; d += blockDim.x) { float v = row[d]; s += v * v; }
    red[threadIdx.x] = s;
    __syncthreads();
    for (int off = 128; off > 0; off >>= 1) {
        if (threadIdx.x < off) red[threadIdx.x] += red[threadIdx.x + off];
        __syncthreads();
    }
    float scale = rsqrtf(red[0] / (float)DM + EPS);
    __half* dst = out + (size_t)t * (2 * DM);
    for (int d = threadIdx.x; d < DM; d += blockDim.x) {
        float v = row[d] * scale * w[d];
        __half hi, lo; split_half(v, hi, lo);
        dst[d] = hi; dst[DM + d] = lo;
    }
}

// ---------------- fp32 [R,C] -> fp16x2 planes (1 row/thread-chunk) ----------
__global__ void convert2h_w_kernel(const float* __restrict__ src,
                                   __half* __restrict__ dst,
                                   int C) {
    int c8 = blockIdx.x * blockDim.x + threadIdx.x;
    int C8 = C >> 3;
    if (c8 >= C8) return;
    int r = blockIdx.y;
    const float* s = src + (size_t)r * C + c8 * 8;
    float4 v0 = *(const float4*)(s);
    float4 v1 = *(const float4*)(s + 4);
    uint4 hv;
    ((__half2*)&hv)[0] = __halves2half2(__float2half(v0.x), __float2half(v0.y));
    ((__half2*)&hv)[1] = __halves2half2(__float2half(v0.z), __float2half(v0.w));
    ((__half2*)&hv)[2] = __halves2half2(__float2half(v1.x), __float2half(v1.y));
    ((__half2*)&hv)[3] = __halves2half2(__float2half(v1.z), __float2half(v1.w));
    __half* d = dst + (size_t)r * (2 * (size_t)C) + c8 * 8;
    *(uint4*)(d)     = hv;
    *(uint4*)(d + C) = hv;
}

// =============================================================================
// HMMA fp16 GEMM: C[M,N] (=/+=) A[M,:] @ W[N,:]^T over kchunk K-cols starting
// at blockIdx.z*kchunk. 128x128 CTA tile, BK=64, 256 threads, mma.m16n8k16,
// 3-stage cp.async pipeline with rotating buffer counters, 1 sync/iter.
// =============================================================================
#define BM 128
#define BN 128
#define BK 64
#define SSTR 72                 // smem row stride in 16-bit elems (64 + 8 pad)
#define NSTAGE 3
#define STAGE_ELEMS (BM * SSTR)          // 9216
#define STAGE_BYTES (STAGE_ELEMS * 2)    // 18432 B
#define HMMA_SMEM (NSTAGE * 2 * STAGE_BYTES)   // 110592 B

template <int EPI>   // EPI: 0 store, 2 atomicAdd (split-K)
__global__ void __launch_bounds__(256, 2)
hmma_gemm_kernel(const __half* __restrict__ A,
                 const __half* __restrict__ W,
                 float* __restrict__ C, int lda, int ldw, int N, int kchunk)
{
    extern __shared__ char dsm_raw[];
    __half* dsm = (__half*)dsm_raw;

    const int tid = threadIdx.x;
    const int lane = tid & 31;
    const int wid = tid >> 5;
    const int wm = wid >> 2;     // 0..1 -> 64 rows
    const int wn = wid & 3;      // 0..3 -> 32 cols
    const int bm = blockIdx.x * BM;
    const int bn = blockIdx.y * BN;
    const int kbeg = blockIdx.z * kchunk;

    const uint32_t sA = smem_u32(dsm);
    const uint32_t sW = sA + NSTAGE * STAGE_BYTES;

    const int ar0 = tid >> 3;            // 0..31
    const int ak0 = (tid & 7) * 8;       // 0..56
    const __half* Ag = A + (size_t)bm * lda + kbeg + ak0;
    const __half* Wg = W + (size_t)bn * ldw + kbeg + ak0;
    uint32_t stoff[4];
    const __half *Agp[4], *Wgp[4];
    #pragma unroll
    for (int q = 0; q < 4; q++) {
        int row = ar0 + q * 32;
        stoff[q] = (uint32_t)(row * SSTR + ak0) * 2;
        Agp[q] = Ag + (size_t)row * lda;
        Wgp[q] = Wg + (size_t)row * ldw;
    }

    uint32_t a_base[4], b_base[2];
    {
        const int grp = lane >> 3, wi = lane & 7;
        #pragma unroll
        for (int mt = 0; mt < 4; mt++) {
            int row = wm * 64 + mt * 16 + (lane & 15);
            int col = (lane >> 4) * 8;
            a_base[mt] = (uint32_t)(row * SSTR + col) * 2;
        }
        #pragma unroll
        for (int np = 0; np < 2; np++) {
            int row = wn * 32 + np * 16 + (grp >> 1) * 8 + wi;
            int col = (grp & 1) * 8;
            b_base[np] = (uint32_t)(row * SSTR + col) * 2;
        }
    }

    float acc[4][4][4];
    #pragma unroll
    for (int i = 0; i < 4; i++)
        #pragma unroll
        for (int j = 0; j < 4; j++)
            #pragma unroll
            for (int k = 0; k < 4; k++) acc[i][j][k] = 0.0f;

#define LOAD_TILE(buf, k0) do { \
    uint32_t ab_ = sA + (buf) * STAGE_BYTES; \
    uint32_t wb_ = sW + (buf) * STAGE_BYTES; \
    _Pragma("unroll") \
    for (int q = 0; q < 4; q++) { \
        cp_async16(ab_ + stoff[q], Agp[q] + (k0)); \
        cp_async16(wb_ + stoff[q], Wgp[q] + (k0)); \
    } \
} while (0)

    const int nc = kchunk / BK;
    LOAD_TILE(0, 0); CP_COMMIT();
    LOAD_TILE(1, BK); CP_COMMIT();

    int load_buf = 2;
    int cons_buf = 0;

    for (int c = 0; c < nc; c++) {
        CP_WAIT(1);
        __syncthreads();
        int nf = c + 2;
        if (nf < nc) LOAD_TILE(load_buf, nf * BK);
        CP_COMMIT();
        if (++load_buf == NSTAGE) load_buf = 0;

        const uint32_t ab = sA + cons_buf * STAGE_BYTES;
        const uint32_t wb = sW + cons_buf * STAGE_BYTES;
        if (++cons_buf == NSTAGE) cons_buf = 0;

        #pragma unroll
        for (int ks = 0; ks < 4; ks++) {
            uint32_t a[4][4];
            #pragma unroll
            for (int mt = 0; mt < 4; mt++)
                asm volatile("ldmatrix.sync.aligned.m8n8.x4.shared.b16 {%0,%1,%2,%3}, [%4];"
                    : "=r"(a[mt][0]), "=r"(a[mt][1]), "=r"(a[mt][2]), "=r"(a[mt][3])
                    : "r"(ab + a_base[mt] + ks * 32));
            uint32_t b[4][2];
            #pragma unroll
            for (int np = 0; np < 2; np++)
                asm volatile("ldmatrix.sync.aligned.m8n8.x4.shared.b16 {%0,%1,%2,%3}, [%4];"
                    : "=r"(b[np * 2][0]), "=r"(b[np * 2][1]),
                      "=r"(b[np * 2 + 1][0]), "=r"(b[np * 2 + 1][1])
                    : "r"(wb + b_base[np] + ks * 32));
            #pragma unroll
            for (int mt = 0; mt < 4; mt++)
                #pragma unroll
                for (int nt = 0; nt < 4; nt++)
                    asm volatile(
                        "mma.sync.aligned.m16n8k16.row.col.f32.f16.f16.f32 "
                        "{%0,%1,%2,%3}, {%4,%5,%6,%7}, {%8,%9}, {%0,%1,%2,%3};"
                        : "+f"(acc[mt][nt][0]), "+f"(acc[mt][nt][1]),
                          "+f"(acc[mt][nt][2]), "+f"(acc[mt][nt][3])
                        : "r"(a[mt][0]), "r"(a[mt][1]), "r"(a[mt][2]), "r"(a[mt][3]),
                          "r"(b[nt][0]), "r"(b[nt][1]));
        }
    }
#undef LOAD_TILE

    // epilogue
    #pragma unroll
    for (int mt = 0; mt < 4; mt++) {
        int r0 = bm + wm * 64 + mt * 16 + (lane >> 2);
        #pragma unroll
        for (int nt = 0; nt < 4; nt++) {
            int c0 = bn + wn * 32 + nt * 8 + (lane & 3) * 2;
            float* p0 = C + (size_t)r0 * N + c0;
            float* p1 = C + (size_t)(r0 + 8) * N + c0;
            if (EPI == 2) {
                atomicAdd(p0 + 0, acc[mt][nt][0]); atomicAdd(p0 + 1, acc[mt][nt][1]);
                atomicAdd(p1 + 0, acc[mt][nt][2]); atomicAdd(p1 + 1, acc[mt][nt][3]);
            } else {
                p0[0] = acc[mt][nt][0]; p0[1] = acc[mt][nt][1];
                p1[0] = acc[mt][nt][2]; p1[1] = acc[mt][nt][3];
            }
        }
    }
}

// ---------------- fp32 SGEMM for small shapes (x_proj, dt_proj) -------------
#define GBM 64
#define GBN 64
#define GBK 16
enum { EPI_NONE = 0, EPI_SOFTPLUS_BIAS = 1 };

template <int EPI, bool ATOMIC>
__global__ void __launch_bounds__(256)
gemm_tn_kernel(const float* __restrict__ A, int lda,
               const float* __restrict__ W, int ldw,
               float* __restrict__ C, int ldc,
               int M, int N, int kchunk,
               const float* __restrict__ bias)
{
    __shared__ float Asm[GBK][GBM + 1];
    __shared__ float Wsm[GBK][GBN + 1];

    int tid = threadIdx.x;
    int bm = blockIdx.y * GBM;
    int bn = blockIdx.x * GBN;
    int kbeg = blockIdx.z * kchunk;
    int kend = kbeg + kchunk;
    int lr = tid >> 2;
    int lk = (tid & 3) << 2;
    int ty = tid >> 4;
    int tx = tid & 15;

    float acc[4][4];
    #pragma unroll
    for (int i = 0; i < 4; i++)
        #pragma unroll
        for (int j = 0; j < 4; j++) acc[i][j] = 0.0f;

    for (int k0 = kbeg; k0 < kend; k0 += GBK) {
        {
            const float4 v = *(const float4*)(A + (size_t)(bm + lr) * lda + k0 + lk);
            Asm[lk + 0][lr] = v.x; Asm[lk + 1][lr] = v.y;
            Asm[lk + 2][lr] = v.z; Asm[lk + 3][lr] = v.w;
        }
        {
            float4 v = make_float4(0.f, 0.f, 0.f, 0.f);
            int row = bn + lr;
            if (row < N) v = *(const float4*)(W + (size_t)row * ldw + k0 + lk);
            Wsm[lk + 0][lr] = v.x; Wsm[lk + 1][lr] = v.y;
            Wsm[lk + 2][lr] = v.z; Wsm[lk + 3][lr] = v.w;
        }
        __syncthreads();
        #pragma unroll
        for (int kk = 0; kk < GBK; kk++) {
            float a[4], b[4];
            #pragma unroll
            for (int i = 0; i < 4; i++) a[i] = Asm[kk][ty * 4 + i];
            #pragma unroll
            for (int j = 0; j < 4; j++) b[j] = Wsm[kk][tx * 4 + j];
            #pragma unroll
            for (int i = 0; i < 4; i++)
                #pragma unroll
                for (int j = 0; j < 4; j++)
                    acc[i][j] = fmaf(a[i], b[j], acc[i][j]);
        }
        __syncthreads();
    }

    #pragma unroll
    for (int i = 0; i < 4; i++) {
        int row = bm + ty * 4 + i;
        #pragma unroll
        for (int j = 0; j < 4; j++) {
            int col = bn + tx * 4 + j;
            if (col < N) {
                float v = acc[i][j];
                if (ATOMIC) {
                    atomicAdd(&C[(size_t)row * ldc + col], v);
                } else {
                    if (EPI == EPI_SOFTPLUS_BIAS) v = softplusf(v + bias[col]);
                    C[(size_t)row * ldc + col] = v;
                }
            }
        }
    }
}

__global__ void zero_kernel(float* __restrict__ p, int n) {
    int i = blockIdx.x * blockDim.x + threadIdx.x;
    if (i < n) p[i] = 0.0f;
}

// ---------------- causal depthwise conv (width 4) + silu ----------------
__global__ void conv_silu_kernel(const float* __restrict__ proj,
                                 const float* __restrict__ cw,
                                 const float* __restrict__ cb,
                                 float* __restrict__ out)
{
    int idx = blockIdx.x * blockDim.x + threadIdx.x;
    if (idx >= TT * DI) return;
    int d = idx % DI;
    int t = idx / DI;
    int l = t % LL;
    float w0 = cw[d * 4 + 0], w1 = cw[d * 4 + 1], w2 = cw[d * 4 + 2], w3 = cw[d * 4 + 3];
    float acc = cb[d];
    if (l >= 3) acc = fmaf(w0, proj[(size_t)(t - 3) * (2 * DI) + d], acc);
    if (l >= 2) acc = fmaf(w1, proj[(size_t)(t - 2) * (2 * DI) + d], acc);
    if (l >= 1) acc = fmaf(w2, proj[(size_t)(t - 1) * (2 * DI) + d], acc);
    acc = fmaf(w3, proj[(size_t)t * (2 * DI) + d], acc);
    out[idx] = siluf(acc);
}

// ---------------- selective scan (prefetched) -> fp16x2 y [T, 2*DI] ---------
__global__ void scan_kernel(const float* __restrict__ dt,
                            const float* __restrict__ hconv,
                            const float* __restrict__ ssm,
                            const float* __restrict__ proj,
                            const float* __restrict__ A_log,
                            const float* __restrict__ D_skip,
                            __half* __restrict__ y)
{
    int s = threadIdx.x & 15;
    int d = blockIdx.x * 16 + (threadIdx.x >> 4);
    int b = blockIdx.y;

    float Aneg = -__expf(A_log[d * DS + s]);
    float Dk = D_skip[d];

    const int t0 = b * LL;
    float dtv = dt[(size_t)t0 * DI + d];
    float hv  = hconv[(size_t)t0 * DI + d];
    float Bv  = ssm[(size_t)t0 * 80 + DTR + s];
    float Cv  = ssm[(size_t)t0 * 80 + DTR + DS + s];
    float gv  = proj[(size_t)t0 * (2 * DI) + DI + d];

    float state = 0.0f;
    for (int l = 0; l < LL; l++) {
        int t = t0 + l;
        int tn = t + ((l + 1 < LL) ? 1 : 0);
        float n_dtv = dt[(size_t)tn * DI + d];
        float n_hv  = hconv[(size_t)tn * DI + d];
        float n_Bv  = ssm[(size_t)tn * 80 + DTR + s];
        float n_Cv  = ssm[(size_t)tn * 80 + DTR + DS + s];
        float n_gv  = proj[(size_t)tn * (2 * DI) + DI + d];

        float a = __expf(dtv * Aneg);
        state = fmaf(a, state, dtv * hv * Bv);
        float p = state * Cv;
        p += __shfl_xor_sync(0xffffffffu, p, 8);
        p += __shfl_xor_sync(0xffffffffu, p, 4);
        p += __shfl_xor_sync(0xffffffffu, p, 2);
        p += __shfl_xor_sync(0xffffffffu, p, 1);
        if (s == 0) {
            float val = (p + Dk * hv) * siluf(gv);
            __half hi, lo; split_half(val, hi, lo);
            __half* dst = y + (size_t)t * (2 * DI);
            dst[d] = hi; dst[DI + d] = lo;
        }
        dtv = n_dtv; hv = n_hv; Bv = n_Bv; Cv = n_Cv; gv = n_gv;
    }
}

// ---------------- launcher ----------------
extern "C" void kernel_launch(void* const* d_in, const int* in_sizes, int n_in,
                              void* d_out, int out_size)
{
    const int*   input_ids = (const int*)  d_in[0];
    const float* embed     = (const float*)d_in[1];
    const float* norm_f_w  = (const float*)d_in[2];
    const float* in_proj_w = (const float*)d_in[3];
    const float* conv_w    = (const float*)d_in[4];
    const float* conv_b    = (const float*)d_in[5];
    const float* x_proj_w  = (const float*)d_in[6];
    const float* dt_proj_w = (const float*)d_in[7];
    const float* dt_proj_b = (const float*)d_in[8];
    const float* A_log     = (const float*)d_in[9];
    const float* D_skip    = (const float*)d_in[10];
    const float* out_proj_w= (const float*)d_in[11];
    const float* norm_w    = (const float*)d_in[12];
    float* logits = (float*)d_out;

    float *ph, *pproj, *pconv, *pssm, *pdt;
    __half *pxnh, *pinw, *py, *poutw, *pembh;
    cudaGetSymbolAddress((void**)&ph,    g_h);
    cudaGetSymbolAddress((void**)&pproj, g_proj);
    cudaGetSymbolAddress((void**)&pconv, g_conv);
    cudaGetSymbolAddress((void**)&pssm,  g_ssm);
    cudaGetSymbolAddress((void**)&pdt,   g_dt);
    cudaGetSymbolAddress((void**)&pxnh,  g_xn_half);
    cudaGetSymbolAddress((void**)&pinw,  g_inw_half);
    cudaGetSymbolAddress((void**)&py,    g_y_half);
    cudaGetSymbolAddress((void**)&poutw, g_outw_half);
    cudaGetSymbolAddress((void**)&pembh, g_embed_half);

    cudaFuncSetAttribute((const void*)hmma_gemm_kernel<0>,
                         cudaFuncAttributeMaxDynamicSharedMemorySize, HMMA_SMEM);
    cudaFuncSetAttribute((const void*)hmma_gemm_kernel<2>,
                         cudaFuncAttributeMaxDynamicSharedMemorySize, HMMA_SMEM);

    // 1-3: bulk weight conversions (all fp16 [hi,hi], 1 row per thread-chunk)
    {
        dim3 ge((DM / 8 + 127) / 128, VOCAB);
        convert2h_w_kernel<<<ge, 128>>>(embed, pembh, DM);            // lm head
        dim3 gi((DM / 8 + 127) / 128, NL * 2 * DI);
        convert2h_w_kernel<<<gi, 128>>>(in_proj_w, pinw, DM);         // in_proj
        dim3 go((DI / 8 + 127) / 128, NL * DM);
        convert2h_w_kernel<<<go, 128>>>(out_proj_w, poutw, DI);       // out_proj
    }

    // 4: fused embed gather + layer-0 rmsnorm (fp16x2) + zero(pproj)
    embed_rmsnorm2h_kernel<<<TT, 256>>>(input_ids, embed, norm_w, ph, pxnh, (float4*)pproj);
    // 5: zero pssm (launch #6 = in_proj GEMM for ncu -s 5 -c 1)
    zero_kernel<<<(TT * 80 + 255) / 256, 256>>>(pssm, TT * 80);

    for (int i = 0; i < NL; i++) {
        const __half* w_in2  = pinw  + (size_t)i * (2 * DI) * (2 * DM);
        const __half* w_out2 = poutw + (size_t)i * DM * (2 * DI);
        const float* w_cv  = conv_w     + (size_t)i * DI * DCONV;
        const float* b_cv  = conv_b     + (size_t)i * DI;
        const float* w_xp  = x_proj_w   + (size_t)i * (DTR + 2 * DS) * DI;
        const float* w_dtp = dt_proj_w  + (size_t)i * DI * DTR;
        const float* b_dtp = dt_proj_b  + (size_t)i * DI;
        const float* a_log = A_log      + (size_t)i * DI * DS;
        const float* d_sk  = D_skip     + (size_t)i * DI;
        const float* w_nrm = norm_w     + (size_t)i * DM;

        if (i > 0) {
            rmsnorm2h_zero_kernel<<<TT, 256>>>(ph, w_nrm, pxnh, (float4*)pproj);
            zero_kernel<<<(TT * 80 + 255) / 256, 256>>>(pssm, TT * 80);
        }

        // in_proj (fp16x2): [1024, 1536] @ [3072, 1536]^T -> proj, split-K=3 atomic
        {
            dim3 grid(TT / BM, (2 * DI) / BN, 3);
            hmma_gemm_kernel<2><<<grid, 256, HMMA_SMEM>>>(
                pxnh, w_in2, pproj, 2 * DM, 2 * DM, 2 * DI, (2 * DM) / 3);
        }

        // conv + silu
        conv_silu_kernel<<<(TT * DI + 255) / 256, 256>>>(pproj, w_cv, b_cv, pconv);

        // x_proj: fp32, split-K=6 atomic (pssm zeroed above)
        {
            dim3 grid((80 + GBN - 1) / GBN, TT / GBM, 6);
            gemm_tn_kernel<EPI_NONE, true><<<grid, 256>>>(
                pconv, DI, w_xp, DI, pssm, 80, TT, 80, DI / 6, nullptr);
        }

        // dt_proj + softplus
        {
            dim3 grid(DI / GBN, TT / GBM, 1);
            gemm_tn_kernel<EPI_SOFTPLUS_BIAS, false><<<grid, 256>>>(
                pssm, 80, w_dtp, DTR, pdt, DI, TT, DI, DTR, b_dtp);
        }

        // selective scan -> fp16x2 y
        {
            dim3 grid(DI / 16, BB);
            scan_kernel<<<grid, 256>>>(pdt, pconv, pssm, pproj, a_log, d_sk, py);
        }

        // out_proj (fp16x2) + residual: h += y @ w_out^T, split-K=6 (288 CTAs)
        {
            dim3 grid(TT / BM, DM / BN, 6);
            hmma_gemm_kernel<2><<<grid, 256, HMMA_SMEM>>>(
                py, w_out2, ph, 2 * DI, 2 * DI, DM, (2 * DI) / 6);
        }
    }

    // final rmsnorm -> fp16x2 [hi, lo]
    rmsnorm2h_kernel<<<TT, 256>>>(ph, norm_f_w, pxnh);

    // lm head (fp16 2-plane): [1024, 1536] @ [32000, 1536]^T -> logits
    {
        dim3 grid(TT / BM, VOCAB / BN, 1);
        hmma_gemm_kernel<0><<<grid, 256, HMMA_SMEM>>>(
            pxnh, pembh, logits, 2 * DM, 2 * DM, VOCAB, 2 * DM);
    }
}

// round 13
// speedup vs baseline: 3.3283x; 1.0007x over previous
#include <cuda_runtime.h>
#include <cuda_bf16.h>
#include <cuda_fp16.h>
#include <cstdint>
#include <math.h>

// ---------------- problem constants ----------------
#define NL    4
#define DM    768
#define DI    1536
#define DS    16
#define DTR   48
#define DCONV 4
#define VOCAB 32000
#define BB    2
#define LL    512
#define TT    (BB*LL)          // 1024 tokens
#define EPS   1e-5f

// ---------------- scratch (static device memory; no allocations) -------------
__device__ float g_h   [TT * DM];            // residual stream (fp32)
__device__ float g_proj[TT * 2 * DI];        // in_proj output (h | gate)
__device__ float g_conv[TT * DI];            // conv + silu output
__device__ float g_ssm [TT * 80];            // x_proj output (dt_raw | B | C)
__device__ float g_dt  [TT * DI];            // softplus(dt)

// Activations: fp16 2-plane [hi, lo]. Weights: fp16 SINGLE plane (the GEMM
// reads it twice via K-index wrap — planes [hi,hi] are identical).
__device__ __half g_xn_half   [TT * 2 * DM];                   // rmsnorm out
__device__ __half g_inw_half  [(size_t)NL * (2*DI) * DM];      // in_proj_w (1 plane)
__device__ __half g_y_half    [TT * 2 * DI];                   // scan out
__device__ __half g_outw_half [(size_t)NL * DM * DI];          // out_proj_w (1 plane)
__device__ __half g_embed_half[(size_t)VOCAB * DM];            // embed (1 plane, fits L2)

// ---------------- helpers ----------------
__device__ __forceinline__ uint32_t smem_u32(const void* p) {
    uint32_t a;
    asm("{ .reg .u64 t; cvta.to.shared.u64 t, %1; cvt.u32.u64 %0, t; }" : "=r"(a) : "l"(p));
    return a;
}
__device__ __forceinline__ void cp_async16(uint32_t dst, const void* src) {
    asm volatile("cp.async.cg.shared.global [%0], [%1], 16;" :: "r"(dst), "l"(src));
}
#define CP_COMMIT() asm volatile("cp.async.commit_group;" ::: "memory")
#define CP_WAIT(n)  asm volatile("cp.async.wait_group %0;" :: "n"(n) : "memory")

__device__ __forceinline__ float siluf(float x) { return x / (1.0f + __expf(-x)); }
__device__ __forceinline__ float softplusf(float x) {
    return fmaxf(x, 0.0f) + log1pf(__expf(-fabsf(x)));
}
__device__ __forceinline__ void split_half(float v, __half& hi, __half& lo) {
    hi = __float2half(v);
    lo = __float2half(v - __half2float(hi));
}

// ---------------- fused embed gather + rmsnorm -> fp16x2 (+ zero pproj) -----
__global__ void embed_rmsnorm2h_kernel(const int* __restrict__ ids,
                                       const float* __restrict__ embed,
                                       const float* __restrict__ w,
                                       float* __restrict__ hout,
                                       __half* __restrict__ out,
                                       float4* __restrict__ zbuf) {
    __shared__ float red[256];
    int t = blockIdx.x;
    {
        float4 z = make_float4(0.f, 0.f, 0.f, 0.f);
        float4* zp = zbuf + (size_t)t * 768;
        #pragma unroll
        for (int q = 0; q < 3; q++) zp[threadIdx.x + q * 256] = z;
    }
    int id = ids[t];
    const float* src = embed + (size_t)id * DM;
    float* hdst = hout + (size_t)t * DM;
    float vals[3];
    float s = 0.0f;
    #pragma unroll
    for (int q = 0; q < 3; q++) {
        int d = threadIdx.x + q * 256;
        float v = src[d];
        vals[q] = v;
        hdst[d] = v;
        s += v * v;
    }
    red[threadIdx.x] = s;
    __syncthreads();
    for (int off = 128; off > 0; off >>= 1) {
        if (threadIdx.x < off) red[threadIdx.x] += red[threadIdx.x + off];
        __syncthreads();
    }
    float scale = rsqrtf(red[0] / (float)DM + EPS);
    __half* dst = out + (size_t)t * (2 * DM);
    #pragma unroll
    for (int q = 0; q < 3; q++) {
        int d = threadIdx.x + q * 256;
        float v = vals[q] * scale * w[d];
        __half hi, lo; split_half(v, hi, lo);
        dst[d] = hi; dst[DM + d] = lo;
    }
}

// ---------------- rmsnorm -> fp16x2 (+ zero pproj slice) --------------------
__global__ void rmsnorm2h_zero_kernel(const float* __restrict__ x,
                                      const float* __restrict__ w,
                                      __half* __restrict__ out,
                                      float4* __restrict__ zbuf) {
    __shared__ float red[256];
    int t = blockIdx.x;
    {
        float4 z = make_float4(0.f, 0.f, 0.f, 0.f);
        float4* zp = zbuf + (size_t)t * 768;
        #pragma unroll
        for (int q = 0; q < 3; q++) zp[threadIdx.x + q * 256] = z;
    }
    const float* row = x + (size_t)t * DM;
    float vals[3];
    float s = 0.0f;
    #pragma unroll
    for (int q = 0; q < 3; q++) {
        int d = threadIdx.x + q * 256;
        float v = row[d];
        vals[q] = v;
        s += v * v;
    }
    red[threadIdx.x] = s;
    __syncthreads();
    for (int off = 128; off > 0; off >>= 1) {
        if (threadIdx.x < off) red[threadIdx.x] += red[threadIdx.x + off];
        __syncthreads();
    }
    float scale = rsqrtf(red[0] / (float)DM + EPS);
    __half* dst = out + (size_t)t * (2 * DM);
    #pragma unroll
    for (int q = 0; q < 3; q++) {
        int d = threadIdx.x + q * 256;
        float v = vals[q] * scale * w[d];
        __half hi, lo; split_half(v, hi, lo);
        dst[d] = hi; dst[DM + d] = lo;
    }
}

// ---------------- final rmsnorm -> fp16x2 (no zero) -------------------------
__global__ void rmsnorm2h_kernel(const float* __restrict__ x,
                                 const float* __restrict__ w,
                                 __half* __restrict__ out) {
    __shared__ float red[256];
    int t = blockIdx.x;
    const float* row = x + (size_t)t * DM;
    float s = 0.0f;
    for (int d = threadIdx.x; d < DM; d += blockDim.x) { float v = row[d]; s += v * v; }
    red[threadIdx.x] = s;
    __syncthreads();
    for (int off = 128; off > 0; off >>= 1) {
        if (threadIdx.x < off) red[threadIdx.x] += red[threadIdx.x + off];
        __syncthreads();
    }
    float scale = rsqrtf(red[0] / (float)DM + EPS);
    __half* dst = out + (size_t)t * (2 * DM);
    for (int d = threadIdx.x; d < DM; d += blockDim.x) {
        float v = row[d] * scale * w[d];
        __half hi, lo; split_half(v, hi, lo);
        dst[d] = hi; dst[DM + d] = lo;
    }
}

// ---------------- fp32 [R,C] -> fp16 single plane (1 row/thread-chunk) ------
__global__ void convert1h_w_kernel(const float* __restrict__ src,
                                   __half* __restrict__ dst,
                                   int C) {
    int c8 = blockIdx.x * blockDim.x + threadIdx.x;
    int C8 = C >> 3;
    if (c8 >= C8) return;
    int r = blockIdx.y;
    const float* s = src + (size_t)r * C + c8 * 8;
    float4 v0 = *(const float4*)(s);
    float4 v1 = *(const float4*)(s + 4);
    uint4 hv;
    ((__half2*)&hv)[0] = __halves2half2(__float2half(v0.x), __float2half(v0.y));
    ((__half2*)&hv)[1] = __halves2half2(__float2half(v0.z), __float2half(v0.w));
    ((__half2*)&hv)[2] = __halves2half2(__float2half(v1.x), __float2half(v1.y));
    ((__half2*)&hv)[3] = __halves2half2(__float2half(v1.z), __float2half(v1.w));
    *(uint4*)(dst + (size_t)r * C + c8 * 8) = hv;
}

// =============================================================================
// HMMA fp16 GEMM: C[M,N] (=/+=) A[M,:] @ W[N, : mod Cw]^T over kchunk K-cols
// starting at blockIdx.z*kchunk. W has only Cw K-columns; K-index wraps
// (W planes are identical). 128x128 tile, BK=64, 256 threads, m16n8k16,
// 3-stage cp.async pipeline, 1 sync/iter.
// =============================================================================
#define BM 128
#define BN 128
#define BK 64
#define SSTR 72                 // smem row stride in 16-bit elems (64 + 8 pad)
#define NSTAGE 3
#define STAGE_ELEMS (BM * SSTR)          // 9216
#define STAGE_BYTES (STAGE_ELEMS * 2)    // 18432 B
#define HMMA_SMEM (NSTAGE * 2 * STAGE_BYTES)   // 110592 B

template <int EPI>   // EPI: 0 store, 2 atomicAdd (split-K)
__global__ void __launch_bounds__(256, 2)
hmma_gemm_kernel(const __half* __restrict__ A,
                 const __half* __restrict__ W,
                 float* __restrict__ C, int lda, int ldw, int Cw,
                 int N, int kchunk)
{
    extern __shared__ char dsm_raw[];
    __half* dsm = (__half*)dsm_raw;

    const int tid = threadIdx.x;
    const int lane = tid & 31;
    const int wid = tid >> 5;
    const int wm = wid >> 2;     // 0..1 -> 64 rows
    const int wn = wid & 3;      // 0..3 -> 32 cols
    const int bm = blockIdx.x * BM;
    const int bn = blockIdx.y * BN;
    const int kbeg = blockIdx.z * kchunk;

    const uint32_t sA = smem_u32(dsm);
    const uint32_t sW = sA + NSTAGE * STAGE_BYTES;

    const int ar0 = tid >> 3;            // 0..31
    const int ak0 = (tid & 7) * 8;       // 0..56
    const __half* Ag = A + (size_t)bm * lda + kbeg + ak0;
    const __half* Wg = W + (size_t)bn * ldw + ak0;   // no kbeg: wrapped per-tile
    uint32_t stoff[4];
    const __half *Agp[4], *Wgp[4];
    #pragma unroll
    for (int q = 0; q < 4; q++) {
        int row = ar0 + q * 32;
        stoff[q] = (uint32_t)(row * SSTR + ak0) * 2;
        Agp[q] = Ag + (size_t)row * lda;
        Wgp[q] = Wg + (size_t)row * ldw;
    }

    uint32_t a_base[4], b_base[2];
    {
        const int grp = lane >> 3, wi = lane & 7;
        #pragma unroll
        for (int mt = 0; mt < 4; mt++) {
            int row = wm * 64 + mt * 16 + (lane & 15);
            int col = (lane >> 4) * 8;
            a_base[mt] = (uint32_t)(row * SSTR + col) * 2;
        }
        #pragma unroll
        for (int np = 0; np < 2; np++) {
            int row = wn * 32 + np * 16 + (grp >> 1) * 8 + wi;
            int col = (grp & 1) * 8;
            b_base[np] = (uint32_t)(row * SSTR + col) * 2;
        }
    }

    float acc[4][4][4];
    #pragma unroll
    for (int i = 0; i < 4; i++)
        #pragma unroll
        for (int j = 0; j < 4; j++)
            #pragma unroll
            for (int k = 0; k < 4; k++) acc[i][j][k] = 0.0f;

// k0 = K offset within this split-K chunk; A uses kbeg+k0 (baked into Agp),
// W uses (kbeg + k0) mod Cw (BK divides Cw, so the wrap is per-tile clean).
#define LOAD_TILE(buf, k0) do { \
    uint32_t ab_ = sA + (buf) * STAGE_BYTES; \
    uint32_t wb_ = sW + (buf) * STAGE_BYTES; \
    int wk_ = kbeg + (k0); \
    while (wk_ >= Cw) wk_ -= Cw; \
    _Pragma("unroll") \
    for (int q = 0; q < 4; q++) { \
        cp_async16(ab_ + stoff[q], Agp[q] + (k0)); \
        cp_async16(wb_ + stoff[q], Wgp[q] + wk_); \
    } \
} while (0)

    const int nc = kchunk / BK;
    LOAD_TILE(0, 0); CP_COMMIT();
    LOAD_TILE(1, BK); CP_COMMIT();

    int load_buf = 2;
    int cons_buf = 0;

    for (int c = 0; c < nc; c++) {
        CP_WAIT(1);
        __syncthreads();
        int nf = c + 2;
        if (nf < nc) LOAD_TILE(load_buf, nf * BK);
        CP_COMMIT();
        if (++load_buf == NSTAGE) load_buf = 0;

        const uint32_t ab = sA + cons_buf * STAGE_BYTES;
        const uint32_t wb = sW + cons_buf * STAGE_BYTES;
        if (++cons_buf == NSTAGE) cons_buf = 0;

        #pragma unroll
        for (int ks = 0; ks < 4; ks++) {
            uint32_t a[4][4];
            #pragma unroll
            for (int mt = 0; mt < 4; mt++)
                asm volatile("ldmatrix.sync.aligned.m8n8.x4.shared.b16 {%0,%1,%2,%3}, [%4];"
                    : "=r"(a[mt][0]), "=r"(a[mt][1]), "=r"(a[mt][2]), "=r"(a[mt][3])
                    : "r"(ab + a_base[mt] + ks * 32));
            uint32_t b[4][2];
            #pragma unroll
            for (int np = 0; np < 2; np++)
                asm volatile("ldmatrix.sync.aligned.m8n8.x4.shared.b16 {%0,%1,%2,%3}, [%4];"
                    : "=r"(b[np * 2][0]), "=r"(b[np * 2][1]),
                      "=r"(b[np * 2 + 1][0]), "=r"(b[np * 2 + 1][1])
                    : "r"(wb + b_base[np] + ks * 32));
            #pragma unroll
            for (int mt = 0; mt < 4; mt++)
                #pragma unroll
                for (int nt = 0; nt < 4; nt++)
                    asm volatile(
                        "mma.sync.aligned.m16n8k16.row.col.f32.f16.f16.f32 "
                        "{%0,%1,%2,%3}, {%4,%5,%6,%7}, {%8,%9}, {%0,%1,%2,%3};"
                        : "+f"(acc[mt][nt][0]), "+f"(acc[mt][nt][1]),
                          "+f"(acc[mt][nt][2]), "+f"(acc[mt][nt][3])
                        : "r"(a[mt][0]), "r"(a[mt][1]), "r"(a[mt][2]), "r"(a[mt][3]),
                          "r"(b[nt][0]), "r"(b[nt][1]));
        }
    }
#undef LOAD_TILE

    // epilogue
    #pragma unroll
    for (int mt = 0; mt < 4; mt++) {
        int r0 = bm + wm * 64 + mt * 16 + (lane >> 2);
        #pragma unroll
        for (int nt = 0; nt < 4; nt++) {
            int c0 = bn + wn * 32 + nt * 8 + (lane & 3) * 2;
            float* p0 = C + (size_t)r0 * N + c0;
            float* p1 = C + (size_t)(r0 + 8) * N + c0;
            if (EPI == 2) {
                atomicAdd(p0 + 0, acc[mt][nt][0]); atomicAdd(p0 + 1, acc[mt][nt][1]);
                atomicAdd(p1 + 0, acc[mt][nt][2]); atomicAdd(p1 + 1, acc[mt][nt][3]);
            } else {
                p0[0] = acc[mt][nt][0]; p0[1] = acc[mt][nt][1];
                p1[0] = acc[mt][nt][2]; p1[1] = acc[mt][nt][3];
            }
        }
    }
}

// ---------------- fp32 SGEMM for small shapes (x_proj, dt_proj) -------------
#define GBM 64
#define GBN 64
#define GBK 16
enum { EPI_NONE = 0, EPI_SOFTPLUS_BIAS = 1 };

template <int EPI, bool ATOMIC>
__global__ void __launch_bounds__(256)
gemm_tn_kernel(const float* __restrict__ A, int lda,
               const float* __restrict__ W, int ldw,
               float* __restrict__ C, int ldc,
               int M, int N, int kchunk,
               const float* __restrict__ bias)
{
    __shared__ float Asm[GBK][GBM + 1];
    __shared__ float Wsm[GBK][GBN + 1];

    int tid = threadIdx.x;
    int bm = blockIdx.y * GBM;
    int bn = blockIdx.x * GBN;
    int kbeg = blockIdx.z * kchunk;
    int kend = kbeg + kchunk;
    int lr = tid >> 2;
    int lk = (tid & 3) << 2;
    int ty = tid >> 4;
    int tx = tid & 15;

    float acc[4][4];
    #pragma unroll
    for (int i = 0; i < 4; i++)
        #pragma unroll
        for (int j = 0; j < 4; j++) acc[i][j] = 0.0f;

    for (int k0 = kbeg; k0 < kend; k0 += GBK) {
        {
            const float4 v = *(const float4*)(A + (size_t)(bm + lr) * lda + k0 + lk);
            Asm[lk + 0][lr] = v.x; Asm[lk + 1][lr] = v.y;
            Asm[lk + 2][lr] = v.z; Asm[lk + 3][lr] = v.w;
        }
        {
            float4 v = make_float4(0.f, 0.f, 0.f, 0.f);
            int row = bn + lr;
            if (row < N) v = *(const float4*)(W + (size_t)row * ldw + k0 + lk);
            Wsm[lk + 0][lr] = v.x; Wsm[lk + 1][lr] = v.y;
            Wsm[lk + 2][lr] = v.z; Wsm[lk + 3][lr] = v.w;
        }
        __syncthreads();
        #pragma unroll
        for (int kk = 0; kk < GBK; kk++) {
            float a[4], b[4];
            #pragma unroll
            for (int i = 0; i < 4; i++) a[i] = Asm[kk][ty * 4 + i];
            #pragma unroll
            for (int j = 0; j < 4; j++) b[j] = Wsm[kk][tx * 4 + j];
            #pragma unroll
            for (int i = 0; i < 4; i++)
                #pragma unroll
                for (int j = 0; j < 4; j++)
                    acc[i][j] = fmaf(a[i], b[j], acc[i][j]);
        }
        __syncthreads();
    }

    #pragma unroll
    for (int i = 0; i < 4; i++) {
        int row = bm + ty * 4 + i;
        #pragma unroll
        for (int j = 0; j < 4; j++) {
            int col = bn + tx * 4 + j;
            if (col < N) {
                float v = acc[i][j];
                if (ATOMIC) {
                    atomicAdd(&C[(size_t)row * ldc + col], v);
                } else {
                    if (EPI == EPI_SOFTPLUS_BIAS) v = softplusf(v + bias[col]);
                    C[(size_t)row * ldc + col] = v;
                }
            }
        }
    }
}

__global__ void zero_kernel(float* __restrict__ p, int n) {
    int i = blockIdx.x * blockDim.x + threadIdx.x;
    if (i < n) p[i] = 0.0f;
}

// ---------------- causal depthwise conv (width 4) + silu ----------------
__global__ void conv_silu_kernel(const float* __restrict__ proj,
                                 const float* __restrict__ cw,
                                 const float* __restrict__ cb,
                                 float* __restrict__ out)
{
    int idx = blockIdx.x * blockDim.x + threadIdx.x;
    if (idx >= TT * DI) return;
    int d = idx % DI;
    int t = idx / DI;
    int l = t % LL;
    float w0 = cw[d * 4 + 0], w1 = cw[d * 4 + 1], w2 = cw[d * 4 + 2], w3 = cw[d * 4 + 3];
    float acc = cb[d];
    if (l >= 3) acc = fmaf(w0, proj[(size_t)(t - 3) * (2 * DI) + d], acc);
    if (l >= 2) acc = fmaf(w1, proj[(size_t)(t - 2) * (2 * DI) + d], acc);
    if (l >= 1) acc = fmaf(w2, proj[(size_t)(t - 1) * (2 * DI) + d], acc);
    acc = fmaf(w3, proj[(size_t)t * (2 * DI) + d], acc);
    out[idx] = siluf(acc);
}

// ---------------- selective scan (prefetched) -> fp16x2 y [T, 2*DI] ---------
__global__ void scan_kernel(const float* __restrict__ dt,
                            const float* __restrict__ hconv,
                            const float* __restrict__ ssm,
                            const float* __restrict__ proj,
                            const float* __restrict__ A_log,
                            const float* __restrict__ D_skip,
                            __half* __restrict__ y)
{
    int s = threadIdx.x & 15;
    int d = blockIdx.x * 16 + (threadIdx.x >> 4);
    int b = blockIdx.y;

    float Aneg = -__expf(A_log[d * DS + s]);
    float Dk = D_skip[d];

    const int t0 = b * LL;
    float dtv = dt[(size_t)t0 * DI + d];
    float hv  = hconv[(size_t)t0 * DI + d];
    float Bv  = ssm[(size_t)t0 * 80 + DTR + s];
    float Cv  = ssm[(size_t)t0 * 80 + DTR + DS + s];
    float gv  = proj[(size_t)t0 * (2 * DI) + DI + d];

    float state = 0.0f;
    for (int l = 0; l < LL; l++) {
        int t = t0 + l;
        int tn = t + ((l + 1 < LL) ? 1 : 0);
        float n_dtv = dt[(size_t)tn * DI + d];
        float n_hv  = hconv[(size_t)tn * DI + d];
        float n_Bv  = ssm[(size_t)tn * 80 + DTR + s];
        float n_Cv  = ssm[(size_t)tn * 80 + DTR + DS + s];
        float n_gv  = proj[(size_t)tn * (2 * DI) + DI + d];

        float a = __expf(dtv * Aneg);
        state = fmaf(a, state, dtv * hv * Bv);
        float p = state * Cv;
        p += __shfl_xor_sync(0xffffffffu, p, 8);
        p += __shfl_xor_sync(0xffffffffu, p, 4);
        p += __shfl_xor_sync(0xffffffffu, p, 2);
        p += __shfl_xor_sync(0xffffffffu, p, 1);
        if (s == 0) {
            float val = (p + Dk * hv) * siluf(gv);
            __half hi, lo; split_half(val, hi, lo);
            __half* dst = y + (size_t)t * (2 * DI);
            dst[d] = hi; dst[DI + d] = lo;
        }
        dtv = n_dtv; hv = n_hv; Bv = n_Bv; Cv = n_Cv; gv = n_gv;
    }
}

// ---------------- launcher ----------------
extern "C" void kernel_launch(void* const* d_in, const int* in_sizes, int n_in,
                              void* d_out, int out_size)
{
    const int*   input_ids = (const int*)  d_in[0];
    const float* embed     = (const float*)d_in[1];
    const float* norm_f_w  = (const float*)d_in[2];
    const float* in_proj_w = (const float*)d_in[3];
    const float* conv_w    = (const float*)d_in[4];
    const float* conv_b    = (const float*)d_in[5];
    const float* x_proj_w  = (const float*)d_in[6];
    const float* dt_proj_w = (const float*)d_in[7];
    const float* dt_proj_b = (const float*)d_in[8];
    const float* A_log     = (const float*)d_in[9];
    const float* D_skip    = (const float*)d_in[10];
    const float* out_proj_w= (const float*)d_in[11];
    const float* norm_w    = (const float*)d_in[12];
    float* logits = (float*)d_out;

    float *ph, *pproj, *pconv, *pssm, *pdt;
    __half *pxnh, *pinw, *py, *poutw, *pembh;
    cudaGetSymbolAddress((void**)&ph,    g_h);
    cudaGetSymbolAddress((void**)&pproj, g_proj);
    cudaGetSymbolAddress((void**)&pconv, g_conv);
    cudaGetSymbolAddress((void**)&pssm,  g_ssm);
    cudaGetSymbolAddress((void**)&pdt,   g_dt);
    cudaGetSymbolAddress((void**)&pxnh,  g_xn_half);
    cudaGetSymbolAddress((void**)&pinw,  g_inw_half);
    cudaGetSymbolAddress((void**)&py,    g_y_half);
    cudaGetSymbolAddress((void**)&poutw, g_outw_half);
    cudaGetSymbolAddress((void**)&pembh, g_embed_half);

    cudaFuncSetAttribute((const void*)hmma_gemm_kernel<0>,
                         cudaFuncAttributeMaxDynamicSharedMemorySize, HMMA_SMEM);
    cudaFuncSetAttribute((const void*)hmma_gemm_kernel<2>,
                         cudaFuncAttributeMaxDynamicSharedMemorySize, HMMA_SMEM);

    // 1-3: bulk weight conversions (single fp16 plane each — GEMM wraps K)
    {
        dim3 ge((DM / 8 + 127) / 128, VOCAB);
        convert1h_w_kernel<<<ge, 128>>>(embed, pembh, DM);            // lm head
        dim3 gi((DM / 8 + 127) / 128, NL * 2 * DI);
        convert1h_w_kernel<<<gi, 128>>>(in_proj_w, pinw, DM);         // in_proj
        dim3 go((DI / 8 + 127) / 128, NL * DM);
        convert1h_w_kernel<<<go, 128>>>(out_proj_w, poutw, DI);       // out_proj
    }

    // 4: fused embed gather + layer-0 rmsnorm (fp16x2) + zero(pproj)
    embed_rmsnorm2h_kernel<<<TT, 256>>>(input_ids, embed, norm_w, ph, pxnh, (float4*)pproj);
    // 5: zero pssm (launch #6 = in_proj GEMM for ncu -s 5 -c 1)
    zero_kernel<<<(TT * 80 + 255) / 256, 256>>>(pssm, TT * 80);

    for (int i = 0; i < NL; i++) {
        const __half* w_in1  = pinw  + (size_t)i * (2 * DI) * DM;
        const __half* w_out1 = poutw + (size_t)i * DM * DI;
        const float* w_cv  = conv_w     + (size_t)i * DI * DCONV;
        const float* b_cv  = conv_b     + (size_t)i * DI;
        const float* w_xp  = x_proj_w   + (size_t)i * (DTR + 2 * DS) * DI;
        const float* w_dtp = dt_proj_w  + (size_t)i * DI * DTR;
        const float* b_dtp = dt_proj_b  + (size_t)i * DI;
        const float* a_log = A_log      + (size_t)i * DI * DS;
        const float* d_sk  = D_skip     + (size_t)i * DI;
        const float* w_nrm = norm_w     + (size_t)i * DM;

        if (i > 0) {
            rmsnorm2h_zero_kernel<<<TT, 256>>>(ph, w_nrm, pxnh, (float4*)pproj);
            zero_kernel<<<(TT * 80 + 255) / 256, 256>>>(pssm, TT * 80);
        }

        // in_proj (fp16x2 A, single-plane W): K'=1536, split-K=3 atomic
        {
            dim3 grid(TT / BM, (2 * DI) / BN, 3);
            hmma_gemm_kernel<2><<<grid, 256, HMMA_SMEM>>>(
                pxnh, w_in1, pproj, 2 * DM, DM, DM, 2 * DI, (2 * DM) / 3);
        }

        // conv + silu
        conv_silu_kernel<<<(TT * DI + 255) / 256, 256>>>(pproj, w_cv, b_cv, pconv);

        // x_proj: fp32, split-K=6 atomic (pssm zeroed above)
        {
            dim3 grid((80 + GBN - 1) / GBN, TT / GBM, 6);
            gemm_tn_kernel<EPI_NONE, true><<<grid, 256>>>(
                pconv, DI, w_xp, DI, pssm, 80, TT, 80, DI / 6, nullptr);
        }

        // dt_proj + softplus
        {
            dim3 grid(DI / GBN, TT / GBM, 1);
            gemm_tn_kernel<EPI_SOFTPLUS_BIAS, false><<<grid, 256>>>(
                pssm, 80, w_dtp, DTR, pdt, DI, TT, DI, DTR, b_dtp);
        }

        // selective scan -> fp16x2 y
        {
            dim3 grid(DI / 16, BB);
            scan_kernel<<<grid, 256>>>(pdt, pconv, pssm, pproj, a_log, d_sk, py);
        }

        // out_proj (fp16x2 A, single-plane W): K'=3072, split-K=6 atomic
        {
            dim3 grid(TT / BM, DM / BN, 6);
            hmma_gemm_kernel<2><<<grid, 256, HMMA_SMEM>>>(
                py, w_out1, ph, 2 * DI, DI, DI, DM, (2 * DI) / 6);
        }
    }

    // final rmsnorm -> fp16x2 [hi, lo]
    rmsnorm2h_kernel<<<TT, 256>>>(ph, norm_f_w, pxnh);

    // lm head (fp16x2 A, single-plane W in L2): K'=1536
    {
        dim3 grid(TT / BM, VOCAB / BN, 1);
        hmma_gemm_kernel<0><<<grid, 256, HMMA_SMEM>>>(
            pxnh, pembh, logits, 2 * DM, DM, DM, VOCAB, 2 * DM);
    }
}

// round 14
// speedup vs baseline: 3.6342x; 1.0919x over previous
#include <cuda_runtime.h>
#include <cuda_bf16.h>
#include <cuda_fp16.h>
#include <cstdint>
#include <math.h>

// ---------------- problem constants ----------------
#define NL    4
#define DM    768
#define DI    1536
#define DS    16
#define DTR   48
#define DCONV 4
#define VOCAB 32000
#define BB    2
#define LL    512
#define TT    (BB*LL)          // 1024 tokens
#define EPS   1e-5f

// ---------------- scratch (static device memory; no allocations) -------------
__device__ float g_h   [TT * DM];            // residual stream (fp32)
__device__ float g_proj[TT * 2 * DI];        // in_proj output (h | gate)
__device__ float g_conv[TT * DI];            // conv + silu output
__device__ float g_ssm [TT * 80];            // x_proj output (dt_raw | B | C)
__device__ float g_dt  [TT * DI];            // softplus(dt)

// Layer GEMMs: activations fp16 2-plane [hi, lo]; weights single fp16 plane
// (GEMM wraps the W K-index — the two logical planes are identical).
// lm head: BOTH A and W single-plane fp16 (K=768).
__device__ __half g_xn_half   [TT * 2 * DM];                   // rmsnorm out
__device__ __half g_inw_half  [(size_t)NL * (2*DI) * DM];      // in_proj_w (1 plane)
__device__ __half g_y_half    [TT * 2 * DI];                   // scan out
__device__ __half g_outw_half [(size_t)NL * DM * DI];          // out_proj_w (1 plane)
__device__ __half g_embed_half[(size_t)VOCAB * DM];            // embed (1 plane)

// ---------------- helpers ----------------
__device__ __forceinline__ uint32_t smem_u32(const void* p) {
    uint32_t a;
    asm("{ .reg .u64 t; cvta.to.shared.u64 t, %1; cvt.u32.u64 %0, t; }" : "=r"(a) : "l"(p));
    return a;
}
__device__ __forceinline__ void cp_async16(uint32_t dst, const void* src) {
    asm volatile("cp.async.cg.shared.global [%0], [%1], 16;" :: "r"(dst), "l"(src));
}
#define CP_COMMIT() asm volatile("cp.async.commit_group;" ::: "memory")
#define CP_WAIT(n)  asm volatile("cp.async.wait_group %0;" :: "n"(n) : "memory")

__device__ __forceinline__ float siluf(float x) { return x / (1.0f + __expf(-x)); }
__device__ __forceinline__ float softplusf(float x) {
    return fmaxf(x, 0.0f) + log1pf(__expf(-fabsf(x)));
}
__device__ __forceinline__ void split_half(float v, __half& hi, __half& lo) {
    hi = __float2half(v);
    lo = __float2half(v - __half2float(hi));
}

// ---------------- fused embed gather + rmsnorm -> fp16x2 (+ zero pproj) -----
__global__ void embed_rmsnorm2h_kernel(const int* __restrict__ ids,
                                       const float* __restrict__ embed,
                                       const float* __restrict__ w,
                                       float* __restrict__ hout,
                                       __half* __restrict__ out,
                                       float4* __restrict__ zbuf) {
    __shared__ float red[256];
    int t = blockIdx.x;
    {
        float4 z = make_float4(0.f, 0.f, 0.f, 0.f);
        float4* zp = zbuf + (size_t)t * 768;
        #pragma unroll
        for (int q = 0; q < 3; q++) zp[threadIdx.x + q * 256] = z;
    }
    int id = ids[t];
    const float* src = embed + (size_t)id * DM;
    float* hdst = hout + (size_t)t * DM;
    float vals[3];
    float s = 0.0f;
    #pragma unroll
    for (int q = 0; q < 3; q++) {
        int d = threadIdx.x + q * 256;
        float v = src[d];
        vals[q] = v;
        hdst[d] = v;
        s += v * v;
    }
    red[threadIdx.x] = s;
    __syncthreads();
    for (int off = 128; off > 0; off >>= 1) {
        if (threadIdx.x < off) red[threadIdx.x] += red[threadIdx.x + off];
        __syncthreads();
    }
    float scale = rsqrtf(red[0] / (float)DM + EPS);
    __half* dst = out + (size_t)t * (2 * DM);
    #pragma unroll
    for (int q = 0; q < 3; q++) {
        int d = threadIdx.x + q * 256;
        float v = vals[q] * scale * w[d];
        __half hi, lo; split_half(v, hi, lo);
        dst[d] = hi; dst[DM + d] = lo;
    }
}

// ---------------- rmsnorm -> fp16x2 (+ zero pproj slice) --------------------
__global__ void rmsnorm2h_zero_kernel(const float* __restrict__ x,
                                      const float* __restrict__ w,
                                      __half* __restrict__ out,
                                      float4* __restrict__ zbuf) {
    __shared__ float red[256];
    int t = blockIdx.x;
    {
        float4 z = make_float4(0.f, 0.f, 0.f, 0.f);
        float4* zp = zbuf + (size_t)t * 768;
        #pragma unroll
        for (int q = 0; q < 3; q++) zp[threadIdx.x + q * 256] = z;
    }
    const float* row = x + (size_t)t * DM;
    float vals[3];
    float s = 0.0f;
    #pragma unroll
    for (int q = 0; q < 3; q++) {
        int d = threadIdx.x + q * 256;
        float v = row[d];
        vals[q] = v;
        s += v * v;
    }
    red[threadIdx.x] = s;
    __syncthreads();
    for (int off = 128; off > 0; off >>= 1) {
        if (threadIdx.x < off) red[threadIdx.x] += red[threadIdx.x + off];
        __syncthreads();
    }
    float scale = rsqrtf(red[0] / (float)DM + EPS);
    __half* dst = out + (size_t)t * (2 * DM);
    #pragma unroll
    for (int q = 0; q < 3; q++) {
        int d = threadIdx.x + q * 256;
        float v = vals[q] * scale * w[d];
        __half hi, lo; split_half(v, hi, lo);
        dst[d] = hi; dst[DM + d] = lo;
    }
}

// ---------------- final rmsnorm -> SINGLE fp16 plane [T, DM] ----------------
__global__ void rmsnorm1h_kernel(const float* __restrict__ x,
                                 const float* __restrict__ w,
                                 __half* __restrict__ out) {
    __shared__ float red[256];
    int t = blockIdx.x;
    const float* row = x + (size_t)t * DM;
    float s = 0.0f;
    for (int d = threadIdx.x; d < DM; d += blockDim.x) { float v = row[d]; s += v * v; }
    red[threadIdx.x] = s;
    __syncthreads();
    for (int off = 128; off > 0; off >>= 1) {
        if (threadIdx.x < off) red[threadIdx.x] += red[threadIdx.x + off];
        __syncthreads();
    }
    float scale = rsqrtf(red[0] / (float)DM + EPS);
    __half* dst = out + (size_t)t * DM;
    for (int d = threadIdx.x; d < DM; d += blockDim.x) {
        float v = row[d] * scale * w[d];
        dst[d] = __float2half(v);
    }
}

// ---------------- fp32 [R,C] -> fp16 single plane (1 row/thread-chunk) ------
__global__ void convert1h_w_kernel(const float* __restrict__ src,
                                   __half* __restrict__ dst,
                                   int C) {
    int c8 = blockIdx.x * blockDim.x + threadIdx.x;
    int C8 = C >> 3;
    if (c8 >= C8) return;
    int r = blockIdx.y;
    const float* s = src + (size_t)r * C + c8 * 8;
    float4 v0 = *(const float4*)(s);
    float4 v1 = *(const float4*)(s + 4);
    uint4 hv;
    ((__half2*)&hv)[0] = __halves2half2(__float2half(v0.x), __float2half(v0.y));
    ((__half2*)&hv)[1] = __halves2half2(__float2half(v0.z), __float2half(v0.w));
    ((__half2*)&hv)[2] = __halves2half2(__float2half(v1.x), __float2half(v1.y));
    ((__half2*)&hv)[3] = __halves2half2(__float2half(v1.z), __float2half(v1.w));
    *(uint4*)(dst + (size_t)r * C + c8 * 8) = hv;
}

// =============================================================================
// HMMA fp16 GEMM: C[M,N] (=/+=) A[M,:] @ W[N, : mod Cw]^T over kchunk K-cols
// starting at blockIdx.z*kchunk. W has only Cw K-columns; K-index wraps.
// 128x128 tile, BK=64, 256 threads, m16n8k16, 3-stage cp.async pipeline.
// =============================================================================
#define BM 128
#define BN 128
#define BK 64
#define SSTR 72                 // smem row stride in 16-bit elems (64 + 8 pad)
#define NSTAGE 3
#define STAGE_ELEMS (BM * SSTR)          // 9216
#define STAGE_BYTES (STAGE_ELEMS * 2)    // 18432 B
#define HMMA_SMEM (NSTAGE * 2 * STAGE_BYTES)   // 110592 B

template <int EPI>   // EPI: 0 store, 2 atomicAdd (split-K)
__global__ void __launch_bounds__(256, 2)
hmma_gemm_kernel(const __half* __restrict__ A,
                 const __half* __restrict__ W,
                 float* __restrict__ C, int lda, int ldw, int Cw,
                 int N, int kchunk)
{
    extern __shared__ char dsm_raw[];
    __half* dsm = (__half*)dsm_raw;

    const int tid = threadIdx.x;
    const int lane = tid & 31;
    const int wid = tid >> 5;
    const int wm = wid >> 2;     // 0..1 -> 64 rows
    const int wn = wid & 3;      // 0..3 -> 32 cols
    const int bm = blockIdx.x * BM;
    const int bn = blockIdx.y * BN;
    const int kbeg = blockIdx.z * kchunk;

    const uint32_t sA = smem_u32(dsm);
    const uint32_t sW = sA + NSTAGE * STAGE_BYTES;

    const int ar0 = tid >> 3;            // 0..31
    const int ak0 = (tid & 7) * 8;       // 0..56
    const __half* Ag = A + (size_t)bm * lda + kbeg + ak0;
    const __half* Wg = W + (size_t)bn * ldw + ak0;
    uint32_t stoff[4];
    const __half *Agp[4], *Wgp[4];
    #pragma unroll
    for (int q = 0; q < 4; q++) {
        int row = ar0 + q * 32;
        stoff[q] = (uint32_t)(row * SSTR + ak0) * 2;
        Agp[q] = Ag + (size_t)row * lda;
        Wgp[q] = Wg + (size_t)row * ldw;
    }

    uint32_t a_base[4], b_base[2];
    {
        const int grp = lane >> 3, wi = lane & 7;
        #pragma unroll
        for (int mt = 0; mt < 4; mt++) {
            int row = wm * 64 + mt * 16 + (lane & 15);
            int col = (lane >> 4) * 8;
            a_base[mt] = (uint32_t)(row * SSTR + col) * 2;
        }
        #pragma unroll
        for (int np = 0; np < 2; np++) {
            int row = wn * 32 + np * 16 + (grp >> 1) * 8 + wi;
            int col = (grp & 1) * 8;
            b_base[np] = (uint32_t)(row * SSTR + col) * 2;
        }
    }

    float acc[4][4][4];
    #pragma unroll
    for (int i = 0; i < 4; i++)
        #pragma unroll
        for (int j = 0; j < 4; j++)
            #pragma unroll
            for (int k = 0; k < 4; k++) acc[i][j][k] = 0.0f;

#define LOAD_TILE(buf, k0) do { \
    uint32_t ab_ = sA + (buf) * STAGE_BYTES; \
    uint32_t wb_ = sW + (buf) * STAGE_BYTES; \
    int wk_ = kbeg + (k0); \
    while (wk_ >= Cw) wk_ -= Cw; \
    _Pragma("unroll") \
    for (int q = 0; q < 4; q++) { \
        cp_async16(ab_ + stoff[q], Agp[q] + (k0)); \
        cp_async16(wb_ + stoff[q], Wgp[q] + wk_); \
    } \
} while (0)

    const int nc = kchunk / BK;
    LOAD_TILE(0, 0); CP_COMMIT();
    LOAD_TILE(1, BK); CP_COMMIT();

    int load_buf = 2;
    int cons_buf = 0;

    for (int c = 0; c < nc; c++) {
        CP_WAIT(1);
        __syncthreads();
        int nf = c + 2;
        if (nf < nc) LOAD_TILE(load_buf, nf * BK);
        CP_COMMIT();
        if (++load_buf == NSTAGE) load_buf = 0;

        const uint32_t ab = sA + cons_buf * STAGE_BYTES;
        const uint32_t wb = sW + cons_buf * STAGE_BYTES;
        if (++cons_buf == NSTAGE) cons_buf = 0;

        #pragma unroll
        for (int ks = 0; ks < 4; ks++) {
            uint32_t a[4][4];
            #pragma unroll
            for (int mt = 0; mt < 4; mt++)
                asm volatile("ldmatrix.sync.aligned.m8n8.x4.shared.b16 {%0,%1,%2,%3}, [%4];"
                    : "=r"(a[mt][0]), "=r"(a[mt][1]), "=r"(a[mt][2]), "=r"(a[mt][3])
                    : "r"(ab + a_base[mt] + ks * 32));
            uint32_t b[4][2];
            #pragma unroll
            for (int np = 0; np < 2; np++)
                asm volatile("ldmatrix.sync.aligned.m8n8.x4.shared.b16 {%0,%1,%2,%3}, [%4];"
                    : "=r"(b[np * 2][0]), "=r"(b[np * 2][1]),
                      "=r"(b[np * 2 + 1][0]), "=r"(b[np * 2 + 1][1])
                    : "r"(wb + b_base[np] + ks * 32));
            #pragma unroll
            for (int mt = 0; mt < 4; mt++)
                #pragma unroll
                for (int nt = 0; nt < 4; nt++)
                    asm volatile(
                        "mma.sync.aligned.m16n8k16.row.col.f32.f16.f16.f32 "
                        "{%0,%1,%2,%3}, {%4,%5,%6,%7}, {%8,%9}, {%0,%1,%2,%3};"
                        : "+f"(acc[mt][nt][0]), "+f"(acc[mt][nt][1]),
                          "+f"(acc[mt][nt][2]), "+f"(acc[mt][nt][3])
                        : "r"(a[mt][0]), "r"(a[mt][1]), "r"(a[mt][2]), "r"(a[mt][3]),
                          "r"(b[nt][0]), "r"(b[nt][1]));
        }
    }
#undef LOAD_TILE

    // epilogue
    #pragma unroll
    for (int mt = 0; mt < 4; mt++) {
        int r0 = bm + wm * 64 + mt * 16 + (lane >> 2);
        #pragma unroll
        for (int nt = 0; nt < 4; nt++) {
            int c0 = bn + wn * 32 + nt * 8 + (lane & 3) * 2;
            float* p0 = C + (size_t)r0 * N + c0;
            float* p1 = C + (size_t)(r0 + 8) * N + c0;
            if (EPI == 2) {
                atomicAdd(p0 + 0, acc[mt][nt][0]); atomicAdd(p0 + 1, acc[mt][nt][1]);
                atomicAdd(p1 + 0, acc[mt][nt][2]); atomicAdd(p1 + 1, acc[mt][nt][3]);
            } else {
                p0[0] = acc[mt][nt][0]; p0[1] = acc[mt][nt][1];
                p1[0] = acc[mt][nt][2]; p1[1] = acc[mt][nt][3];
            }
        }
    }
}

// ---------------- fp32 SGEMM for small shapes (x_proj, dt_proj) -------------
#define GBM 64
#define GBN 64
#define GBK 16
enum { EPI_NONE = 0, EPI_SOFTPLUS_BIAS = 1 };

template <int EPI, bool ATOMIC>
__global__ void __launch_bounds__(256)
gemm_tn_kernel(const float* __restrict__ A, int lda,
               const float* __restrict__ W, int ldw,
               float* __restrict__ C, int ldc,
               int M, int N, int kchunk,
               const float* __restrict__ bias)
{
    __shared__ float Asm[GBK][GBM + 1];
    __shared__ float Wsm[GBK][GBN + 1];

    int tid = threadIdx.x;
    int bm = blockIdx.y * GBM;
    int bn = blockIdx.x * GBN;
    int kbeg = blockIdx.z * kchunk;
    int kend = kbeg + kchunk;
    int lr = tid >> 2;
    int lk = (tid & 3) << 2;
    int ty = tid >> 4;
    int tx = tid & 15;

    float acc[4][4];
    #pragma unroll
    for (int i = 0; i < 4; i++)
        #pragma unroll
        for (int j = 0; j < 4; j++) acc[i][j] = 0.0f;

    for (int k0 = kbeg; k0 < kend; k0 += GBK) {
        {
            const float4 v = *(const float4*)(A + (size_t)(bm + lr) * lda + k0 + lk);
            Asm[lk + 0][lr] = v.x; Asm[lk + 1][lr] = v.y;
            Asm[lk + 2][lr] = v.z; Asm[lk + 3][lr] = v.w;
        }
        {
            float4 v = make_float4(0.f, 0.f, 0.f, 0.f);
            int row = bn + lr;
            if (row < N) v = *(const float4*)(W + (size_t)row * ldw + k0 + lk);
            Wsm[lk + 0][lr] = v.x; Wsm[lk + 1][lr] = v.y;
            Wsm[lk + 2][lr] = v.z; Wsm[lk + 3][lr] = v.w;
        }
        __syncthreads();
        #pragma unroll
        for (int kk = 0; kk < GBK; kk++) {
            float a[4], b[4];
            #pragma unroll
            for (int i = 0; i < 4; i++) a[i] = Asm[kk][ty * 4 + i];
            #pragma unroll
            for (int j = 0; j < 4; j++) b[j] = Wsm[kk][tx * 4 + j];
            #pragma unroll
            for (int i = 0; i < 4; i++)
                #pragma unroll
                for (int j = 0; j < 4; j++)
                    acc[i][j] = fmaf(a[i], b[j], acc[i][j]);
        }
        __syncthreads();
    }

    #pragma unroll
    for (int i = 0; i < 4; i++) {
        int row = bm + ty * 4 + i;
        #pragma unroll
        for (int j = 0; j < 4; j++) {
            int col = bn + tx * 4 + j;
            if (col < N) {
                float v = acc[i][j];
                if (ATOMIC) {
                    atomicAdd(&C[(size_t)row * ldc + col], v);
                } else {
                    if (EPI == EPI_SOFTPLUS_BIAS) v = softplusf(v + bias[col]);
                    C[(size_t)row * ldc + col] = v;
                }
            }
        }
    }
}

__global__ void zero_kernel(float* __restrict__ p, int n) {
    int i = blockIdx.x * blockDim.x + threadIdx.x;
    if (i < n) p[i] = 0.0f;
}

// ---------------- causal depthwise conv (width 4) + silu ----------------
__global__ void conv_silu_kernel(const float* __restrict__ proj,
                                 const float* __restrict__ cw,
                                 const float* __restrict__ cb,
                                 float* __restrict__ out)
{
    int idx = blockIdx.x * blockDim.x + threadIdx.x;
    if (idx >= TT * DI) return;
    int d = idx % DI;
    int t = idx / DI;
    int l = t % LL;
    float w0 = cw[d * 4 + 0], w1 = cw[d * 4 + 1], w2 = cw[d * 4 + 2], w3 = cw[d * 4 + 3];
    float acc = cb[d];
    if (l >= 3) acc = fmaf(w0, proj[(size_t)(t - 3) * (2 * DI) + d], acc);
    if (l >= 2) acc = fmaf(w1, proj[(size_t)(t - 2) * (2 * DI) + d], acc);
    if (l >= 1) acc = fmaf(w2, proj[(size_t)(t - 1) * (2 * DI) + d], acc);
    acc = fmaf(w3, proj[(size_t)t * (2 * DI) + d], acc);
    out[idx] = siluf(acc);
}

// ---------------- selective scan (prefetched) -> fp16x2 y [T, 2*DI] ---------
__global__ void scan_kernel(const float* __restrict__ dt,
                            const float* __restrict__ hconv,
                            const float* __restrict__ ssm,
                            const float* __restrict__ proj,
                            const float* __restrict__ A_log,
                            const float* __restrict__ D_skip,
                            __half* __restrict__ y)
{
    int s = threadIdx.x & 15;
    int d = blockIdx.x * 16 + (threadIdx.x >> 4);
    int b = blockIdx.y;

    float Aneg = -__expf(A_log[d * DS + s]);
    float Dk = D_skip[d];

    const int t0 = b * LL;
    float dtv = dt[(size_t)t0 * DI + d];
    float hv  = hconv[(size_t)t0 * DI + d];
    float Bv  = ssm[(size_t)t0 * 80 + DTR + s];
    float Cv  = ssm[(size_t)t0 * 80 + DTR + DS + s];
    float gv  = proj[(size_t)t0 * (2 * DI) + DI + d];

    float state = 0.0f;
    for (int l = 0; l < LL; l++) {
        int t = t0 + l;
        int tn = t + ((l + 1 < LL) ? 1 : 0);
        float n_dtv = dt[(size_t)tn * DI + d];
        float n_hv  = hconv[(size_t)tn * DI + d];
        float n_Bv  = ssm[(size_t)tn * 80 + DTR + s];
        float n_Cv  = ssm[(size_t)tn * 80 + DTR + DS + s];
        float n_gv  = proj[(size_t)tn * (2 * DI) + DI + d];

        float a = __expf(dtv * Aneg);
        state = fmaf(a, state, dtv * hv * Bv);
        float p = state * Cv;
        p += __shfl_xor_sync(0xffffffffu, p, 8);
        p += __shfl_xor_sync(0xffffffffu, p, 4);
        p += __shfl_xor_sync(0xffffffffu, p, 2);
        p += __shfl_xor_sync(0xffffffffu, p, 1);
        if (s == 0) {
            float val = (p + Dk * hv) * siluf(gv);
            __half hi, lo; split_half(val, hi, lo);
            __half* dst = y + (size_t)t * (2 * DI);
            dst[d] = hi; dst[DI + d] = lo;
        }
        dtv = n_dtv; hv = n_hv; Bv = n_Bv; Cv = n_Cv; gv = n_gv;
    }
}

// ---------------- launcher ----------------
extern "C" void kernel_launch(void* const* d_in, const int* in_sizes, int n_in,
                              void* d_out, int out_size)
{
    const int*   input_ids = (const int*)  d_in[0];
    const float* embed     = (const float*)d_in[1];
    const float* norm_f_w  = (const float*)d_in[2];
    const float* in_proj_w = (const float*)d_in[3];
    const float* conv_w    = (const float*)d_in[4];
    const float* conv_b    = (const float*)d_in[5];
    const float* x_proj_w  = (const float*)d_in[6];
    const float* dt_proj_w = (const float*)d_in[7];
    const float* dt_proj_b = (const float*)d_in[8];
    const float* A_log     = (const float*)d_in[9];
    const float* D_skip    = (const float*)d_in[10];
    const float* out_proj_w= (const float*)d_in[11];
    const float* norm_w    = (const float*)d_in[12];
    float* logits = (float*)d_out;

    float *ph, *pproj, *pconv, *pssm, *pdt;
    __half *pxnh, *pinw, *py, *poutw, *pembh;
    cudaGetSymbolAddress((void**)&ph,    g_h);
    cudaGetSymbolAddress((void**)&pproj, g_proj);
    cudaGetSymbolAddress((void**)&pconv, g_conv);
    cudaGetSymbolAddress((void**)&pssm,  g_ssm);
    cudaGetSymbolAddress((void**)&pdt,   g_dt);
    cudaGetSymbolAddress((void**)&pxnh,  g_xn_half);
    cudaGetSymbolAddress((void**)&pinw,  g_inw_half);
    cudaGetSymbolAddress((void**)&py,    g_y_half);
    cudaGetSymbolAddress((void**)&poutw, g_outw_half);
    cudaGetSymbolAddress((void**)&pembh, g_embed_half);

    cudaFuncSetAttribute((const void*)hmma_gemm_kernel<0>,
                         cudaFuncAttributeMaxDynamicSharedMemorySize, HMMA_SMEM);
    cudaFuncSetAttribute((const void*)hmma_gemm_kernel<2>,
                         cudaFuncAttributeMaxDynamicSharedMemorySize, HMMA_SMEM);

    // 1-3: bulk weight conversions (single fp16 plane each)
    {
        dim3 ge((DM / 8 + 127) / 128, VOCAB);
        convert1h_w_kernel<<<ge, 128>>>(embed, pembh, DM);            // lm head
        dim3 gi((DM / 8 + 127) / 128, NL * 2 * DI);
        convert1h_w_kernel<<<gi, 128>>>(in_proj_w, pinw, DM);         // in_proj
        dim3 go((DI / 8 + 127) / 128, NL * DM);
        convert1h_w_kernel<<<go, 128>>>(out_proj_w, poutw, DI);       // out_proj
    }

    // 4: fused embed gather + layer-0 rmsnorm (fp16x2) + zero(pproj)
    embed_rmsnorm2h_kernel<<<TT, 256>>>(input_ids, embed, norm_w, ph, pxnh, (float4*)pproj);
    // 5: zero pssm
    zero_kernel<<<(TT * 80 + 255) / 256, 256>>>(pssm, TT * 80);

    for (int i = 0; i < NL; i++) {
        const __half* w_in1  = pinw  + (size_t)i * (2 * DI) * DM;
        const __half* w_out1 = poutw + (size_t)i * DM * DI;
        const float* w_cv  = conv_w     + (size_t)i * DI * DCONV;
        const float* b_cv  = conv_b     + (size_t)i * DI;
        const float* w_xp  = x_proj_w   + (size_t)i * (DTR + 2 * DS) * DI;
        const float* w_dtp = dt_proj_w  + (size_t)i * DI * DTR;
        const float* b_dtp = dt_proj_b  + (size_t)i * DI;
        const float* a_log = A_log      + (size_t)i * DI * DS;
        const float* d_sk  = D_skip     + (size_t)i * DI;
        const float* w_nrm = norm_w     + (size_t)i * DM;

        if (i > 0) {
            rmsnorm2h_zero_kernel<<<TT, 256>>>(ph, w_nrm, pxnh, (float4*)pproj);
            zero_kernel<<<(TT * 80 + 255) / 256, 256>>>(pssm, TT * 80);
        }

        // in_proj (fp16x2 A, single-plane W): K'=1536, split-K=3 atomic
        {
            dim3 grid(TT / BM, (2 * DI) / BN, 3);
            hmma_gemm_kernel<2><<<grid, 256, HMMA_SMEM>>>(
                pxnh, w_in1, pproj, 2 * DM, DM, DM, 2 * DI, (2 * DM) / 3);
        }

        // conv + silu
        conv_silu_kernel<<<(TT * DI + 255) / 256, 256>>>(pproj, w_cv, b_cv, pconv);

        // x_proj: fp32, split-K=6 atomic (pssm zeroed above)
        {
            dim3 grid((80 + GBN - 1) / GBN, TT / GBM, 6);
            gemm_tn_kernel<EPI_NONE, true><<<grid, 256>>>(
                pconv, DI, w_xp, DI, pssm, 80, TT, 80, DI / 6, nullptr);
        }

        // dt_proj + softplus
        {
            dim3 grid(DI / GBN, TT / GBM, 1);
            gemm_tn_kernel<EPI_SOFTPLUS_BIAS, false><<<grid, 256>>>(
                pssm, 80, w_dtp, DTR, pdt, DI, TT, DI, DTR, b_dtp);
        }

        // selective scan -> fp16x2 y
        {
            dim3 grid(DI / 16, BB);
            scan_kernel<<<grid, 256>>>(pdt, pconv, pssm, pproj, a_log, d_sk, py);
        }

        // out_proj (fp16x2 A, single-plane W): K'=3072, split-K=6 atomic
        {
            dim3 grid(TT / BM, DM / BN, 6);
            hmma_gemm_kernel<2><<<grid, 256, HMMA_SMEM>>>(
                py, w_out1, ph, 2 * DI, DI, DI, DM, (2 * DI) / 6);
        }
    }

    // final rmsnorm -> single fp16 plane
    rmsnorm1h_kernel<<<TT, 256>>>(ph, norm_f_w, pxnh);

    // lm head: PURE fp16 single-plane, K=768 (half the FLOPs of 2-plane)
    {
        dim3 grid(TT / BM, VOCAB / BN, 1);
        hmma_gemm_kernel<0><<<grid, 256, HMMA_SMEM>>>(
            pxnh, pembh, logits, DM, DM, DM, VOCAB, DM);
    }
}

// round 15
// speedup vs baseline: 4.7535x; 1.3080x over previous
#include <cuda_runtime.h>
#include <cuda_bf16.h>
#include <cuda_fp16.h>
#include <cstdint>
#include <math.h>

// ---------------- problem constants ----------------
#define NL    4
#define DM    768
#define DI    1536
#define DS    16
#define DTR   48
#define DCONV 4
#define VOCAB 32000
#define BB    2
#define LL    512
#define TT    (BB*LL)          // 1024 tokens
#define EPS   1e-5f
#define NCH   4                // scan chunks per sequence
#define CHL   (LL/NCH)         // 128

// ---------------- scratch (static device memory; no allocations) -------------
__device__ float g_h   [TT * DM];            // residual stream (fp32)
__device__ float g_proj[TT * 2 * DI];        // in_proj output (h | gate)
__device__ float g_conv[TT * DI];            // conv + silu output
__device__ float g_ssm [TT * 80];            // x_proj output (dt_raw | B | C)
__device__ float g_dt  [TT * DI];            // softplus(dt)
// chunked-scan intermediates: [b][ch][d][s]
__device__ float g_scanP[BB * NCH * DI * DS];
__device__ float g_scanS[BB * NCH * DI * DS];
__device__ float g_scanI[BB * NCH * DI * DS];

// Layer GEMMs: activations fp16 2-plane [hi, lo]; weights single fp16 plane
// (GEMM wraps the W K-index). lm head: both sides single-plane fp16 (K=768).
__device__ __half g_xn_half   [TT * 2 * DM];                   // rmsnorm out
__device__ __half g_inw_half  [(size_t)NL * (2*DI) * DM];      // in_proj_w (1 plane)
__device__ __half g_y_half    [TT * 2 * DI];                   // scan out
__device__ __half g_outw_half [(size_t)NL * DM * DI];          // out_proj_w (1 plane)
__device__ __half g_embed_half[(size_t)VOCAB * DM];            // embed (1 plane)

// ---------------- helpers ----------------
__device__ __forceinline__ uint32_t smem_u32(const void* p) {
    uint32_t a;
    asm("{ .reg .u64 t; cvta.to.shared.u64 t, %1; cvt.u32.u64 %0, t; }" : "=r"(a) : "l"(p));
    return a;
}
__device__ __forceinline__ void cp_async16(uint32_t dst, const void* src) {
    asm volatile("cp.async.cg.shared.global [%0], [%1], 16;" :: "r"(dst), "l"(src));
}
#define CP_COMMIT() asm volatile("cp.async.commit_group;" ::: "memory")
#define CP_WAIT(n)  asm volatile("cp.async.wait_group %0;" :: "n"(n) : "memory")

__device__ __forceinline__ float siluf(float x) { return x / (1.0f + __expf(-x)); }
__device__ __forceinline__ float softplusf(float x) {
    return fmaxf(x, 0.0f) + log1pf(__expf(-fabsf(x)));
}
__device__ __forceinline__ void split_half(float v, __half& hi, __half& lo) {
    hi = __float2half(v);
    lo = __float2half(v - __half2float(hi));
}

// ---------------- fused embed+rmsnorm -> fp16x2 (+ zero pproj & pssm) -------
__global__ void embed_rmsnorm2h_kernel(const int* __restrict__ ids,
                                       const float* __restrict__ embed,
                                       const float* __restrict__ w,
                                       float* __restrict__ hout,
                                       __half* __restrict__ out,
                                       float4* __restrict__ zbuf,
                                       float* __restrict__ zssm) {
    __shared__ float red[256];
    int t = blockIdx.x;
    {
        float4 z = make_float4(0.f, 0.f, 0.f, 0.f);
        float4* zp = zbuf + (size_t)t * 768;
        #pragma unroll
        for (int q = 0; q < 3; q++) zp[threadIdx.x + q * 256] = z;
        if (threadIdx.x < 80) zssm[t * 80 + threadIdx.x] = 0.0f;
    }
    int id = ids[t];
    const float* src = embed + (size_t)id * DM;
    float* hdst = hout + (size_t)t * DM;
    float vals[3];
    float s = 0.0f;
    #pragma unroll
    for (int q = 0; q < 3; q++) {
        int d = threadIdx.x + q * 256;
        float v = src[d];
        vals[q] = v;
        hdst[d] = v;
        s += v * v;
    }
    red[threadIdx.x] = s;
    __syncthreads();
    for (int off = 128; off > 0; off >>= 1) {
        if (threadIdx.x < off) red[threadIdx.x] += red[threadIdx.x + off];
        __syncthreads();
    }
    float scale = rsqrtf(red[0] / (float)DM + EPS);
    __half* dst = out + (size_t)t * (2 * DM);
    #pragma unroll
    for (int q = 0; q < 3; q++) {
        int d = threadIdx.x + q * 256;
        float v = vals[q] * scale * w[d];
        __half hi, lo; split_half(v, hi, lo);
        dst[d] = hi; dst[DM + d] = lo;
    }
}

// ---------------- rmsnorm -> fp16x2 (+ zero pproj & pssm) -------------------
__global__ void rmsnorm2h_zero_kernel(const float* __restrict__ x,
                                      const float* __restrict__ w,
                                      __half* __restrict__ out,
                                      float4* __restrict__ zbuf,
                                      float* __restrict__ zssm) {
    __shared__ float red[256];
    int t = blockIdx.x;
    {
        float4 z = make_float4(0.f, 0.f, 0.f, 0.f);
        float4* zp = zbuf + (size_t)t * 768;
        #pragma unroll
        for (int q = 0; q < 3; q++) zp[threadIdx.x + q * 256] = z;
        if (threadIdx.x < 80) zssm[t * 80 + threadIdx.x] = 0.0f;
    }
    const float* row = x + (size_t)t * DM;
    float vals[3];
    float s = 0.0f;
    #pragma unroll
    for (int q = 0; q < 3; q++) {
        int d = threadIdx.x + q * 256;
        float v = row[d];
        vals[q] = v;
        s += v * v;
    }
    red[threadIdx.x] = s;
    __syncthreads();
    for (int off = 128; off > 0; off >>= 1) {
        if (threadIdx.x < off) red[threadIdx.x] += red[threadIdx.x + off];
        __syncthreads();
    }
    float scale = rsqrtf(red[0] / (float)DM + EPS);
    __half* dst = out + (size_t)t * (2 * DM);
    #pragma unroll
    for (int q = 0; q < 3; q++) {
        int d = threadIdx.x + q * 256;
        float v = vals[q] * scale * w[d];
        __half hi, lo; split_half(v, hi, lo);
        dst[d] = hi; dst[DM + d] = lo;
    }
}

// ---------------- final rmsnorm -> SINGLE fp16 plane [T, DM] ----------------
__global__ void rmsnorm1h_kernel(const float* __restrict__ x,
                                 const float* __restrict__ w,
                                 __half* __restrict__ out) {
    __shared__ float red[256];
    int t = blockIdx.x;
    const float* row = x + (size_t)t * DM;
    float s = 0.0f;
    for (int d = threadIdx.x; d < DM; d += blockDim.x) { float v = row[d]; s += v * v; }
    red[threadIdx.x] = s;
    __syncthreads();
    for (int off = 128; off > 0; off >>= 1) {
        if (threadIdx.x < off) red[threadIdx.x] += red[threadIdx.x + off];
        __syncthreads();
    }
    float scale = rsqrtf(red[0] / (float)DM + EPS);
    __half* dst = out + (size_t)t * DM;
    for (int d = threadIdx.x; d < DM; d += blockDim.x) {
        float v = row[d] * scale * w[d];
        dst[d] = __float2half(v);
    }
}

// ---------------- fp32 [R,C] -> fp16 single plane (1 row/thread-chunk) ------
__global__ void convert1h_w_kernel(const float* __restrict__ src,
                                   __half* __restrict__ dst,
                                   int C) {
    int c8 = blockIdx.x * blockDim.x + threadIdx.x;
    int C8 = C >> 3;
    if (c8 >= C8) return;
    int r = blockIdx.y;
    const float* s = src + (size_t)r * C + c8 * 8;
    float4 v0 = *(const float4*)(s);
    float4 v1 = *(const float4*)(s + 4);
    uint4 hv;
    ((__half2*)&hv)[0] = __halves2half2(__float2half(v0.x), __float2half(v0.y));
    ((__half2*)&hv)[1] = __halves2half2(__float2half(v0.z), __float2half(v0.w));
    ((__half2*)&hv)[2] = __halves2half2(__float2half(v1.x), __float2half(v1.y));
    ((__half2*)&hv)[3] = __halves2half2(__float2half(v1.z), __float2half(v1.w));
    *(uint4*)(dst + (size_t)r * C + c8 * 8) = hv;
}

// =============================================================================
// HMMA fp16 GEMM (unchanged from round 13)
// =============================================================================
#define BM 128
#define BN 128
#define BK 64
#define SSTR 72
#define NSTAGE 3
#define STAGE_ELEMS (BM * SSTR)
#define STAGE_BYTES (STAGE_ELEMS * 2)
#define HMMA_SMEM (NSTAGE * 2 * STAGE_BYTES)

template <int EPI>   // EPI: 0 store, 2 atomicAdd (split-K)
__global__ void __launch_bounds__(256, 2)
hmma_gemm_kernel(const __half* __restrict__ A,
                 const __half* __restrict__ W,
                 float* __restrict__ C, int lda, int ldw, int Cw,
                 int N, int kchunk)
{
    extern __shared__ char dsm_raw[];
    __half* dsm = (__half*)dsm_raw;

    const int tid = threadIdx.x;
    const int lane = tid & 31;
    const int wid = tid >> 5;
    const int wm = wid >> 2;
    const int wn = wid & 3;
    const int bm = blockIdx.x * BM;
    const int bn = blockIdx.y * BN;
    const int kbeg = blockIdx.z * kchunk;

    const uint32_t sA = smem_u32(dsm);
    const uint32_t sW = sA + NSTAGE * STAGE_BYTES;

    const int ar0 = tid >> 3;
    const int ak0 = (tid & 7) * 8;
    const __half* Ag = A + (size_t)bm * lda + kbeg + ak0;
    const __half* Wg = W + (size_t)bn * ldw + ak0;
    uint32_t stoff[4];
    const __half *Agp[4], *Wgp[4];
    #pragma unroll
    for (int q = 0; q < 4; q++) {
        int row = ar0 + q * 32;
        stoff[q] = (uint32_t)(row * SSTR + ak0) * 2;
        Agp[q] = Ag + (size_t)row * lda;
        Wgp[q] = Wg + (size_t)row * ldw;
    }

    uint32_t a_base[4], b_base[2];
    {
        const int grp = lane >> 3, wi = lane & 7;
        #pragma unroll
        for (int mt = 0; mt < 4; mt++) {
            int row = wm * 64 + mt * 16 + (lane & 15);
            int col = (lane >> 4) * 8;
            a_base[mt] = (uint32_t)(row * SSTR + col) * 2;
        }
        #pragma unroll
        for (int np = 0; np < 2; np++) {
            int row = wn * 32 + np * 16 + (grp >> 1) * 8 + wi;
            int col = (grp & 1) * 8;
            b_base[np] = (uint32_t)(row * SSTR + col) * 2;
        }
    }

    float acc[4][4][4];
    #pragma unroll
    for (int i = 0; i < 4; i++)
        #pragma unroll
        for (int j = 0; j < 4; j++)
            #pragma unroll
            for (int k = 0; k < 4; k++) acc[i][j][k] = 0.0f;

#define LOAD_TILE(buf, k0) do { \
    uint32_t ab_ = sA + (buf) * STAGE_BYTES; \
    uint32_t wb_ = sW + (buf) * STAGE_BYTES; \
    int wk_ = kbeg + (k0); \
    while (wk_ >= Cw) wk_ -= Cw; \
    _Pragma("unroll") \
    for (int q = 0; q < 4; q++) { \
        cp_async16(ab_ + stoff[q], Agp[q] + (k0)); \
        cp_async16(wb_ + stoff[q], Wgp[q] + wk_); \
    } \
} while (0)

    const int nc = kchunk / BK;
    LOAD_TILE(0, 0); CP_COMMIT();
    LOAD_TILE(1, BK); CP_COMMIT();

    int load_buf = 2;
    int cons_buf = 0;

    for (int c = 0; c < nc; c++) {
        CP_WAIT(1);
        __syncthreads();
        int nf = c + 2;
        if (nf < nc) LOAD_TILE(load_buf, nf * BK);
        CP_COMMIT();
        if (++load_buf == NSTAGE) load_buf = 0;

        const uint32_t ab = sA + cons_buf * STAGE_BYTES;
        const uint32_t wb = sW + cons_buf * STAGE_BYTES;
        if (++cons_buf == NSTAGE) cons_buf = 0;

        #pragma unroll
        for (int ks = 0; ks < 4; ks++) {
            uint32_t a[4][4];
            #pragma unroll
            for (int mt = 0; mt < 4; mt++)
                asm volatile("ldmatrix.sync.aligned.m8n8.x4.shared.b16 {%0,%1,%2,%3}, [%4];"
                    : "=r"(a[mt][0]), "=r"(a[mt][1]), "=r"(a[mt][2]), "=r"(a[mt][3])
                    : "r"(ab + a_base[mt] + ks * 32));
            uint32_t b[4][2];
            #pragma unroll
            for (int np = 0; np < 2; np++)
                asm volatile("ldmatrix.sync.aligned.m8n8.x4.shared.b16 {%0,%1,%2,%3}, [%4];"
                    : "=r"(b[np * 2][0]), "=r"(b[np * 2][1]),
                      "=r"(b[np * 2 + 1][0]), "=r"(b[np * 2 + 1][1])
                    : "r"(wb + b_base[np] + ks * 32));
            #pragma unroll
            for (int mt = 0; mt < 4; mt++)
                #pragma unroll
                for (int nt = 0; nt < 4; nt++)
                    asm volatile(
                        "mma.sync.aligned.m16n8k16.row.col.f32.f16.f16.f32 "
                        "{%0,%1,%2,%3}, {%4,%5,%6,%7}, {%8,%9}, {%0,%1,%2,%3};"
                        : "+f"(acc[mt][nt][0]), "+f"(acc[mt][nt][1]),
                          "+f"(acc[mt][nt][2]), "+f"(acc[mt][nt][3])
                        : "r"(a[mt][0]), "r"(a[mt][1]), "r"(a[mt][2]), "r"(a[mt][3]),
                          "r"(b[nt][0]), "r"(b[nt][1]));
        }
    }
#undef LOAD_TILE

    #pragma unroll
    for (int mt = 0; mt < 4; mt++) {
        int r0 = bm + wm * 64 + mt * 16 + (lane >> 2);
        #pragma unroll
        for (int nt = 0; nt < 4; nt++) {
            int c0 = bn + wn * 32 + nt * 8 + (lane & 3) * 2;
            float* p0 = C + (size_t)r0 * N + c0;
            float* p1 = C + (size_t)(r0 + 8) * N + c0;
            if (EPI == 2) {
                atomicAdd(p0 + 0, acc[mt][nt][0]); atomicAdd(p0 + 1, acc[mt][nt][1]);
                atomicAdd(p1 + 0, acc[mt][nt][2]); atomicAdd(p1 + 1, acc[mt][nt][3]);
            } else {
                p0[0] = acc[mt][nt][0]; p0[1] = acc[mt][nt][1];
                p1[0] = acc[mt][nt][2]; p1[1] = acc[mt][nt][3];
            }
        }
    }
}

// ---------------- fp32 SGEMM for small shapes (x_proj, dt_proj) -------------
#define GBM 64
#define GBN 64
#define GBK 16
enum { EPI_NONE = 0, EPI_SOFTPLUS_BIAS = 1 };

template <int EPI, bool ATOMIC>
__global__ void __launch_bounds__(256)
gemm_tn_kernel(const float* __restrict__ A, int lda,
               const float* __restrict__ W, int ldw,
               float* __restrict__ C, int ldc,
               int M, int N, int kchunk,
               const float* __restrict__ bias)
{
    __shared__ float Asm[GBK][GBM + 1];
    __shared__ float Wsm[GBK][GBN + 1];

    int tid = threadIdx.x;
    int bm = blockIdx.y * GBM;
    int bn = blockIdx.x * GBN;
    int kbeg = blockIdx.z * kchunk;
    int kend = kbeg + kchunk;
    int lr = tid >> 2;
    int lk = (tid & 3) << 2;
    int ty = tid >> 4;
    int tx = tid & 15;

    float acc[4][4];
    #pragma unroll
    for (int i = 0; i < 4; i++)
        #pragma unroll
        for (int j = 0; j < 4; j++) acc[i][j] = 0.0f;

    for (int k0 = kbeg; k0 < kend; k0 += GBK) {
        {
            const float4 v = *(const float4*)(A + (size_t)(bm + lr) * lda + k0 + lk);
            Asm[lk + 0][lr] = v.x; Asm[lk + 1][lr] = v.y;
            Asm[lk + 2][lr] = v.z; Asm[lk + 3][lr] = v.w;
        }
        {
            float4 v = make_float4(0.f, 0.f, 0.f, 0.f);
            int row = bn + lr;
            if (row < N) v = *(const float4*)(W + (size_t)row * ldw + k0 + lk);
            Wsm[lk + 0][lr] = v.x; Wsm[lk + 1][lr] = v.y;
            Wsm[lk + 2][lr] = v.z; Wsm[lk + 3][lr] = v.w;
        }
        __syncthreads();
        #pragma unroll
        for (int kk = 0; kk < GBK; kk++) {
            float a[4], b[4];
            #pragma unroll
            for (int i = 0; i < 4; i++) a[i] = Asm[kk][ty * 4 + i];
            #pragma unroll
            for (int j = 0; j < 4; j++) b[j] = Wsm[kk][tx * 4 + j];
            #pragma unroll
            for (int i = 0; i < 4; i++)
                #pragma unroll
                for (int j = 0; j < 4; j++)
                    acc[i][j] = fmaf(a[i], b[j], acc[i][j]);
        }
        __syncthreads();
    }

    #pragma unroll
    for (int i = 0; i < 4; i++) {
        int row = bm + ty * 4 + i;
        #pragma unroll
        for (int j = 0; j < 4; j++) {
            int col = bn + tx * 4 + j;
            if (col < N) {
                float v = acc[i][j];
                if (ATOMIC) {
                    atomicAdd(&C[(size_t)row * ldc + col], v);
                } else {
                    if (EPI == EPI_SOFTPLUS_BIAS) v = softplusf(v + bias[col]);
                    C[(size_t)row * ldc + col] = v;
                }
            }
        }
    }
}

// ---------------- causal depthwise conv (width 4) + silu, 4 t per thread ----
__global__ void conv_silu4_kernel(const float* __restrict__ proj,
                                  const float* __restrict__ cw,
                                  const float* __restrict__ cb,
                                  float* __restrict__ out)
{
    int idx = blockIdx.x * blockDim.x + threadIdx.x;
    if (idx >= (TT / 4) * DI) return;
    int d = idx % DI;
    int t4 = idx / DI;
    int tbase = t4 * 4;
    int lbase = tbase & (LL - 1);     // LL power of 2
    float w0 = cw[d * 4 + 0], w1 = cw[d * 4 + 1], w2 = cw[d * 4 + 2], w3 = cw[d * 4 + 3];
    float bias = cb[d];
    float x[7];
    #pragma unroll
    for (int j = 0; j < 7; j++) {
        int l = lbase - 3 + j;
        x[j] = (l >= 0) ? proj[(size_t)(tbase - 3 + j) * (2 * DI) + d] : 0.0f;
    }
    #pragma unroll
    for (int i = 0; i < 4; i++) {
        float acc = bias;
        acc = fmaf(w0, x[i + 0], acc);
        acc = fmaf(w1, x[i + 1], acc);
        acc = fmaf(w2, x[i + 2], acc);
        acc = fmaf(w3, x[i + 3], acc);
        out[(size_t)(tbase + i) * DI + d] = siluf(acc);
    }
}

// ---------------- chunked selective scan ------------------------------------
// A: per-chunk local scan from 0 -> (prod of a, local final state)
__global__ void scan_a_kernel(const float* __restrict__ dt,
                              const float* __restrict__ hconv,
                              const float* __restrict__ ssm,
                              const float* __restrict__ A_log,
                              float* __restrict__ P,
                              float* __restrict__ S)
{
    int s = threadIdx.x & 15;
    int d = blockIdx.x * 16 + (threadIdx.x >> 4);
    int b = blockIdx.y >> 2;
    int ch = blockIdx.y & 3;
    float Aneg = -__expf(A_log[d * DS + s]);

    const int t0 = b * LL + ch * CHL;
    float state = 0.0f, prod = 1.0f;
    float dtv = dt[(size_t)t0 * DI + d];
    float hv  = hconv[(size_t)t0 * DI + d];
    float Bv  = ssm[(size_t)t0 * 80 + DTR + s];
    for (int l = 0; l < CHL; l++) {
        int tn = t0 + l + ((l + 1 < CHL) ? 1 : 0);
        float n_dtv = dt[(size_t)tn * DI + d];
        float n_hv  = hconv[(size_t)tn * DI + d];
        float n_Bv  = ssm[(size_t)tn * 80 + DTR + s];
        float a = __expf(dtv * Aneg);
        state = fmaf(a, state, dtv * hv * Bv);
        prod *= a;
        dtv = n_dtv; hv = n_hv; Bv = n_Bv;
    }
    int o = ((b * NCH + ch) * DI + d) * DS + s;
    P[o] = prod; S[o] = state;
}

// B: chain carries across chunks (tiny)
__global__ void scan_b_kernel(const float* __restrict__ P,
                              const float* __restrict__ S,
                              float* __restrict__ I)
{
    int idx = blockIdx.x * blockDim.x + threadIdx.x;   // (b,d,s)
    int s = idx & 15;
    int rest = idx >> 4;
    int d = rest % DI;
    int b = rest / DI;
    float init = 0.0f;
    #pragma unroll
    for (int ch = 0; ch < NCH; ch++) {
        int o = ((b * NCH + ch) * DI + d) * DS + s;
        I[o] = init;
        init = fmaf(P[o], init, S[o]);
    }
}

// C: re-run each chunk from its carry, emit y (D-skip + gate silu, fp16x2)
__global__ void scan_c_kernel(const float* __restrict__ dt,
                              const float* __restrict__ hconv,
                              const float* __restrict__ ssm,
                              const float* __restrict__ proj,
                              const float* __restrict__ A_log,
                              const float* __restrict__ D_skip,
                              const float* __restrict__ I,
                              __half* __restrict__ y)
{
    int s = threadIdx.x & 15;
    int d = blockIdx.x * 16 + (threadIdx.x >> 4);
    int b = blockIdx.y >> 2;
    int ch = blockIdx.y & 3;
    float Aneg = -__expf(A_log[d * DS + s]);
    float Dk = D_skip[d];

    const int t0 = b * LL + ch * CHL;
    float state = I[((b * NCH + ch) * DI + d) * DS + s];

    float dtv = dt[(size_t)t0 * DI + d];
    float hv  = hconv[(size_t)t0 * DI + d];
    float Bv  = ssm[(size_t)t0 * 80 + DTR + s];
    float Cv  = ssm[(size_t)t0 * 80 + DTR + DS + s];
    float gv  = proj[(size_t)t0 * (2 * DI) + DI + d];

    for (int l = 0; l < CHL; l++) {
        int t = t0 + l;
        int tn = t + ((l + 1 < CHL) ? 1 : 0);
        float n_dtv = dt[(size_t)tn * DI + d];
        float n_hv  = hconv[(size_t)tn * DI + d];
        float n_Bv  = ssm[(size_t)tn * 80 + DTR + s];
        float n_Cv  = ssm[(size_t)tn * 80 + DTR + DS + s];
        float n_gv  = proj[(size_t)tn * (2 * DI) + DI + d];

        float a = __expf(dtv * Aneg);
        state = fmaf(a, state, dtv * hv * Bv);
        float p = state * Cv;
        p += __shfl_xor_sync(0xffffffffu, p, 8);
        p += __shfl_xor_sync(0xffffffffu, p, 4);
        p += __shfl_xor_sync(0xffffffffu, p, 2);
        p += __shfl_xor_sync(0xffffffffu, p, 1);
        if (s == 0) {
            float val = (p + Dk * hv) * siluf(gv);
            __half hi, lo; split_half(val, hi, lo);
            __half* dst = y + (size_t)t * (2 * DI);
            dst[d] = hi; dst[DI + d] = lo;
        }
        dtv = n_dtv; hv = n_hv; Bv = n_Bv; Cv = n_Cv; gv = n_gv;
    }
}

// ---------------- launcher ----------------
extern "C" void kernel_launch(void* const* d_in, const int* in_sizes, int n_in,
                              void* d_out, int out_size)
{
    const int*   input_ids = (const int*)  d_in[0];
    const float* embed     = (const float*)d_in[1];
    const float* norm_f_w  = (const float*)d_in[2];
    const float* in_proj_w = (const float*)d_in[3];
    const float* conv_w    = (const float*)d_in[4];
    const float* conv_b    = (const float*)d_in[5];
    const float* x_proj_w  = (const float*)d_in[6];
    const float* dt_proj_w = (const float*)d_in[7];
    const float* dt_proj_b = (const float*)d_in[8];
    const float* A_log     = (const float*)d_in[9];
    const float* D_skip    = (const float*)d_in[10];
    const float* out_proj_w= (const float*)d_in[11];
    const float* norm_w    = (const float*)d_in[12];
    float* logits = (float*)d_out;

    float *ph, *pproj, *pconv, *pssm, *pdt, *pP, *pS, *pI;
    __half *pxnh, *pinw, *py, *poutw, *pembh;
    cudaGetSymbolAddress((void**)&ph,    g_h);
    cudaGetSymbolAddress((void**)&pproj, g_proj);
    cudaGetSymbolAddress((void**)&pconv, g_conv);
    cudaGetSymbolAddress((void**)&pssm,  g_ssm);
    cudaGetSymbolAddress((void**)&pdt,   g_dt);
    cudaGetSymbolAddress((void**)&pP,    g_scanP);
    cudaGetSymbolAddress((void**)&pS,    g_scanS);
    cudaGetSymbolAddress((void**)&pI,    g_scanI);
    cudaGetSymbolAddress((void**)&pxnh,  g_xn_half);
    cudaGetSymbolAddress((void**)&pinw,  g_inw_half);
    cudaGetSymbolAddress((void**)&py,    g_y_half);
    cudaGetSymbolAddress((void**)&poutw, g_outw_half);
    cudaGetSymbolAddress((void**)&pembh, g_embed_half);

    cudaFuncSetAttribute((const void*)hmma_gemm_kernel<0>,
                         cudaFuncAttributeMaxDynamicSharedMemorySize, HMMA_SMEM);
    cudaFuncSetAttribute((const void*)hmma_gemm_kernel<2>,
                         cudaFuncAttributeMaxDynamicSharedMemorySize, HMMA_SMEM);

    // bulk weight conversions (single fp16 plane each)
    {
        dim3 ge((DM / 8 + 127) / 128, VOCAB);
        convert1h_w_kernel<<<ge, 128>>>(embed, pembh, DM);
        dim3 gi((DM / 8 + 127) / 128, NL * 2 * DI);
        convert1h_w_kernel<<<gi, 128>>>(in_proj_w, pinw, DM);
        dim3 go((DI / 8 + 127) / 128, NL * DM);
        convert1h_w_kernel<<<go, 128>>>(out_proj_w, poutw, DI);
    }

    // fused embed + layer-0 rmsnorm + zero(pproj, pssm)
    embed_rmsnorm2h_kernel<<<TT, 256>>>(input_ids, embed, norm_w, ph, pxnh,
                                        (float4*)pproj, pssm);

    for (int i = 0; i < NL; i++) {
        const __half* w_in1  = pinw  + (size_t)i * (2 * DI) * DM;
        const __half* w_out1 = poutw + (size_t)i * DM * DI;
        const float* w_cv  = conv_w     + (size_t)i * DI * DCONV;
        const float* b_cv  = conv_b     + (size_t)i * DI;
        const float* w_xp  = x_proj_w   + (size_t)i * (DTR + 2 * DS) * DI;
        const float* w_dtp = dt_proj_w  + (size_t)i * DI * DTR;
        const float* b_dtp = dt_proj_b  + (size_t)i * DI;
        const float* a_log = A_log      + (size_t)i * DI * DS;
        const float* d_sk  = D_skip     + (size_t)i * DI;
        const float* w_nrm = norm_w     + (size_t)i * DM;

        if (i > 0)
            rmsnorm2h_zero_kernel<<<TT, 256>>>(ph, w_nrm, pxnh, (float4*)pproj, pssm);

        // in_proj (fp16x2 A, single-plane W): K'=1536, split-K=3 atomic
        {
            dim3 grid(TT / BM, (2 * DI) / BN, 3);
            hmma_gemm_kernel<2><<<grid, 256, HMMA_SMEM>>>(
                pxnh, w_in1, pproj, 2 * DM, DM, DM, 2 * DI, (2 * DM) / 3);
        }

        // conv + silu (4 t per thread)
        conv_silu4_kernel<<<((TT / 4) * DI + 255) / 256, 256>>>(pproj, w_cv, b_cv, pconv);

        // x_proj: fp32, split-K=6 atomic (pssm zeroed in rmsnorm)
        {
            dim3 grid((80 + GBN - 1) / GBN, TT / GBM, 6);
            gemm_tn_kernel<EPI_NONE, true><<<grid, 256>>>(
                pconv, DI, w_xp, DI, pssm, 80, TT, 80, DI / 6, nullptr);
        }

        // dt_proj + softplus
        {
            dim3 grid(DI / GBN, TT / GBM, 1);
            gemm_tn_kernel<EPI_SOFTPLUS_BIAS, false><<<grid, 256>>>(
                pssm, 80, w_dtp, DTR, pdt, DI, TT, DI, DTR, b_dtp);
        }

        // chunked selective scan (A: local scans; B: carry chain; C: emit y)
        {
            dim3 gac(DI / 16, BB * NCH);
            scan_a_kernel<<<gac, 256>>>(pdt, pconv, pssm, a_log, pP, pS);
            scan_b_kernel<<<(BB * DI * DS) / 256, 256>>>(pP, pS, pI);
            scan_c_kernel<<<gac, 256>>>(pdt, pconv, pssm, pproj, a_log, d_sk, pI, py);
        }

        // out_proj (fp16x2 A, single-plane W): K'=3072, split-K=6 atomic
        {
            dim3 grid(TT / BM, DM / BN, 6);
            hmma_gemm_kernel<2><<<grid, 256, HMMA_SMEM>>>(
                py, w_out1, ph, 2 * DI, DI, DI, DM, (2 * DI) / 6);
        }
    }

    // final rmsnorm -> single fp16 plane
    rmsnorm1h_kernel<<<TT, 256>>>(ph, norm_f_w, pxnh);

    // lm head: pure fp16 single-plane, K=768
    {
        dim3 grid(TT / BM, VOCAB / BN, 1);
        hmma_gemm_kernel<0><<<grid, 256, HMMA_SMEM>>>(
            pxnh, pembh, logits, DM, DM, DM, VOCAB, DM);
    }
}

// round 16
// speedup vs baseline: 5.0163x; 1.0553x over previous
#include <cuda_runtime.h>
#include <cuda_bf16.h>
#include <cuda_fp16.h>
#include <cstdint>
#include <math.h>

// ---------------- problem constants ----------------
#define NL    4
#define DM    768
#define DI    1536
#define DS    16
#define DTR   48
#define DCONV 4
#define VOCAB 32000
#define BB    2
#define LL    512
#define TT    (BB*LL)          // 1024 tokens
#define EPS   1e-5f
#define NCH   8                // scan chunks per sequence
#define CHL   (LL/NCH)         // 64

// ---------------- scratch (static device memory; no allocations) -------------
__device__ float g_h   [TT * DM];            // residual stream (fp32)
__device__ float g_proj[TT * 2 * DI];        // in_proj output (h | gate)
__device__ float g_conv[TT * DI];            // conv + silu output
__device__ float g_ssm [TT * 80];            // x_proj output (dt_raw | B | C)
__device__ float g_dt  [TT * DI];            // softplus(dt)
// chunked-scan intermediates: [b][ch][d][s]
__device__ float g_scanP[BB * NCH * DI * DS];
__device__ float g_scanS[BB * NCH * DI * DS];

// Layer GEMMs: activations fp16 2-plane [hi, lo]; weights single fp16 plane
// (GEMM wraps the W K-index). lm head: both sides single-plane fp16 (K=768).
__device__ __half g_xn_half   [TT * 2 * DM];                   // rmsnorm out
__device__ __half g_inw_half  [(size_t)NL * (2*DI) * DM];      // in_proj_w (1 plane)
__device__ __half g_y_half    [TT * 2 * DI];                   // scan out
__device__ __half g_outw_half [(size_t)NL * DM * DI];          // out_proj_w (1 plane)
__device__ __half g_embed_half[(size_t)VOCAB * DM];            // embed (1 plane)

// ---------------- helpers ----------------
__device__ __forceinline__ uint32_t smem_u32(const void* p) {
    uint32_t a;
    asm("{ .reg .u64 t; cvta.to.shared.u64 t, %1; cvt.u32.u64 %0, t; }" : "=r"(a) : "l"(p));
    return a;
}
__device__ __forceinline__ void cp_async16(uint32_t dst, const void* src) {
    asm volatile("cp.async.cg.shared.global [%0], [%1], 16;" :: "r"(dst), "l"(src));
}
#define CP_COMMIT() asm volatile("cp.async.commit_group;" ::: "memory")
#define CP_WAIT(n)  asm volatile("cp.async.wait_group %0;" :: "n"(n) : "memory")

__device__ __forceinline__ float siluf(float x) { return x / (1.0f + __expf(-x)); }
__device__ __forceinline__ float softplusf(float x) {
    return fmaxf(x, 0.0f) + log1pf(__expf(-fabsf(x)));
}
__device__ __forceinline__ void split_half(float v, __half& hi, __half& lo) {
    hi = __float2half(v);
    lo = __float2half(v - __half2float(hi));
}

// ---------------- fused embed+rmsnorm -> fp16x2 (+ zero pproj & pssm) -------
__global__ void embed_rmsnorm2h_kernel(const int* __restrict__ ids,
                                       const float* __restrict__ embed,
                                       const float* __restrict__ w,
                                       float* __restrict__ hout,
                                       __half* __restrict__ out,
                                       float4* __restrict__ zbuf,
                                       float* __restrict__ zssm) {
    __shared__ float red[256];
    int t = blockIdx.x;
    {
        float4 z = make_float4(0.f, 0.f, 0.f, 0.f);
        float4* zp = zbuf + (size_t)t * 768;
        #pragma unroll
        for (int q = 0; q < 3; q++) zp[threadIdx.x + q * 256] = z;
        if (threadIdx.x < 80) zssm[t * 80 + threadIdx.x] = 0.0f;
    }
    int id = ids[t];
    const float* src = embed + (size_t)id * DM;
    float* hdst = hout + (size_t)t * DM;
    float vals[3];
    float s = 0.0f;
    #pragma unroll
    for (int q = 0; q < 3; q++) {
        int d = threadIdx.x + q * 256;
        float v = src[d];
        vals[q] = v;
        hdst[d] = v;
        s += v * v;
    }
    red[threadIdx.x] = s;
    __syncthreads();
    for (int off = 128; off > 0; off >>= 1) {
        if (threadIdx.x < off) red[threadIdx.x] += red[threadIdx.x + off];
        __syncthreads();
    }
    float scale = rsqrtf(red[0] / (float)DM + EPS);
    __half* dst = out + (size_t)t * (2 * DM);
    #pragma unroll
    for (int q = 0; q < 3; q++) {
        int d = threadIdx.x + q * 256;
        float v = vals[q] * scale * w[d];
        __half hi, lo; split_half(v, hi, lo);
        dst[d] = hi; dst[DM + d] = lo;
    }
}

// ---------------- rmsnorm -> fp16x2 (+ zero pproj & pssm) -------------------
__global__ void rmsnorm2h_zero_kernel(const float* __restrict__ x,
                                      const float* __restrict__ w,
                                      __half* __restrict__ out,
                                      float4* __restrict__ zbuf,
                                      float* __restrict__ zssm) {
    __shared__ float red[256];
    int t = blockIdx.x;
    {
        float4 z = make_float4(0.f, 0.f, 0.f, 0.f);
        float4* zp = zbuf + (size_t)t * 768;
        #pragma unroll
        for (int q = 0; q < 3; q++) zp[threadIdx.x + q * 256] = z;
        if (threadIdx.x < 80) zssm[t * 80 + threadIdx.x] = 0.0f;
    }
    const float* row = x + (size_t)t * DM;
    float vals[3];
    float s = 0.0f;
    #pragma unroll
    for (int q = 0; q < 3; q++) {
        int d = threadIdx.x + q * 256;
        float v = row[d];
        vals[q] = v;
        s += v * v;
    }
    red[threadIdx.x] = s;
    __syncthreads();
    for (int off = 128; off > 0; off >>= 1) {
        if (threadIdx.x < off) red[threadIdx.x] += red[threadIdx.x + off];
        __syncthreads();
    }
    float scale = rsqrtf(red[0] / (float)DM + EPS);
    __half* dst = out + (size_t)t * (2 * DM);
    #pragma unroll
    for (int q = 0; q < 3; q++) {
        int d = threadIdx.x + q * 256;
        float v = vals[q] * scale * w[d];
        __half hi, lo; split_half(v, hi, lo);
        dst[d] = hi; dst[DM + d] = lo;
    }
}

// ---------------- final rmsnorm -> SINGLE fp16 plane [T, DM] ----------------
__global__ void rmsnorm1h_kernel(const float* __restrict__ x,
                                 const float* __restrict__ w,
                                 __half* __restrict__ out) {
    __shared__ float red[256];
    int t = blockIdx.x;
    const float* row = x + (size_t)t * DM;
    float s = 0.0f;
    for (int d = threadIdx.x; d < DM; d += blockDim.x) { float v = row[d]; s += v * v; }
    red[threadIdx.x] = s;
    __syncthreads();
    for (int off = 128; off > 0; off >>= 1) {
        if (threadIdx.x < off) red[threadIdx.x] += red[threadIdx.x + off];
        __syncthreads();
    }
    float scale = rsqrtf(red[0] / (float)DM + EPS);
    __half* dst = out + (size_t)t * DM;
    for (int d = threadIdx.x; d < DM; d += blockDim.x) {
        float v = row[d] * scale * w[d];
        dst[d] = __float2half(v);
    }
}

// ---------------- fp32 [R,C] -> fp16 single plane (1 row/thread-chunk) ------
__global__ void convert1h_w_kernel(const float* __restrict__ src,
                                   __half* __restrict__ dst,
                                   int C) {
    int c8 = blockIdx.x * blockDim.x + threadIdx.x;
    int C8 = C >> 3;
    if (c8 >= C8) return;
    int r = blockIdx.y;
    const float* s = src + (size_t)r * C + c8 * 8;
    float4 v0 = *(const float4*)(s);
    float4 v1 = *(const float4*)(s + 4);
    uint4 hv;
    ((__half2*)&hv)[0] = __halves2half2(__float2half(v0.x), __float2half(v0.y));
    ((__half2*)&hv)[1] = __halves2half2(__float2half(v0.z), __float2half(v0.w));
    ((__half2*)&hv)[2] = __halves2half2(__float2half(v1.x), __float2half(v1.y));
    ((__half2*)&hv)[3] = __halves2half2(__float2half(v1.z), __float2half(v1.w));
    *(uint4*)(dst + (size_t)r * C + c8 * 8) = hv;
}

// =============================================================================
// HMMA fp16 GEMM (unchanged)
// =============================================================================
#define BM 128
#define BN 128
#define BK 64
#define SSTR 72
#define NSTAGE 3
#define STAGE_ELEMS (BM * SSTR)
#define STAGE_BYTES (STAGE_ELEMS * 2)
#define HMMA_SMEM (NSTAGE * 2 * STAGE_BYTES)

template <int EPI>   // EPI: 0 store, 2 atomicAdd (split-K)
__global__ void __launch_bounds__(256, 2)
hmma_gemm_kernel(const __half* __restrict__ A,
                 const __half* __restrict__ W,
                 float* __restrict__ C, int lda, int ldw, int Cw,
                 int N, int kchunk)
{
    extern __shared__ char dsm_raw[];
    __half* dsm = (__half*)dsm_raw;

    const int tid = threadIdx.x;
    const int lane = tid & 31;
    const int wid = tid >> 5;
    const int wm = wid >> 2;
    const int wn = wid & 3;
    const int bm = blockIdx.x * BM;
    const int bn = blockIdx.y * BN;
    const int kbeg = blockIdx.z * kchunk;

    const uint32_t sA = smem_u32(dsm);
    const uint32_t sW = sA + NSTAGE * STAGE_BYTES;

    const int ar0 = tid >> 3;
    const int ak0 = (tid & 7) * 8;
    const __half* Ag = A + (size_t)bm * lda + kbeg + ak0;
    const __half* Wg = W + (size_t)bn * ldw + ak0;
    uint32_t stoff[4];
    const __half *Agp[4], *Wgp[4];
    #pragma unroll
    for (int q = 0; q < 4; q++) {
        int row = ar0 + q * 32;
        stoff[q] = (uint32_t)(row * SSTR + ak0) * 2;
        Agp[q] = Ag + (size_t)row * lda;
        Wgp[q] = Wg + (size_t)row * ldw;
    }

    uint32_t a_base[4], b_base[2];
    {
        const int grp = lane >> 3, wi = lane & 7;
        #pragma unroll
        for (int mt = 0; mt < 4; mt++) {
            int row = wm * 64 + mt * 16 + (lane & 15);
            int col = (lane >> 4) * 8;
            a_base[mt] = (uint32_t)(row * SSTR + col) * 2;
        }
        #pragma unroll
        for (int np = 0; np < 2; np++) {
            int row = wn * 32 + np * 16 + (grp >> 1) * 8 + wi;
            int col = (grp & 1) * 8;
            b_base[np] = (uint32_t)(row * SSTR + col) * 2;
        }
    }

    float acc[4][4][4];
    #pragma unroll
    for (int i = 0; i < 4; i++)
        #pragma unroll
        for (int j = 0; j < 4; j++)
            #pragma unroll
            for (int k = 0; k < 4; k++) acc[i][j][k] = 0.0f;

#define LOAD_TILE(buf, k0) do { \
    uint32_t ab_ = sA + (buf) * STAGE_BYTES; \
    uint32_t wb_ = sW + (buf) * STAGE_BYTES; \
    int wk_ = kbeg + (k0); \
    while (wk_ >= Cw) wk_ -= Cw; \
    _Pragma("unroll") \
    for (int q = 0; q < 4; q++) { \
        cp_async16(ab_ + stoff[q], Agp[q] + (k0)); \
        cp_async16(wb_ + stoff[q], Wgp[q] + wk_); \
    } \
} while (0)

    const int nc = kchunk / BK;
    LOAD_TILE(0, 0); CP_COMMIT();
    LOAD_TILE(1, BK); CP_COMMIT();

    int load_buf = 2;
    int cons_buf = 0;

    for (int c = 0; c < nc; c++) {
        CP_WAIT(1);
        __syncthreads();
        int nf = c + 2;
        if (nf < nc) LOAD_TILE(load_buf, nf * BK);
        CP_COMMIT();
        if (++load_buf == NSTAGE) load_buf = 0;

        const uint32_t ab = sA + cons_buf * STAGE_BYTES;
        const uint32_t wb = sW + cons_buf * STAGE_BYTES;
        if (++cons_buf == NSTAGE) cons_buf = 0;

        #pragma unroll
        for (int ks = 0; ks < 4; ks++) {
            uint32_t a[4][4];
            #pragma unroll
            for (int mt = 0; mt < 4; mt++)
                asm volatile("ldmatrix.sync.aligned.m8n8.x4.shared.b16 {%0,%1,%2,%3}, [%4];"
                    : "=r"(a[mt][0]), "=r"(a[mt][1]), "=r"(a[mt][2]), "=r"(a[mt][3])
                    : "r"(ab + a_base[mt] + ks * 32));
            uint32_t b[4][2];
            #pragma unroll
            for (int np = 0; np < 2; np++)
                asm volatile("ldmatrix.sync.aligned.m8n8.x4.shared.b16 {%0,%1,%2,%3}, [%4];"
                    : "=r"(b[np * 2][0]), "=r"(b[np * 2][1]),
                      "=r"(b[np * 2 + 1][0]), "=r"(b[np * 2 + 1][1])
                    : "r"(wb + b_base[np] + ks * 32));
            #pragma unroll
            for (int mt = 0; mt < 4; mt++)
                #pragma unroll
                for (int nt = 0; nt < 4; nt++)
                    asm volatile(
                        "mma.sync.aligned.m16n8k16.row.col.f32.f16.f16.f32 "
                        "{%0,%1,%2,%3}, {%4,%5,%6,%7}, {%8,%9}, {%0,%1,%2,%3};"
                        : "+f"(acc[mt][nt][0]), "+f"(acc[mt][nt][1]),
                          "+f"(acc[mt][nt][2]), "+f"(acc[mt][nt][3])
                        : "r"(a[mt][0]), "r"(a[mt][1]), "r"(a[mt][2]), "r"(a[mt][3]),
                          "r"(b[nt][0]), "r"(b[nt][1]));
        }
    }
#undef LOAD_TILE

    #pragma unroll
    for (int mt = 0; mt < 4; mt++) {
        int r0 = bm + wm * 64 + mt * 16 + (lane >> 2);
        #pragma unroll
        for (int nt = 0; nt < 4; nt++) {
            int c0 = bn + wn * 32 + nt * 8 + (lane & 3) * 2;
            float* p0 = C + (size_t)r0 * N + c0;
            float* p1 = C + (size_t)(r0 + 8) * N + c0;
            if (EPI == 2) {
                atomicAdd(p0 + 0, acc[mt][nt][0]); atomicAdd(p0 + 1, acc[mt][nt][1]);
                atomicAdd(p1 + 0, acc[mt][nt][2]); atomicAdd(p1 + 1, acc[mt][nt][3]);
            } else {
                p0[0] = acc[mt][nt][0]; p0[1] = acc[mt][nt][1];
                p1[0] = acc[mt][nt][2]; p1[1] = acc[mt][nt][3];
            }
        }
    }
}

// ---------------- fp32 SGEMM for small shapes (x_proj, dt_proj) -------------
#define GBM 64
#define GBN 64
#define GBK 16
enum { EPI_NONE = 0, EPI_SOFTPLUS_BIAS = 1 };

template <int EPI, bool ATOMIC>
__global__ void __launch_bounds__(256)
gemm_tn_kernel(const float* __restrict__ A, int lda,
               const float* __restrict__ W, int ldw,
               float* __restrict__ C, int ldc,
               int M, int N, int kchunk,
               const float* __restrict__ bias)
{
    __shared__ float Asm[GBK][GBM + 1];
    __shared__ float Wsm[GBK][GBN + 1];

    int tid = threadIdx.x;
    int bm = blockIdx.y * GBM;
    int bn = blockIdx.x * GBN;
    int kbeg = blockIdx.z * kchunk;
    int kend = kbeg + kchunk;
    int lr = tid >> 2;
    int lk = (tid & 3) << 2;
    int ty = tid >> 4;
    int tx = tid & 15;

    float acc[4][4];
    #pragma unroll
    for (int i = 0; i < 4; i++)
        #pragma unroll
        for (int j = 0; j < 4; j++) acc[i][j] = 0.0f;

    for (int k0 = kbeg; k0 < kend; k0 += GBK) {
        {
            const float4 v = *(const float4*)(A + (size_t)(bm + lr) * lda + k0 + lk);
            Asm[lk + 0][lr] = v.x; Asm[lk + 1][lr] = v.y;
            Asm[lk + 2][lr] = v.z; Asm[lk + 3][lr] = v.w;
        }
        {
            float4 v = make_float4(0.f, 0.f, 0.f, 0.f);
            int row = bn + lr;
            if (row < N) v = *(const float4*)(W + (size_t)row * ldw + k0 + lk);
            Wsm[lk + 0][lr] = v.x; Wsm[lk + 1][lr] = v.y;
            Wsm[lk + 2][lr] = v.z; Wsm[lk + 3][lr] = v.w;
        }
        __syncthreads();
        #pragma unroll
        for (int kk = 0; kk < GBK; kk++) {
            float a[4], b[4];
            #pragma unroll
            for (int i = 0; i < 4; i++) a[i] = Asm[kk][ty * 4 + i];
            #pragma unroll
            for (int j = 0; j < 4; j++) b[j] = Wsm[kk][tx * 4 + j];
            #pragma unroll
            for (int i = 0; i < 4; i++)
                #pragma unroll
                for (int j = 0; j < 4; j++)
                    acc[i][j] = fmaf(a[i], b[j], acc[i][j]);
        }
        __syncthreads();
    }

    #pragma unroll
    for (int i = 0; i < 4; i++) {
        int row = bm + ty * 4 + i;
        #pragma unroll
        for (int j = 0; j < 4; j++) {
            int col = bn + tx * 4 + j;
            if (col < N) {
                float v = acc[i][j];
                if (ATOMIC) {
                    atomicAdd(&C[(size_t)row * ldc + col], v);
                } else {
                    if (EPI == EPI_SOFTPLUS_BIAS) v = softplusf(v + bias[col]);
                    C[(size_t)row * ldc + col] = v;
                }
            }
        }
    }
}

// ---------------- causal depthwise conv (width 4) + silu, 4 t per thread ----
__global__ void conv_silu4_kernel(const float* __restrict__ proj,
                                  const float* __restrict__ cw,
                                  const float* __restrict__ cb,
                                  float* __restrict__ out)
{
    int idx = blockIdx.x * blockDim.x + threadIdx.x;
    if (idx >= (TT / 4) * DI) return;
    int d = idx % DI;
    int t4 = idx / DI;
    int tbase = t4 * 4;
    int lbase = tbase & (LL - 1);
    float w0 = cw[d * 4 + 0], w1 = cw[d * 4 + 1], w2 = cw[d * 4 + 2], w3 = cw[d * 4 + 3];
    float bias = cb[d];
    float x[7];
    #pragma unroll
    for (int j = 0; j < 7; j++) {
        int l = lbase - 3 + j;
        x[j] = (l >= 0) ? proj[(size_t)(tbase - 3 + j) * (2 * DI) + d] : 0.0f;
    }
    #pragma unroll
    for (int i = 0; i < 4; i++) {
        float acc = bias;
        acc = fmaf(w0, x[i + 0], acc);
        acc = fmaf(w1, x[i + 1], acc);
        acc = fmaf(w2, x[i + 2], acc);
        acc = fmaf(w3, x[i + 3], acc);
        out[(size_t)(tbase + i) * DI + d] = siluf(acc);
    }
}

// ---------------- chunked selective scan ------------------------------------
// A: per-chunk local scan from 0 -> (prod of a, local final state)
__global__ void scan_a_kernel(const float* __restrict__ dt,
                              const float* __restrict__ hconv,
                              const float* __restrict__ ssm,
                              const float* __restrict__ A_log,
                              float* __restrict__ P,
                              float* __restrict__ S)
{
    int s = threadIdx.x & 15;
    int d = blockIdx.x * 16 + (threadIdx.x >> 4);
    int b = blockIdx.y >> 3;
    int ch = blockIdx.y & 7;
    float Aneg = -__expf(A_log[d * DS + s]);

    const int t0 = b * LL + ch * CHL;
    float state = 0.0f, prod = 1.0f;
    float dtv = dt[(size_t)t0 * DI + d];
    float hv  = hconv[(size_t)t0 * DI + d];
    float Bv  = ssm[(size_t)t0 * 80 + DTR + s];
    for (int l = 0; l < CHL; l++) {
        int tn = t0 + l + ((l + 1 < CHL) ? 1 : 0);
        float n_dtv = dt[(size_t)tn * DI + d];
        float n_hv  = hconv[(size_t)tn * DI + d];
        float n_Bv  = ssm[(size_t)tn * 80 + DTR + s];
        float a = __expf(dtv * Aneg);
        state = fmaf(a, state, dtv * hv * Bv);
        prod *= a;
        dtv = n_dtv; hv = n_hv; Bv = n_Bv;
    }
    int o = ((b * NCH + ch) * DI + d) * DS + s;
    P[o] = prod; S[o] = state;
}

// C: compute carry inline from preceding chunks' (P,S), re-run chunk, emit y
__global__ void scan_c_kernel(const float* __restrict__ dt,
                              const float* __restrict__ hconv,
                              const float* __restrict__ ssm,
                              const float* __restrict__ proj,
                              const float* __restrict__ A_log,
                              const float* __restrict__ D_skip,
                              const float* __restrict__ P,
                              const float* __restrict__ S,
                              __half* __restrict__ y)
{
    int s = threadIdx.x & 15;
    int d = blockIdx.x * 16 + (threadIdx.x >> 4);
    int b = blockIdx.y >> 3;
    int ch = blockIdx.y & 7;
    float Aneg = -__expf(A_log[d * DS + s]);
    float Dk = D_skip[d];

    // carry after chunks 0..ch-1:  init_{j+1} = P_j * init_j + S_j
    float state = 0.0f;
    for (int j = 0; j < ch; j++) {
        int o = ((b * NCH + j) * DI + d) * DS + s;
        state = fmaf(P[o], state, S[o]);
    }

    const int t0 = b * LL + ch * CHL;
    float dtv = dt[(size_t)t0 * DI + d];
    float hv  = hconv[(size_t)t0 * DI + d];
    float Bv  = ssm[(size_t)t0 * 80 + DTR + s];
    float Cv  = ssm[(size_t)t0 * 80 + DTR + DS + s];
    float gv  = proj[(size_t)t0 * (2 * DI) + DI + d];

    for (int l = 0; l < CHL; l++) {
        int t = t0 + l;
        int tn = t + ((l + 1 < CHL) ? 1 : 0);
        float n_dtv = dt[(size_t)tn * DI + d];
        float n_hv  = hconv[(size_t)tn * DI + d];
        float n_Bv  = ssm[(size_t)tn * 80 + DTR + s];
        float n_Cv  = ssm[(size_t)tn * 80 + DTR + DS + s];
        float n_gv  = proj[(size_t)tn * (2 * DI) + DI + d];

        float a = __expf(dtv * Aneg);
        state = fmaf(a, state, dtv * hv * Bv);
        float p = state * Cv;
        p += __shfl_xor_sync(0xffffffffu, p, 8);
        p += __shfl_xor_sync(0xffffffffu, p, 4);
        p += __shfl_xor_sync(0xffffffffu, p, 2);
        p += __shfl_xor_sync(0xffffffffu, p, 1);
        if (s == 0) {
            float val = (p + Dk * hv) * siluf(gv);
            __half hi, lo; split_half(val, hi, lo);
            __half* dst = y + (size_t)t * (2 * DI);
            dst[d] = hi; dst[DI + d] = lo;
        }
        dtv = n_dtv; hv = n_hv; Bv = n_Bv; Cv = n_Cv; gv = n_gv;
    }
}

// ---------------- launcher ----------------
extern "C" void kernel_launch(void* const* d_in, const int* in_sizes, int n_in,
                              void* d_out, int out_size)
{
    const int*   input_ids = (const int*)  d_in[0];
    const float* embed     = (const float*)d_in[1];
    const float* norm_f_w  = (const float*)d_in[2];
    const float* in_proj_w = (const float*)d_in[3];
    const float* conv_w    = (const float*)d_in[4];
    const float* conv_b    = (const float*)d_in[5];
    const float* x_proj_w  = (const float*)d_in[6];
    const float* dt_proj_w = (const float*)d_in[7];
    const float* dt_proj_b = (const float*)d_in[8];
    const float* A_log     = (const float*)d_in[9];
    const float* D_skip    = (const float*)d_in[10];
    const float* out_proj_w= (const float*)d_in[11];
    const float* norm_w    = (const float*)d_in[12];
    float* logits = (float*)d_out;

    float *ph, *pproj, *pconv, *pssm, *pdt, *pP, *pS;
    __half *pxnh, *pinw, *py, *poutw, *pembh;
    cudaGetSymbolAddress((void**)&ph,    g_h);
    cudaGetSymbolAddress((void**)&pproj, g_proj);
    cudaGetSymbolAddress((void**)&pconv, g_conv);
    cudaGetSymbolAddress((void**)&pssm,  g_ssm);
    cudaGetSymbolAddress((void**)&pdt,   g_dt);
    cudaGetSymbolAddress((void**)&pP,    g_scanP);
    cudaGetSymbolAddress((void**)&pS,    g_scanS);
    cudaGetSymbolAddress((void**)&pxnh,  g_xn_half);
    cudaGetSymbolAddress((void**)&pinw,  g_inw_half);
    cudaGetSymbolAddress((void**)&py,    g_y_half);
    cudaGetSymbolAddress((void**)&poutw, g_outw_half);
    cudaGetSymbolAddress((void**)&pembh, g_embed_half);

    cudaFuncSetAttribute((const void*)hmma_gemm_kernel<0>,
                         cudaFuncAttributeMaxDynamicSharedMemorySize, HMMA_SMEM);
    cudaFuncSetAttribute((const void*)hmma_gemm_kernel<2>,
                         cudaFuncAttributeMaxDynamicSharedMemorySize, HMMA_SMEM);

    // bulk weight conversions (single fp16 plane each)
    {
        dim3 ge((DM / 8 + 127) / 128, VOCAB);
        convert1h_w_kernel<<<ge, 128>>>(embed, pembh, DM);
        dim3 gi((DM / 8 + 127) / 128, NL * 2 * DI);
        convert1h_w_kernel<<<gi, 128>>>(in_proj_w, pinw, DM);
        dim3 go((DI / 8 + 127) / 128, NL * DM);
        convert1h_w_kernel<<<go, 128>>>(out_proj_w, poutw, DI);
    }

    // fused embed + layer-0 rmsnorm + zero(pproj, pssm)
    embed_rmsnorm2h_kernel<<<TT, 256>>>(input_ids, embed, norm_w, ph, pxnh,
                                        (float4*)pproj, pssm);

    for (int i = 0; i < NL; i++) {
        const __half* w_in1  = pinw  + (size_t)i * (2 * DI) * DM;
        const __half* w_out1 = poutw + (size_t)i * DM * DI;
        const float* w_cv  = conv_w     + (size_t)i * DI * DCONV;
        const float* b_cv  = conv_b     + (size_t)i * DI;
        const float* w_xp  = x_proj_w   + (size_t)i * (DTR + 2 * DS) * DI;
        const float* w_dtp = dt_proj_w  + (size_t)i * DI * DTR;
        const float* b_dtp = dt_proj_b  + (size_t)i * DI;
        const float* a_log = A_log      + (size_t)i * DI * DS;
        const float* d_sk  = D_skip     + (size_t)i * DI;
        const float* w_nrm = norm_w     + (size_t)i * DM;

        if (i > 0)
            rmsnorm2h_zero_kernel<<<TT, 256>>>(ph, w_nrm, pxnh, (float4*)pproj, pssm);

        // in_proj (fp16x2 A, single-plane W): K'=1536, split-K=3 atomic
        {
            dim3 grid(TT / BM, (2 * DI) / BN, 3);
            hmma_gemm_kernel<2><<<grid, 256, HMMA_SMEM>>>(
                pxnh, w_in1, pproj, 2 * DM, DM, DM, 2 * DI, (2 * DM) / 3);
        }

        // conv + silu (4 t per thread)
        conv_silu4_kernel<<<((TT / 4) * DI + 255) / 256, 256>>>(pproj, w_cv, b_cv, pconv);

        // x_proj: fp32, split-K=6 atomic
        {
            dim3 grid((80 + GBN - 1) / GBN, TT / GBM, 6);
            gemm_tn_kernel<EPI_NONE, true><<<grid, 256>>>(
                pconv, DI, w_xp, DI, pssm, 80, TT, 80, DI / 6, nullptr);
        }

        // dt_proj + softplus
        {
            dim3 grid(DI / GBN, TT / GBM, 1);
            gemm_tn_kernel<EPI_SOFTPLUS_BIAS, false><<<grid, 256>>>(
                pssm, 80, w_dtp, DTR, pdt, DI, TT, DI, DTR, b_dtp);
        }

        // chunked selective scan (A: local scans; C: carry inline + emit y)
        {
            dim3 gac(DI / 16, BB * NCH);
            scan_a_kernel<<<gac, 256>>>(pdt, pconv, pssm, a_log, pP, pS);
            scan_c_kernel<<<gac, 256>>>(pdt, pconv, pssm, pproj, a_log, d_sk, pP, pS, py);
        }

        // out_proj (fp16x2 A, single-plane W): K'=3072, split-K=6 atomic
        {
            dim3 grid(TT / BM, DM / BN, 6);
            hmma_gemm_kernel<2><<<grid, 256, HMMA_SMEM>>>(
                py, w_out1, ph, 2 * DI, DI, DI, DM, (2 * DI) / 6);
        }
    }

    // final rmsnorm -> single fp16 plane
    rmsnorm1h_kernel<<<TT, 256>>>(ph, norm_f_w, pxnh);

    // lm head: pure fp16 single-plane, K=768
    {
        dim3 grid(TT / BM, VOCAB / BN, 1);
        hmma_gemm_kernel<0><<<grid, 256, HMMA_SMEM>>>(
            pxnh, pembh, logits, DM, DM, DM, VOCAB, DM);
    }
}

// round 17
// speedup vs baseline: 5.2782x; 1.0522x over previous
#include <cuda_runtime.h>
#include <cuda_bf16.h>
#include <cuda_fp16.h>
#include <cstdint>
#include <math.h>

// ---------------- problem constants ----------------
#define NL    4
#define DM    768
#define DI    1536
#define DS    16
#define DTR   48
#define DCONV 4
#define VOCAB 32000
#define BB    2
#define LL    512
#define TT    (BB*LL)          // 1024 tokens
#define EPS   1e-5f
#define NCH   16               // scan chunks per sequence
#define CHL   (LL/NCH)         // 32

// ---------------- scratch (static device memory; no allocations) -------------
__device__ float g_h   [TT * DM];            // residual stream (fp32)
__device__ float g_proj[TT * 2 * DI];        // in_proj output (h | gate)
__device__ float g_conv[TT * DI];            // conv + silu output
__device__ float g_ssm [TT * 80];            // x_proj output (dt_raw | B | C)
__device__ float g_dt  [TT * DI];            // softplus(dt)
// chunked-scan intermediates: [b][ch][d][s]
__device__ float g_scanP[BB * NCH * DI * DS];
__device__ float g_scanS[BB * NCH * DI * DS];

// Layer GEMMs: activations fp16 2-plane [hi, lo]; weights single fp16 plane
// (GEMM wraps the W K-index). lm head: both sides single-plane fp16 (K=768).
__device__ __half g_xn_half   [TT * 2 * DM];                   // rmsnorm out
__device__ __half g_inw_half  [(size_t)NL * (2*DI) * DM];      // in_proj_w (1 plane)
__device__ __half g_y_half    [TT * 2 * DI];                   // scan out
__device__ __half g_outw_half [(size_t)NL * DM * DI];          // out_proj_w (1 plane)
__device__ __half g_embed_half[(size_t)VOCAB * DM];            // embed (1 plane)

// ---------------- helpers ----------------
__device__ __forceinline__ uint32_t smem_u32(const void* p) {
    uint32_t a;
    asm("{ .reg .u64 t; cvta.to.shared.u64 t, %1; cvt.u32.u64 %0, t; }" : "=r"(a) : "l"(p));
    return a;
}
__device__ __forceinline__ void cp_async16(uint32_t dst, const void* src) {
    asm volatile("cp.async.cg.shared.global [%0], [%1], 16;" :: "r"(dst), "l"(src));
}
#define CP_COMMIT() asm volatile("cp.async.commit_group;" ::: "memory")
#define CP_WAIT(n)  asm volatile("cp.async.wait_group %0;" :: "n"(n) : "memory")

__device__ __forceinline__ float siluf(float x) { return x / (1.0f + __expf(-x)); }
__device__ __forceinline__ float softplusf(float x) {
    return fmaxf(x, 0.0f) + log1pf(__expf(-fabsf(x)));
}
__device__ __forceinline__ void split_half(float v, __half& hi, __half& lo) {
    hi = __float2half(v);
    lo = __float2half(v - __half2float(hi));
}

// ---------------- fused embed+rmsnorm -> fp16x2 (+ zero pproj & pssm) -------
__global__ void embed_rmsnorm2h_kernel(const int* __restrict__ ids,
                                       const float* __restrict__ embed,
                                       const float* __restrict__ w,
                                       float* __restrict__ hout,
                                       __half* __restrict__ out,
                                       float4* __restrict__ zbuf,
                                       float* __restrict__ zssm) {
    __shared__ float red[256];
    int t = blockIdx.x;
    {
        float4 z = make_float4(0.f, 0.f, 0.f, 0.f);
        float4* zp = zbuf + (size_t)t * 768;
        #pragma unroll
        for (int q = 0; q < 3; q++) zp[threadIdx.x + q * 256] = z;
        if (threadIdx.x < 80) zssm[t * 80 + threadIdx.x] = 0.0f;
    }
    int id = ids[t];
    const float* src = embed + (size_t)id * DM;
    float* hdst = hout + (size_t)t * DM;
    float vals[3];
    float s = 0.0f;
    #pragma unroll
    for (int q = 0; q < 3; q++) {
        int d = threadIdx.x + q * 256;
        float v = src[d];
        vals[q] = v;
        hdst[d] = v;
        s += v * v;
    }
    red[threadIdx.x] = s;
    __syncthreads();
    for (int off = 128; off > 0; off >>= 1) {
        if (threadIdx.x < off) red[threadIdx.x] += red[threadIdx.x + off];
        __syncthreads();
    }
    float scale = rsqrtf(red[0] / (float)DM + EPS);
    __half* dst = out + (size_t)t * (2 * DM);
    #pragma unroll
    for (int q = 0; q < 3; q++) {
        int d = threadIdx.x + q * 256;
        float v = vals[q] * scale * w[d];
        __half hi, lo; split_half(v, hi, lo);
        dst[d] = hi; dst[DM + d] = lo;
    }
}

// ---------------- rmsnorm -> fp16x2 (+ zero pproj & pssm) -------------------
__global__ void rmsnorm2h_zero_kernel(const float* __restrict__ x,
                                      const float* __restrict__ w,
                                      __half* __restrict__ out,
                                      float4* __restrict__ zbuf,
                                      float* __restrict__ zssm) {
    __shared__ float red[256];
    int t = blockIdx.x;
    {
        float4 z = make_float4(0.f, 0.f, 0.f, 0.f);
        float4* zp = zbuf + (size_t)t * 768;
        #pragma unroll
        for (int q = 0; q < 3; q++) zp[threadIdx.x + q * 256] = z;
        if (threadIdx.x < 80) zssm[t * 80 + threadIdx.x] = 0.0f;
    }
    const float* row = x + (size_t)t * DM;
    float vals[3];
    float s = 0.0f;
    #pragma unroll
    for (int q = 0; q < 3; q++) {
        int d = threadIdx.x + q * 256;
        float v = row[d];
        vals[q] = v;
        s += v * v;
    }
    red[threadIdx.x] = s;
    __syncthreads();
    for (int off = 128; off > 0; off >>= 1) {
        if (threadIdx.x < off) red[threadIdx.x] += red[threadIdx.x + off];
        __syncthreads();
    }
    float scale = rsqrtf(red[0] / (float)DM + EPS);
    __half* dst = out + (size_t)t * (2 * DM);
    #pragma unroll
    for (int q = 0; q < 3; q++) {
        int d = threadIdx.x + q * 256;
        float v = vals[q] * scale * w[d];
        __half hi, lo; split_half(v, hi, lo);
        dst[d] = hi; dst[DM + d] = lo;
    }
}

// ---------------- final rmsnorm -> SINGLE fp16 plane [T, DM] ----------------
__global__ void rmsnorm1h_kernel(const float* __restrict__ x,
                                 const float* __restrict__ w,
                                 __half* __restrict__ out) {
    __shared__ float red[256];
    int t = blockIdx.x;
    const float* row = x + (size_t)t * DM;
    float s = 0.0f;
    for (int d = threadIdx.x; d < DM; d += blockDim.x) { float v = row[d]; s += v * v; }
    red[threadIdx.x] = s;
    __syncthreads();
    for (int off = 128; off > 0; off >>= 1) {
        if (threadIdx.x < off) red[threadIdx.x] += red[threadIdx.x + off];
        __syncthreads();
    }
    float scale = rsqrtf(red[0] / (float)DM + EPS);
    __half* dst = out + (size_t)t * DM;
    for (int d = threadIdx.x; d < DM; d += blockDim.x) {
        float v = row[d] * scale * w[d];
        dst[d] = __float2half(v);
    }
}

// ---------------- fp32 [R,C] -> fp16 single plane (1 row/thread-chunk) ------
__global__ void convert1h_w_kernel(const float* __restrict__ src,
                                   __half* __restrict__ dst,
                                   int C) {
    int c8 = blockIdx.x * blockDim.x + threadIdx.x;
    int C8 = C >> 3;
    if (c8 >= C8) return;
    int r = blockIdx.y;
    const float* s = src + (size_t)r * C + c8 * 8;
    float4 v0 = *(const float4*)(s);
    float4 v1 = *(const float4*)(s + 4);
    uint4 hv;
    ((__half2*)&hv)[0] = __halves2half2(__float2half(v0.x), __float2half(v0.y));
    ((__half2*)&hv)[1] = __halves2half2(__float2half(v0.z), __float2half(v0.w));
    ((__half2*)&hv)[2] = __halves2half2(__float2half(v1.x), __float2half(v1.y));
    ((__half2*)&hv)[3] = __halves2half2(__float2half(v1.z), __float2half(v1.w));
    *(uint4*)(dst + (size_t)r * C + c8 * 8) = hv;
}

// =============================================================================
// HMMA fp16 GEMM (unchanged)
// =============================================================================
#define BM 128
#define BN 128
#define BK 64
#define SSTR 72
#define NSTAGE 3
#define STAGE_ELEMS (BM * SSTR)
#define STAGE_BYTES (STAGE_ELEMS * 2)
#define HMMA_SMEM (NSTAGE * 2 * STAGE_BYTES)

template <int EPI>   // EPI: 0 store, 2 atomicAdd (split-K)
__global__ void __launch_bounds__(256, 2)
hmma_gemm_kernel(const __half* __restrict__ A,
                 const __half* __restrict__ W,
                 float* __restrict__ C, int lda, int ldw, int Cw,
                 int N, int kchunk)
{
    extern __shared__ char dsm_raw[];
    __half* dsm = (__half*)dsm_raw;

    const int tid = threadIdx.x;
    const int lane = tid & 31;
    const int wid = tid >> 5;
    const int wm = wid >> 2;
    const int wn = wid & 3;
    const int bm = blockIdx.x * BM;
    const int bn = blockIdx.y * BN;
    const int kbeg = blockIdx.z * kchunk;

    const uint32_t sA = smem_u32(dsm);
    const uint32_t sW = sA + NSTAGE * STAGE_BYTES;

    const int ar0 = tid >> 3;
    const int ak0 = (tid & 7) * 8;
    const __half* Ag = A + (size_t)bm * lda + kbeg + ak0;
    const __half* Wg = W + (size_t)bn * ldw + ak0;
    uint32_t stoff[4];
    const __half *Agp[4], *Wgp[4];
    #pragma unroll
    for (int q = 0; q < 4; q++) {
        int row = ar0 + q * 32;
        stoff[q] = (uint32_t)(row * SSTR + ak0) * 2;
        Agp[q] = Ag + (size_t)row * lda;
        Wgp[q] = Wg + (size_t)row * ldw;
    }

    uint32_t a_base[4], b_base[2];
    {
        const int grp = lane >> 3, wi = lane & 7;
        #pragma unroll
        for (int mt = 0; mt < 4; mt++) {
            int row = wm * 64 + mt * 16 + (lane & 15);
            int col = (lane >> 4) * 8;
            a_base[mt] = (uint32_t)(row * SSTR + col) * 2;
        }
        #pragma unroll
        for (int np = 0; np < 2; np++) {
            int row = wn * 32 + np * 16 + (grp >> 1) * 8 + wi;
            int col = (grp & 1) * 8;
            b_base[np] = (uint32_t)(row * SSTR + col) * 2;
        }
    }

    float acc[4][4][4];
    #pragma unroll
    for (int i = 0; i < 4; i++)
        #pragma unroll
        for (int j = 0; j < 4; j++)
            #pragma unroll
            for (int k = 0; k < 4; k++) acc[i][j][k] = 0.0f;

#define LOAD_TILE(buf, k0) do { \
    uint32_t ab_ = sA + (buf) * STAGE_BYTES; \
    uint32_t wb_ = sW + (buf) * STAGE_BYTES; \
    int wk_ = kbeg + (k0); \
    while (wk_ >= Cw) wk_ -= Cw; \
    _Pragma("unroll") \
    for (int q = 0; q < 4; q++) { \
        cp_async16(ab_ + stoff[q], Agp[q] + (k0)); \
        cp_async16(wb_ + stoff[q], Wgp[q] + wk_); \
    } \
} while (0)

    const int nc = kchunk / BK;
    LOAD_TILE(0, 0); CP_COMMIT();
    LOAD_TILE(1, BK); CP_COMMIT();

    int load_buf = 2;
    int cons_buf = 0;

    for (int c = 0; c < nc; c++) {
        CP_WAIT(1);
        __syncthreads();
        int nf = c + 2;
        if (nf < nc) LOAD_TILE(load_buf, nf * BK);
        CP_COMMIT();
        if (++load_buf == NSTAGE) load_buf = 0;

        const uint32_t ab = sA + cons_buf * STAGE_BYTES;
        const uint32_t wb = sW + cons_buf * STAGE_BYTES;
        if (++cons_buf == NSTAGE) cons_buf = 0;

        #pragma unroll
        for (int ks = 0; ks < 4; ks++) {
            uint32_t a[4][4];
            #pragma unroll
            for (int mt = 0; mt < 4; mt++)
                asm volatile("ldmatrix.sync.aligned.m8n8.x4.shared.b16 {%0,%1,%2,%3}, [%4];"
                    : "=r"(a[mt][0]), "=r"(a[mt][1]), "=r"(a[mt][2]), "=r"(a[mt][3])
                    : "r"(ab + a_base[mt] + ks * 32));
            uint32_t b[4][2];
            #pragma unroll
            for (int np = 0; np < 2; np++)
                asm volatile("ldmatrix.sync.aligned.m8n8.x4.shared.b16 {%0,%1,%2,%3}, [%4];"
                    : "=r"(b[np * 2][0]), "=r"(b[np * 2][1]),
                      "=r"(b[np * 2 + 1][0]), "=r"(b[np * 2 + 1][1])
                    : "r"(wb + b_base[np] + ks * 32));
            #pragma unroll
            for (int mt = 0; mt < 4; mt++)
                #pragma unroll
                for (int nt = 0; nt < 4; nt++)
                    asm volatile(
                        "mma.sync.aligned.m16n8k16.row.col.f32.f16.f16.f32 "
                        "{%0,%1,%2,%3}, {%4,%5,%6,%7}, {%8,%9}, {%0,%1,%2,%3};"
                        : "+f"(acc[mt][nt][0]), "+f"(acc[mt][nt][1]),
                          "+f"(acc[mt][nt][2]), "+f"(acc[mt][nt][3])
                        : "r"(a[mt][0]), "r"(a[mt][1]), "r"(a[mt][2]), "r"(a[mt][3]),
                          "r"(b[nt][0]), "r"(b[nt][1]));
        }
    }
#undef LOAD_TILE

    #pragma unroll
    for (int mt = 0; mt < 4; mt++) {
        int r0 = bm + wm * 64 + mt * 16 + (lane >> 2);
        #pragma unroll
        for (int nt = 0; nt < 4; nt++) {
            int c0 = bn + wn * 32 + nt * 8 + (lane & 3) * 2;
            float* p0 = C + (size_t)r0 * N + c0;
            float* p1 = C + (size_t)(r0 + 8) * N + c0;
            if (EPI == 2) {
                atomicAdd(p0 + 0, acc[mt][nt][0]); atomicAdd(p0 + 1, acc[mt][nt][1]);
                atomicAdd(p1 + 0, acc[mt][nt][2]); atomicAdd(p1 + 1, acc[mt][nt][3]);
            } else {
                p0[0] = acc[mt][nt][0]; p0[1] = acc[mt][nt][1];
                p1[0] = acc[mt][nt][2]; p1[1] = acc[mt][nt][3];
            }
        }
    }
}

// ---------------- fp32 SGEMM for small shapes (x_proj, dt_proj) -------------
#define GBM 64
#define GBN 64
#define GBK 16
enum { EPI_NONE = 0, EPI_SOFTPLUS_BIAS = 1 };

template <int EPI, bool ATOMIC>
__global__ void __launch_bounds__(256)
gemm_tn_kernel(const float* __restrict__ A, int lda,
               const float* __restrict__ W, int ldw,
               float* __restrict__ C, int ldc,
               int M, int N, int kchunk,
               const float* __restrict__ bias)
{
    __shared__ float Asm[GBK][GBM + 1];
    __shared__ float Wsm[GBK][GBN + 1];

    int tid = threadIdx.x;
    int bm = blockIdx.y * GBM;
    int bn = blockIdx.x * GBN;
    int kbeg = blockIdx.z * kchunk;
    int kend = kbeg + kchunk;
    int lr = tid >> 2;
    int lk = (tid & 3) << 2;
    int ty = tid >> 4;
    int tx = tid & 15;

    float acc[4][4];
    #pragma unroll
    for (int i = 0; i < 4; i++)
        #pragma unroll
        for (int j = 0; j < 4; j++) acc[i][j] = 0.0f;

    for (int k0 = kbeg; k0 < kend; k0 += GBK) {
        {
            const float4 v = *(const float4*)(A + (size_t)(bm + lr) * lda + k0 + lk);
            Asm[lk + 0][lr] = v.x; Asm[lk + 1][lr] = v.y;
            Asm[lk + 2][lr] = v.z; Asm[lk + 3][lr] = v.w;
        }
        {
            float4 v = make_float4(0.f, 0.f, 0.f, 0.f);
            int row = bn + lr;
            if (row < N) v = *(const float4*)(W + (size_t)row * ldw + k0 + lk);
            Wsm[lk + 0][lr] = v.x; Wsm[lk + 1][lr] = v.y;
            Wsm[lk + 2][lr] = v.z; Wsm[lk + 3][lr] = v.w;
        }
        __syncthreads();
        #pragma unroll
        for (int kk = 0; kk < GBK; kk++) {
            float a[4], b[4];
            #pragma unroll
            for (int i = 0; i < 4; i++) a[i] = Asm[kk][ty * 4 + i];
            #pragma unroll
            for (int j = 0; j < 4; j++) b[j] = Wsm[kk][tx * 4 + j];
            #pragma unroll
            for (int i = 0; i < 4; i++)
                #pragma unroll
                for (int j = 0; j < 4; j++)
                    acc[i][j] = fmaf(a[i], b[j], acc[i][j]);
        }
        __syncthreads();
    }

    #pragma unroll
    for (int i = 0; i < 4; i++) {
        int row = bm + ty * 4 + i;
        #pragma unroll
        for (int j = 0; j < 4; j++) {
            int col = bn + tx * 4 + j;
            if (col < N) {
                float v = acc[i][j];
                if (ATOMIC) {
                    atomicAdd(&C[(size_t)row * ldc + col], v);
                } else {
                    if (EPI == EPI_SOFTPLUS_BIAS) v = softplusf(v + bias[col]);
                    C[(size_t)row * ldc + col] = v;
                }
            }
        }
    }
}

// ---------------- causal depthwise conv (width 4) + silu, 8 t per thread ----
__global__ void conv_silu8_kernel(const float* __restrict__ proj,
                                  const float* __restrict__ cw,
                                  const float* __restrict__ cb,
                                  float* __restrict__ out)
{
    int idx = blockIdx.x * blockDim.x + threadIdx.x;
    if (idx >= (TT / 8) * DI) return;
    int d = idx % DI;
    int t8 = idx / DI;
    int tbase = t8 * 8;
    int lbase = tbase & (LL - 1);
    float w0 = cw[d * 4 + 0], w1 = cw[d * 4 + 1], w2 = cw[d * 4 + 2], w3 = cw[d * 4 + 3];
    float bias = cb[d];
    float x[11];
    #pragma unroll
    for (int j = 0; j < 11; j++) {
        int l = lbase - 3 + j;
        x[j] = (l >= 0) ? proj[(size_t)(tbase - 3 + j) * (2 * DI) + d] : 0.0f;
    }
    #pragma unroll
    for (int i = 0; i < 8; i++) {
        float acc = bias;
        acc = fmaf(w0, x[i + 0], acc);
        acc = fmaf(w1, x[i + 1], acc);
        acc = fmaf(w2, x[i + 2], acc);
        acc = fmaf(w3, x[i + 3], acc);
        out[(size_t)(tbase + i) * DI + d] = siluf(acc);
    }
}

// ---------------- chunked selective scan ------------------------------------
// A: per-chunk local scan from 0 -> (prod of a, local final state)
__global__ void scan_a_kernel(const float* __restrict__ dt,
                              const float* __restrict__ hconv,
                              const float* __restrict__ ssm,
                              const float* __restrict__ A_log,
                              float* __restrict__ P,
                              float* __restrict__ S)
{
    int s = threadIdx.x & 15;
    int d = blockIdx.x * 16 + (threadIdx.x >> 4);
    int b = blockIdx.y >> 4;
    int ch = blockIdx.y & 15;
    float Aneg = -__expf(A_log[d * DS + s]);

    const int t0 = b * LL + ch * CHL;
    float state = 0.0f, prod = 1.0f;
    float dtv = dt[(size_t)t0 * DI + d];
    float hv  = hconv[(size_t)t0 * DI + d];
    float Bv  = ssm[(size_t)t0 * 80 + DTR + s];
    for (int l = 0; l < CHL; l++) {
        int tn = t0 + l + ((l + 1 < CHL) ? 1 : 0);
        float n_dtv = dt[(size_t)tn * DI + d];
        float n_hv  = hconv[(size_t)tn * DI + d];
        float n_Bv  = ssm[(size_t)tn * 80 + DTR + s];
        float a = __expf(dtv * Aneg);
        state = fmaf(a, state, dtv * hv * Bv);
        prod *= a;
        dtv = n_dtv; hv = n_hv; Bv = n_Bv;
    }
    int o = ((b * NCH + ch) * DI + d) * DS + s;
    P[o] = prod; S[o] = state;
}

// C: compute carry inline from preceding chunks' (P,S), re-run chunk, emit y
__global__ void scan_c_kernel(const float* __restrict__ dt,
                              const float* __restrict__ hconv,
                              const float* __restrict__ ssm,
                              const float* __restrict__ proj,
                              const float* __restrict__ A_log,
                              const float* __restrict__ D_skip,
                              const float* __restrict__ P,
                              const float* __restrict__ S,
                              __half* __restrict__ y)
{
    int s = threadIdx.x & 15;
    int d = blockIdx.x * 16 + (threadIdx.x >> 4);
    int b = blockIdx.y >> 4;
    int ch = blockIdx.y & 15;
    float Aneg = -__expf(A_log[d * DS + s]);
    float Dk = D_skip[d];

    // carry after chunks 0..ch-1:  init_{j+1} = P_j * init_j + S_j
    float state = 0.0f;
    for (int j = 0; j < ch; j++) {
        int o = ((b * NCH + j) * DI + d) * DS + s;
        state = fmaf(P[o], state, S[o]);
    }

    const int t0 = b * LL + ch * CHL;
    float dtv = dt[(size_t)t0 * DI + d];
    float hv  = hconv[(size_t)t0 * DI + d];
    float Bv  = ssm[(size_t)t0 * 80 + DTR + s];
    float Cv  = ssm[(size_t)t0 * 80 + DTR + DS + s];
    float gv  = proj[(size_t)t0 * (2 * DI) + DI + d];

    for (int l = 0; l < CHL; l++) {
        int t = t0 + l;
        int tn = t + ((l + 1 < CHL) ? 1 : 0);
        float n_dtv = dt[(size_t)tn * DI + d];
        float n_hv  = hconv[(size_t)tn * DI + d];
        float n_Bv  = ssm[(size_t)tn * 80 + DTR + s];
        float n_Cv  = ssm[(size_t)tn * 80 + DTR + DS + s];
        float n_gv  = proj[(size_t)tn * (2 * DI) + DI + d];

        float a = __expf(dtv * Aneg);
        state = fmaf(a, state, dtv * hv * Bv);
        float p = state * Cv;
        p += __shfl_xor_sync(0xffffffffu, p, 8);
        p += __shfl_xor_sync(0xffffffffu, p, 4);
        p += __shfl_xor_sync(0xffffffffu, p, 2);
        p += __shfl_xor_sync(0xffffffffu, p, 1);
        if (s == 0) {
            float val = (p + Dk * hv) * siluf(gv);
            __half hi, lo; split_half(val, hi, lo);
            __half* dst = y + (size_t)t * (2 * DI);
            dst[d] = hi; dst[DI + d] = lo;
        }
        dtv = n_dtv; hv = n_hv; Bv = n_Bv; Cv = n_Cv; gv = n_gv;
    }
}

// ---------------- launcher ----------------
extern "C" void kernel_launch(void* const* d_in, const int* in_sizes, int n_in,
                              void* d_out, int out_size)
{
    const int*   input_ids = (const int*)  d_in[0];
    const float* embed     = (const float*)d_in[1];
    const float* norm_f_w  = (const float*)d_in[2];
    const float* in_proj_w = (const float*)d_in[3];
    const float* conv_w    = (const float*)d_in[4];
    const float* conv_b    = (const float*)d_in[5];
    const float* x_proj_w  = (const float*)d_in[6];
    const float* dt_proj_w = (const float*)d_in[7];
    const float* dt_proj_b = (const float*)d_in[8];
    const float* A_log     = (const float*)d_in[9];
    const float* D_skip    = (const float*)d_in[10];
    const float* out_proj_w= (const float*)d_in[11];
    const float* norm_w    = (const float*)d_in[12];
    float* logits = (float*)d_out;

    float *ph, *pproj, *pconv, *pssm, *pdt, *pP, *pS;
    __half *pxnh, *pinw, *py, *poutw, *pembh;
    cudaGetSymbolAddress((void**)&ph,    g_h);
    cudaGetSymbolAddress((void**)&pproj, g_proj);
    cudaGetSymbolAddress((void**)&pconv, g_conv);
    cudaGetSymbolAddress((void**)&pssm,  g_ssm);
    cudaGetSymbolAddress((void**)&pdt,   g_dt);
    cudaGetSymbolAddress((void**)&pP,    g_scanP);
    cudaGetSymbolAddress((void**)&pS,    g_scanS);
    cudaGetSymbolAddress((void**)&pxnh,  g_xn_half);
    cudaGetSymbolAddress((void**)&pinw,  g_inw_half);
    cudaGetSymbolAddress((void**)&py,    g_y_half);
    cudaGetSymbolAddress((void**)&poutw, g_outw_half);
    cudaGetSymbolAddress((void**)&pembh, g_embed_half);

    cudaFuncSetAttribute((const void*)hmma_gemm_kernel<0>,
                         cudaFuncAttributeMaxDynamicSharedMemorySize, HMMA_SMEM);
    cudaFuncSetAttribute((const void*)hmma_gemm_kernel<2>,
                         cudaFuncAttributeMaxDynamicSharedMemorySize, HMMA_SMEM);

    // bulk weight conversions (single fp16 plane each)
    {
        dim3 ge((DM / 8 + 127) / 128, VOCAB);
        convert1h_w_kernel<<<ge, 128>>>(embed, pembh, DM);
        dim3 gi((DM / 8 + 127) / 128, NL * 2 * DI);
        convert1h_w_kernel<<<gi, 128>>>(in_proj_w, pinw, DM);
        dim3 go((DI / 8 + 127) / 128, NL * DM);
        convert1h_w_kernel<<<go, 128>>>(out_proj_w, poutw, DI);
    }

    // fused embed + layer-0 rmsnorm + zero(pproj, pssm)
    embed_rmsnorm2h_kernel<<<TT, 256>>>(input_ids, embed, norm_w, ph, pxnh,
                                        (float4*)pproj, pssm);

    for (int i = 0; i < NL; i++) {
        const __half* w_in1  = pinw  + (size_t)i * (2 * DI) * DM;
        const __half* w_out1 = poutw + (size_t)i * DM * DI;
        const float* w_cv  = conv_w     + (size_t)i * DI * DCONV;
        const float* b_cv  = conv_b     + (size_t)i * DI;
        const float* w_xp  = x_proj_w   + (size_t)i * (DTR + 2 * DS) * DI;
        const float* w_dtp = dt_proj_w  + (size_t)i * DI * DTR;
        const float* b_dtp = dt_proj_b  + (size_t)i * DI;
        const float* a_log = A_log      + (size_t)i * DI * DS;
        const float* d_sk  = D_skip     + (size_t)i * DI;
        const float* w_nrm = norm_w     + (size_t)i * DM;

        if (i > 0)
            rmsnorm2h_zero_kernel<<<TT, 256>>>(ph, w_nrm, pxnh, (float4*)pproj, pssm);

        // in_proj (fp16x2 A, single-plane W): K'=1536, split-K=3 atomic
        {
            dim3 grid(TT / BM, (2 * DI) / BN, 3);
            hmma_gemm_kernel<2><<<grid, 256, HMMA_SMEM>>>(
                pxnh, w_in1, pproj, 2 * DM, DM, DM, 2 * DI, (2 * DM) / 3);
        }

        // conv + silu (8 t per thread)
        conv_silu8_kernel<<<((TT / 8) * DI + 255) / 256, 256>>>(pproj, w_cv, b_cv, pconv);

        // x_proj: fp32, split-K=6 atomic
        {
            dim3 grid((80 + GBN - 1) / GBN, TT / GBM, 6);
            gemm_tn_kernel<EPI_NONE, true><<<grid, 256>>>(
                pconv, DI, w_xp, DI, pssm, 80, TT, 80, DI / 6, nullptr);
        }

        // dt_proj + softplus
        {
            dim3 grid(DI / GBN, TT / GBM, 1);
            gemm_tn_kernel<EPI_SOFTPLUS_BIAS, false><<<grid, 256>>>(
                pssm, 80, w_dtp, DTR, pdt, DI, TT, DI, DTR, b_dtp);
        }

        // chunked selective scan (A: local scans; C: carry inline + emit y)
        {
            dim3 gac(DI / 16, BB * NCH);
            scan_a_kernel<<<gac, 256>>>(pdt, pconv, pssm, a_log, pP, pS);
            scan_c_kernel<<<gac, 256>>>(pdt, pconv, pssm, pproj, a_log, d_sk, pP, pS, py);
        }

        // out_proj (fp16x2 A, single-plane W): K'=3072, split-K=6 atomic
        {
            dim3 grid(TT / BM, DM / BN, 6);
            hmma_gemm_kernel<2><<<grid, 256, HMMA_SMEM>>>(
                py, w_out1, ph, 2 * DI, DI, DI, DM, (2 * DI) / 6);
        }
    }

    // final rmsnorm -> single fp16 plane
    rmsnorm1h_kernel<<<TT, 256>>>(ph, norm_f_w, pxnh);

    // lm head: pure fp16 single-plane, K=768
    {
        dim3 grid(TT / BM, VOCAB / BN, 1);
        hmma_gemm_kernel<0><<<grid, 256, HMMA_SMEM>>>(
            pxnh, pembh, logits, DM, DM, DM, VOCAB, DM);
    }
}